// round 1
// baseline (speedup 1.0000x reference)
#include <cuda_runtime.h>
#include <math.h>

#define Bb 8
#define Tt 12
#define Nn 4000
#define Cc 2
#define Hh 64
#define BT 96          // Bb*Tt
#define Jj 192         // BT*Cc
#define BNr 32000      // Bb*Nn
#define G4 256         // 4*Hh

// ---------------- scratch (static device allocations only) ----------------
__device__ float d_Bmat[Nn * Jj];                 // packed x:  [m][j], j=(b*T+t)*2+c
__device__ float d_XG[Nn * Jj];                   // adj @ x
__device__ float d_G[Tt * BNr * Hh];              // relu GCN output, [t][bn][h]
__device__ float d_PRE[(size_t)Tt * BNr * G4];    // input-side gates + biases
__device__ float d_Hst[BNr * Hh];
__device__ float d_Cst[BNr * Hh];

// ---------------- kernels ----------------

__global__ void zero_state_kernel() {
    int g = blockIdx.x * blockDim.x + threadIdx.x;
    if (g < BNr * Hh) { d_Hst[g] = 0.f; d_Cst[g] = 0.f; }
}

// Bmat[m*192 + j] = x[(bt*N + m)*2 + c], j = bt*2+c
__global__ void pack_kernel(const float* __restrict__ x) {
    int gid = blockIdx.x * blockDim.x + threadIdx.x;
    if (gid >= Nn * Jj) return;
    int m = gid / Jj, j = gid - m * Jj;
    int bt = j >> 1, c = j & 1;
    d_Bmat[gid] = x[(bt * Nn + m) * 2 + c];
}

// XG[n][j] = sum_m adj[n][m] * Bmat[m][j]   (M=4000, N=192, K=4000)
// BM=64, BN=64, BK=32, 256 threads, 4x4 register tile, strided mapping.
__global__ __launch_bounds__(256) void gemm_adj(const float* __restrict__ adj) {
    __shared__ float As[32 * 65];   // As[k][row], padded
    __shared__ float Bs[32 * 64];   // Bs[k][col]
    int tid = threadIdx.x;
    int tx = tid & 15, ty = tid >> 4;
    int rowb = blockIdx.y * 64;
    int colb = blockIdx.x * 64;
    float acc[4][4] = {};
    for (int kb = 0; kb < Nn; kb += 32) {
#pragma unroll
        for (int q = 0; q < 8; q++) {           // A: 64x32
            int lin = tid + 256 * q;
            int r = lin >> 5, k = lin & 31;
            int gr = rowb + r;
            As[k * 65 + r] = (gr < Nn) ? adj[(size_t)gr * Nn + kb + k] : 0.f;
        }
#pragma unroll
        for (int q = 0; q < 8; q++) {           // B: 32x64
            int lin = tid + 256 * q;
            int c = lin & 63, k = lin >> 6;
            Bs[k * 64 + c] = d_Bmat[(kb + k) * Jj + colb + c];
        }
        __syncthreads();
#pragma unroll 8
        for (int k = 0; k < 32; k++) {
            float a[4], bv[4];
#pragma unroll
            for (int i = 0; i < 4; i++) a[i] = As[k * 65 + ty + 16 * i];
#pragma unroll
            for (int j = 0; j < 4; j++) bv[j] = Bs[k * 64 + tx + 16 * j];
#pragma unroll
            for (int i = 0; i < 4; i++)
#pragma unroll
                for (int j = 0; j < 4; j++) acc[i][j] += a[i] * bv[j];
        }
        __syncthreads();
    }
#pragma unroll
    for (int i = 0; i < 4; i++) {
        int gr = rowb + ty + 16 * i;
        if (gr < Nn) {
#pragma unroll
            for (int j = 0; j < 4; j++)
                d_XG[gr * Jj + colb + tx + 16 * j] = acc[i][j];
        }
    }
}

// G[(t*BN + b*N + n)*64 + h] = relu(XG[n][bt*2]*Wg[h][0] + XG[n][bt*2+1]*Wg[h][1] + bg[h])
__global__ void gcn_act(const float* __restrict__ Wg, const float* __restrict__ bg) {
    int gid = blockIdx.x * blockDim.x + threadIdx.x;
    if (gid >= Tt * BNr * Hh) return;
    int h = gid & 63;
    int r = gid >> 6;            // t*BN + b*N + n
    int t = r / BNr;
    int rr = r - t * BNr;
    int b = rr / Nn;
    int n = rr - b * Nn;
    int xi = n * Jj + (b * Tt + t) * 2;
    float v = d_XG[xi] * Wg[h * 2] + d_XG[xi + 1] * Wg[h * 2 + 1] + bg[h];
    d_G[gid] = v > 0.f ? v : 0.f;
}

// Shared-memory sizes for the K=64 GEMM kernels
#define SM_WS (64 * 257)     // Ws[k][o] padded
#define SM_GS (64 * 65)      // Gs[k][row] padded
#define SMEM_BYTES ((SM_WS + SM_GS) * 4)

// PRE[r][o] = sum_k G[r][k]*W_ih[o][k] + b_ih[o] + b_hh[o]   (M=384000, N=256, K=64)
__global__ __launch_bounds__(256, 2) void gemm_pre(const float* __restrict__ Wih,
                                                   const float* __restrict__ bih,
                                                   const float* __restrict__ bhh) {
    extern __shared__ float sm[];
    float* Ws = sm;               // [64][257]
    float* Gs = sm + SM_WS;       // [64][65]
    int tid = threadIdx.x;
    int tx = tid & 15, ty = tid >> 4;
    int rowb = blockIdx.x * 64;
    for (int q = 0; q < 64; q++) {            // W: 256x64 -> transposed
        int lin = tid + 256 * q;
        int o = lin >> 6, k = lin & 63;
        Ws[k * 257 + o] = Wih[lin];
    }
#pragma unroll
    for (int q = 0; q < 16; q++) {            // G tile: 64x64 -> transposed
        int lin = tid + 256 * q;
        int r = lin >> 6, k = lin & 63;
        Gs[k * 65 + r] = d_G[(size_t)(rowb + r) * 64 + k];
    }
    __syncthreads();
    float acc[4][16] = {};
#pragma unroll 8
    for (int k = 0; k < 64; k++) {
        float a[4], bv[16];
#pragma unroll
        for (int i = 0; i < 4; i++) a[i] = Gs[k * 65 + ty + 16 * i];
#pragma unroll
        for (int j = 0; j < 16; j++) bv[j] = Ws[k * 257 + tx + 16 * j];
#pragma unroll
        for (int i = 0; i < 4; i++)
#pragma unroll
            for (int j = 0; j < 16; j++) acc[i][j] += a[i] * bv[j];
    }
#pragma unroll
    for (int i = 0; i < 4; i++) {
        int r = rowb + ty + 16 * i;
#pragma unroll
        for (int j = 0; j < 16; j++) {
            int o = tx + 16 * j;
            d_PRE[(size_t)r * G4 + o] = acc[i][j] + bih[o] + bhh[o];
        }
    }
}

// One LSTM step: gates = PRE[t] + H @ W_hh^T, then fused cell update in registers.
// Row-local in H, so in-place update is safe (each block reads/writes only its rows).
__global__ __launch_bounds__(256, 2) void lstm_step(const float* __restrict__ Whh, int t) {
    extern __shared__ float sm[];
    float* Ws = sm;
    float* Gs = sm + SM_WS;
    int tid = threadIdx.x;
    int tx = tid & 15, ty = tid >> 4;
    int rowb = blockIdx.x * 64;
    for (int q = 0; q < 64; q++) {
        int lin = tid + 256 * q;
        int o = lin >> 6, k = lin & 63;
        Ws[k * 257 + o] = Whh[lin];
    }
#pragma unroll
    for (int q = 0; q < 16; q++) {
        int lin = tid + 256 * q;
        int r = lin >> 6, k = lin & 63;
        Gs[k * 65 + r] = d_Hst[(rowb + r) * 64 + k];
    }
    __syncthreads();
    float acc[4][16];
    const float* pre = d_PRE + (size_t)(t * BNr + rowb) * G4;
#pragma unroll
    for (int i = 0; i < 4; i++)
#pragma unroll
        for (int j = 0; j < 16; j++)
            acc[i][j] = pre[(ty + 16 * i) * G4 + tx + 16 * j];
#pragma unroll 8
    for (int k = 0; k < 64; k++) {
        float a[4], bv[16];
#pragma unroll
        for (int i = 0; i < 4; i++) a[i] = Gs[k * 65 + ty + 16 * i];
#pragma unroll
        for (int j = 0; j < 16; j++) bv[j] = Ws[k * 257 + tx + 16 * j];
#pragma unroll
        for (int i = 0; i < 4; i++)
#pragma unroll
            for (int j = 0; j < 16; j++) acc[i][j] += a[i] * bv[j];
    }
    // Thread holds cols tx+16j; j=0..3 -> gate i, 4..7 -> f, 8..11 -> g, 12..15 -> o,
    // all at hidx = tx+16*hh  => full quadruples in registers.
#pragma unroll
    for (int i = 0; i < 4; i++) {
        int r = rowb + ty + 16 * i;
#pragma unroll
        for (int hh = 0; hh < 4; hh++) {
            int hidx = tx + 16 * hh;
            float ig = acc[i][hh];
            float fg = acc[i][4 + hh];
            float gg = acc[i][8 + hh];
            float og = acc[i][12 + hh];
            float c = d_Cst[r * 64 + hidx];
            float si = 1.f / (1.f + expf(-ig));
            float sf = 1.f / (1.f + expf(-fg));
            float so = 1.f / (1.f + expf(-og));
            float cn = sf * c + si * tanhf(gg);
            d_Cst[r * 64 + hidx] = cn;
            d_Hst[r * 64 + hidx] = so * tanhf(cn);
        }
    }
}

// out[bn] = dot(H[bn], W_out) + b_out   (warp per row)
__global__ void out_kernel(const float* __restrict__ Wout, const float* __restrict__ bout,
                           float* __restrict__ out) {
    int gid = blockIdx.x * blockDim.x + threadIdx.x;
    int warp = gid >> 5;
    int lane = threadIdx.x & 31;
    if (warp >= BNr) return;
    float s = d_Hst[warp * 64 + lane] * Wout[lane]
            + d_Hst[warp * 64 + 32 + lane] * Wout[32 + lane];
#pragma unroll
    for (int off = 16; off; off >>= 1) s += __shfl_down_sync(0xffffffffu, s, off);
    if (lane == 0) out[warp] = s + bout[0];
}

// ---------------- launch ----------------

extern "C" void kernel_launch(void* const* d_in, const int* in_sizes, int n_in,
                              void* d_out, int out_size) {
    const float* x    = (const float*)d_in[0];
    const float* adj  = (const float*)d_in[1];
    const float* Wg   = (const float*)d_in[2];
    const float* bg   = (const float*)d_in[3];
    const float* Wih  = (const float*)d_in[4];
    const float* Whh  = (const float*)d_in[5];
    const float* bih  = (const float*)d_in[6];
    const float* bhh  = (const float*)d_in[7];
    const float* Wout = (const float*)d_in[8];
    const float* bout = (const float*)d_in[9];
    float* out = (float*)d_out;

    cudaFuncSetAttribute(gemm_pre, cudaFuncAttributeMaxDynamicSharedMemorySize, SMEM_BYTES);
    cudaFuncSetAttribute(lstm_step, cudaFuncAttributeMaxDynamicSharedMemorySize, SMEM_BYTES);

    zero_state_kernel<<<(BNr * Hh + 255) / 256, 256>>>();
    pack_kernel<<<(Nn * Jj + 255) / 256, 256>>>(x);
    dim3 ga(Jj / 64, (Nn + 63) / 64);    // (3, 63)
    gemm_adj<<<ga, 256>>>(adj);
    gcn_act<<<(Tt * BNr * Hh + 255) / 256, 256>>>(Wg, bg);
    gemm_pre<<<(Tt * BNr) / 64, 256, SMEM_BYTES>>>(Wih, bih, bhh);
    for (int t = 0; t < Tt; t++)
        lstm_step<<<BNr / 64, 256, SMEM_BYTES>>>(Whh, t);
    out_kernel<<<(BNr * 32 + 255) / 256, 256>>>(Wout, bout, out);
}

// round 2
// speedup vs baseline: 1.3907x; 1.3907x over previous
#include <cuda_runtime.h>

#define Tt 12
#define Nn 4000
#define Jj 192          // B*T*C = 8*12*2
#define BNr 32000       // B*N
#define G4 256          // 4*H
#define NJ (Nn*Jj)
#define SPLITK 5

// ---------------- scratch ----------------
__device__ float d_Bmat[NJ];                      // packed x: [m][j]
__device__ float d_XG[SPLITK * NJ];               // split-K partials of adj @ x
__device__ float d_PRE[(size_t)Tt * BNr * G4];    // input-side gates + biases

// fast transcendentals (EX2/RCP based, ~2e-7 rel err)
__device__ __forceinline__ float sigf(float x) {
    return __fdividef(1.f, 1.f + __expf(-x));
}
__device__ __forceinline__ float tanhfast(float x) {
    return 1.f - 2.f * __fdividef(1.f, __expf(2.f * x) + 1.f);
}

// ---------------- pack: Bmat[m][j] = x[(bt*N+m)*2+c], j=bt*2+c ----------------
__global__ void pack_kernel(const float* __restrict__ x) {
    int gid = blockIdx.x * blockDim.x + threadIdx.x;
    if (gid >= NJ) return;
    int m = gid / Jj, j = gid - m * Jj;
    int bt = j >> 1, c = j & 1;
    d_Bmat[gid] = x[(bt * Nn + m) * 2 + c];
}

// ---------------- adj GEMM: XG[n][0..191] split-K over 5 chunks ----------------
// BM=64, BN=192(all cols), BK=32, 256 thr = 32tx x 8ty, micro 8x6.
__global__ __launch_bounds__(256) void gemm_adj(const float* __restrict__ adj) {
    __shared__ float As[32 * 65];    // As[k][r]
    __shared__ float Bs[32 * 192];   // Bs[k][c]
    int tid = threadIdx.x;
    int tx = tid & 31, ty = tid >> 5;
    int rowb = blockIdx.x * 64;
    int kb0 = blockIdx.y * 800;      // 25 k-tiles of 32
    float acc[8][6] = {};
    for (int kt = 0; kt < 25; kt++) {
        int kb = kb0 + kt * 32;
#pragma unroll
        for (int q = 0; q < 8; q++) {        // A: 64x32, lanes->k coalesced
            int lin = tid + 256 * q;
            int r = lin >> 5, k = lin & 31;
            int gr = rowb + r;
            As[k * 65 + r] = (gr < Nn) ? adj[(size_t)gr * Nn + kb + k] : 0.f;
        }
#pragma unroll
        for (int q = 0; q < 24; q++) {       // B: 32x192, lanes->c coalesced
            int lin = tid + 256 * q;
            int k = lin / 192, c = lin - k * 192;
            Bs[lin] = d_Bmat[(kb + k) * Jj + c];
        }
        __syncthreads();
#pragma unroll 8
        for (int k = 0; k < 32; k++) {
            float a[8];
#pragma unroll
            for (int i = 0; i < 8; i++) a[i] = As[k * 65 + ty + 8 * i];
            float2 b0 = *(float2*)&Bs[k * 192 + tx * 6];
            float2 b1 = *(float2*)&Bs[k * 192 + tx * 6 + 2];
            float2 b2 = *(float2*)&Bs[k * 192 + tx * 6 + 4];
            float b[6] = {b0.x, b0.y, b1.x, b1.y, b2.x, b2.y};
#pragma unroll
            for (int i = 0; i < 8; i++)
#pragma unroll
                for (int j = 0; j < 6; j++) acc[i][j] += a[i] * b[j];
        }
        __syncthreads();
    }
    float* outp = d_XG + (size_t)blockIdx.y * NJ;
#pragma unroll
    for (int i = 0; i < 8; i++) {
        int gr = rowb + ty + 8 * i;
        if (gr < Nn) {
            int base = gr * Jj + tx * 6;
            float2 v0 = {acc[i][0], acc[i][1]};
            float2 v1 = {acc[i][2], acc[i][3]};
            float2 v2 = {acc[i][4], acc[i][5]};
            *(float2*)&outp[base]     = v0;
            *(float2*)&outp[base + 2] = v1;
            *(float2*)&outp[base + 4] = v2;
        }
    }
}

// ---------------- fused GCN + input-projection GEMM ----------------
#define WS_STRIDE 258
#define SM_WS (64 * WS_STRIDE)   // 16512 floats
#define SM_GS (64 * 65)          // 4160 floats
#define GCN_SMEM ((SM_WS + SM_GS + 64 + 64 + 128 + 64 + 256) * 4)
#define LSTM_SMEM ((SM_WS + SM_GS + 64) * 4)

// PRE[R][o] = sum_k relu-G[R][k]*Wih[o][k] + bih[o]+bhh[o], R = t*BN + b*N + n
__global__ __launch_bounds__(256, 2) void gcn_pre(const float* __restrict__ Wg,
                                                  const float* __restrict__ bg,
                                                  const float* __restrict__ Wih,
                                                  const float* __restrict__ bih,
                                                  const float* __restrict__ bhh) {
    extern __shared__ float sm[];
    float* Ws  = sm;                 // [k][o] stride 258
    float* Gs  = sm + SM_WS;         // [k][r] stride 65
    float* sx0 = Gs + SM_GS;
    float* sx1 = sx0 + 64;
    float* sWg = sx1 + 64;
    float* sbg = sWg + 128;
    float* sb  = sbg + 64;
    int tid = threadIdx.x;
    int tx = tid & 31, ty = tid >> 5;
    int rowb = blockIdx.x * 64;
#pragma unroll 8
    for (int q = 0; q < 64; q++) {           // Wih transposed into smem
        int lin = tid + 256 * q;
        int o = lin >> 6, k = lin & 63;
        Ws[k * WS_STRIDE + o] = Wih[lin];
    }
    if (tid < 128) sWg[tid] = Wg[tid];
    if (tid < 64)  sbg[tid] = bg[tid];
    sb[tid] = bih[tid] + bhh[tid];
    if (tid < 64) {                           // per-row graph features
        int R = rowb + tid;
        int t = R / BNr;
        int rr = R - t * BNr;
        int b = rr / Nn;
        int n = rr - b * Nn;
        int xi = n * Jj + (b * Tt + t) * 2;
        float s0 = 0.f, s1 = 0.f;
#pragma unroll
        for (int s = 0; s < SPLITK; s++) { s0 += d_XG[s * NJ + xi]; s1 += d_XG[s * NJ + xi + 1]; }
        sx0[tid] = s0; sx1[tid] = s1;
    }
    __syncthreads();
#pragma unroll
    for (int q = 0; q < 16; q++) {            // G tile (relu) straight into smem
        int lin = tid + 256 * q;
        int r = lin & 63, h = lin >> 6;
        float v = sx0[r] * sWg[2 * h] + sx1[r] * sWg[2 * h + 1] + sbg[h];
        Gs[h * 65 + r] = v > 0.f ? v : 0.f;
    }
    __syncthreads();
    float acc[8][8] = {};
#pragma unroll 8
    for (int k = 0; k < 64; k++) {
        float a[8];
#pragma unroll
        for (int i = 0; i < 8; i++) a[i] = Gs[k * 65 + ty + 8 * i];
#pragma unroll
        for (int g = 0; g < 4; g++) {
            float2 w = *(float2*)&Ws[k * WS_STRIDE + g * 64 + tx * 2];
#pragma unroll
            for (int i = 0; i < 8; i++) {
                acc[i][2 * g]     += a[i] * w.x;
                acc[i][2 * g + 1] += a[i] * w.y;
            }
        }
    }
    float* pre = d_PRE + (size_t)rowb * G4;
#pragma unroll
    for (int i = 0; i < 8; i++) {
        int r = ty + 8 * i;
#pragma unroll
        for (int g = 0; g < 4; g++) {
            int o = g * 64 + tx * 2;
            float2 v = {acc[i][2 * g] + sb[o], acc[i][2 * g + 1] + sb[o + 1]};
            *(float2*)&pre[(size_t)r * G4 + o] = v;
        }
    }
}

// ---------------- all 12 LSTM steps in ONE kernel (row-local recurrence) ----------------
__global__ __launch_bounds__(256, 2) void lstm_all(const float* __restrict__ Whh,
                                                   const float* __restrict__ Wout,
                                                   const float* __restrict__ bout,
                                                   float* __restrict__ out) {
    extern __shared__ float sm[];
    float* Ws  = sm;             // Whh transposed [k][o]
    float* Gs  = sm + SM_WS;     // H state [h][r]
    float* sWo = Gs + SM_GS;
    int tid = threadIdx.x;
    int tx = tid & 31, ty = tid >> 5;
    int rowb = blockIdx.x * 64;
#pragma unroll 8
    for (int q = 0; q < 64; q++) {
        int lin = tid + 256 * q;
        int o = lin >> 6, k = lin & 63;
        Ws[k * WS_STRIDE + o] = Whh[lin];
    }
    if (tid < 64) sWo[tid] = Wout[tid];
    float cst[8][2] = {};        // cell state in registers
    float acc[8][8];
    for (int t = 0; t < Tt; t++) {
        const float* pre = d_PRE + ((size_t)t * BNr + rowb) * G4;
#pragma unroll
        for (int i = 0; i < 8; i++) {
            int r = ty + 8 * i;
#pragma unroll
            for (int g = 0; g < 4; g++) {
                float2 p = *(const float2*)&pre[(size_t)r * G4 + g * 64 + tx * 2];
                acc[i][2 * g] = p.x; acc[i][2 * g + 1] = p.y;
            }
        }
        if (t > 0) {             // h(0) = 0 -> skip recurrent GEMM on first step
#pragma unroll 8
            for (int k = 0; k < 64; k++) {
                float a[8];
#pragma unroll
                for (int i = 0; i < 8; i++) a[i] = Gs[k * 65 + ty + 8 * i];
#pragma unroll
                for (int g = 0; g < 4; g++) {
                    float2 w = *(float2*)&Ws[k * WS_STRIDE + g * 64 + tx * 2];
#pragma unroll
                    for (int i = 0; i < 8; i++) {
                        acc[i][2 * g]     += a[i] * w.x;
                        acc[i][2 * g + 1] += a[i] * w.y;
                    }
                }
            }
        }
        // fused cell update: thread owns full i/f/g/o quadruples (cols g*64 + tx*2 + j)
#pragma unroll
        for (int i = 0; i < 8; i++) {
#pragma unroll
            for (int j = 0; j < 2; j++) {
                float ig = acc[i][j],     fg = acc[i][2 + j];
                float gg = acc[i][4 + j], og = acc[i][6 + j];
                float cn = sigf(fg) * cst[i][j] + sigf(ig) * tanhfast(gg);
                cst[i][j] = cn;
                acc[i][j] = sigf(og) * tanhfast(cn);   // new h, staged in acc[i][0..1]
            }
        }
        __syncthreads();                               // all Gs reads done
#pragma unroll
        for (int i = 0; i < 8; i++) {
            int r = ty + 8 * i;
            Gs[(tx * 2) * 65 + r]     = acc[i][0];
            Gs[(tx * 2 + 1) * 65 + r] = acc[i][1];
        }
        __syncthreads();
    }
    // fused output head: out[r] = dot(H[r], Wout) + bout
    if (tid < 64) {
        float s = 0.f;
#pragma unroll 8
        for (int k = 0; k < 64; k++) s += Gs[k * 65 + tid] * sWo[k];
        out[rowb + tid] = s + bout[0];
    }
}

// ---------------- launch ----------------
extern "C" void kernel_launch(void* const* d_in, const int* in_sizes, int n_in,
                              void* d_out, int out_size) {
    const float* x    = (const float*)d_in[0];
    const float* adj  = (const float*)d_in[1];
    const float* Wg   = (const float*)d_in[2];
    const float* bg   = (const float*)d_in[3];
    const float* Wih  = (const float*)d_in[4];
    const float* Whh  = (const float*)d_in[5];
    const float* bih  = (const float*)d_in[6];
    const float* bhh  = (const float*)d_in[7];
    const float* Wout = (const float*)d_in[8];
    const float* bout = (const float*)d_in[9];
    float* out = (float*)d_out;

    cudaFuncSetAttribute(gcn_pre,  cudaFuncAttributeMaxDynamicSharedMemorySize, GCN_SMEM);
    cudaFuncSetAttribute(lstm_all, cudaFuncAttributeMaxDynamicSharedMemorySize, LSTM_SMEM);

    pack_kernel<<<(NJ + 255) / 256, 256>>>(x);
    dim3 ga(63, SPLITK);
    gemm_adj<<<ga, 256>>>(adj);
    gcn_pre<<<(Tt * BNr) / 64, 256, GCN_SMEM>>>(Wg, bg, Wih, bih, bhh);
    lstm_all<<<BNr / 64, 256, LSTM_SMEM>>>(Whh, Wout, bout, out);
}

// round 3
// speedup vs baseline: 1.5972x; 1.1485x over previous
#include <cuda_runtime.h>

#define Tt 12
#define Nn 4000
#define Jj 192          // B*T*C
#define BNr 32000       // B*N
#define NJ (Nn*Jj)
#define SPLITK 5

// ---------------- scratch ----------------
__device__ float d_Bmat[NJ];              // packed x: [m][j], j = bt*2+c
__device__ float d_XGp[SPLITK * NJ];      // split-K partials of adj @ x
__device__ float d_XGs[NJ];               // summed adj @ x

// ---------------- packed f32x2 FMA (sm_103a; doubles fp32 rate) ----------------
union F2U { float2 f; unsigned long long u; };
__device__ __forceinline__ float2 ffma2(float2 a, float2 b, float2 c) {
    F2U A, B, C, D; A.f = a; B.f = b; C.f = c;
    asm("fma.rn.f32x2 %0, %1, %2, %3;" : "=l"(D.u) : "l"(A.u), "l"(B.u), "l"(C.u));
    return D.f;
}
__device__ __forceinline__ float2 dup2(float x) { return make_float2(x, x); }

__device__ __forceinline__ float sigf(float x) {
    return __fdividef(1.f, 1.f + __expf(-x));
}
__device__ __forceinline__ float tanhfast(float x) {
    return 1.f - 2.f * __fdividef(1.f, __expf(2.f * x) + 1.f);
}

// ---------------- pack: Bmat[m][j] = x[(bt*N+m)*2+c] ----------------
// thread per (bt, m); coalesced float2 reads, scattered float2 writes
__global__ void pack_kernel(const float* __restrict__ x) {
    int gid = blockIdx.x * blockDim.x + threadIdx.x;
    if (gid >= Nn * 96) return;
    int bt = gid / Nn, m = gid - bt * Nn;
    float2 v = *(const float2*)&x[(size_t)(bt * Nn + m) * 2];
    *(float2*)&d_Bmat[m * Jj + bt * 2] = v;
}

// ---------------- adj GEMM with FFMA2: XGp[s][n][j], split-K over 5 ----------------
// BM=64, BN=192, BK=32. 256 thr: ty=tid>>5 -> 8x8 contig rows, tx -> cols tx+32j.
__global__ __launch_bounds__(256) void gemm_adj(const float* __restrict__ adj) {
    __shared__ __align__(16) float As[32 * 68];    // [k][r] stride 68
    __shared__ __align__(16) float Bs[32 * 192];   // [k][c]
    int tid = threadIdx.x, tx = tid & 31, ty = tid >> 5;
    int rowb = blockIdx.x * 64;
    int kb0 = blockIdx.y * 800;
    float2 acc[4][6];
#pragma unroll
    for (int p = 0; p < 4; p++)
#pragma unroll
        for (int j = 0; j < 6; j++) acc[p][j] = make_float2(0.f, 0.f);
    for (int kt = 0; kt < 25; kt++) {
        int kb = kb0 + kt * 32;
#pragma unroll
        for (int q = 0; q < 8; q++) {              // A 64x32, lanes->k coalesced
            int lin = tid + 256 * q;
            int r = lin >> 5, k = lin & 31;
            int gr = rowb + r;
            As[k * 68 + r] = (gr < Nn) ? adj[(size_t)gr * Nn + kb + k] : 0.f;
        }
#pragma unroll
        for (int q = 0; q < 24; q++) {             // B 32x192 coalesced
            int lin = tid + 256 * q;
            int k = lin / 192, c = lin - k * 192;
            Bs[lin] = d_Bmat[(kb + k) * Jj + c];
        }
        __syncthreads();
#pragma unroll 8
        for (int k = 0; k < 32; k++) {
            float4 a0 = *(float4*)&As[k * 68 + ty * 8];       // broadcast, free
            float4 a1 = *(float4*)&As[k * 68 + ty * 8 + 4];
            float2 ap[4] = {{a0.x, a0.y}, {a0.z, a0.w}, {a1.x, a1.y}, {a1.z, a1.w}};
#pragma unroll
            for (int j = 0; j < 6; j++) {
                float2 bj = dup2(Bs[k * 192 + tx + 32 * j]);  // conflict-free
#pragma unroll
                for (int p = 0; p < 4; p++) acc[p][j] = ffma2(ap[p], bj, acc[p][j]);
            }
        }
        __syncthreads();
    }
    float* outp = d_XGp + (size_t)blockIdx.y * NJ;
#pragma unroll
    for (int p = 0; p < 4; p++) {
        int r0 = rowb + ty * 8 + 2 * p;
        if (r0 < Nn) {
#pragma unroll
            for (int j = 0; j < 6; j++) outp[r0 * Jj + tx + 32 * j] = acc[p][j].x;
        }
        if (r0 + 1 < Nn) {
#pragma unroll
            for (int j = 0; j < 6; j++) outp[(r0 + 1) * Jj + tx + 32 * j] = acc[p][j].y;
        }
    }
}

// ---------------- split-K reduce ----------------
__global__ void reduce_xg() {
    int i = blockIdx.x * blockDim.x + threadIdx.x;   // float4 index
    if (i >= NJ / 4) return;
    float4 s = ((const float4*)d_XGp)[i];
#pragma unroll
    for (int sp = 1; sp < SPLITK; sp++) {
        float4 v = ((const float4*)(d_XGp + (size_t)sp * NJ))[i];
        s.x += v.x; s.y += v.y; s.z += v.z; s.w += v.w;
    }
    ((float4*)d_XGs)[i] = s;
}

// ---------------- fully fused GCN + input-proj + 12-step LSTM + head ----------------
#define WST 257
#define RST 68
#define SM_W (64 * WST)      // 16448 floats per weight matrix
#define SM_T (64 * RST)      // 4352 floats per activation tile
#define LSTM_SMEM ((2*SM_W + 2*SM_T + 12*128 + 128 + 64 + 64) * 4)

__global__ __launch_bounds__(256, 1) void lstm_fused(
        const float* __restrict__ Wg,  const float* __restrict__ bg,
        const float* __restrict__ Wih, const float* __restrict__ Whh,
        const float* __restrict__ bih, const float* __restrict__ bhh,
        const float* __restrict__ Wout, const float* __restrict__ bout,
        float* __restrict__ out) {
    extern __shared__ __align__(16) float sm[];
    float* WsI = sm;                 // Wih^T [k][o]
    float* WsH = WsI + SM_W;         // Whh^T [k][o]
    float* Gt  = WsH + SM_W;         // G tile [h][r]
    float* Hs  = Gt + SM_T;          // H state [h][r]
    float* sxa = Hs + SM_T;          // xg per (t, r): 12*128
    float* sWg = sxa + 12 * 128;
    float* sbg = sWg + 128;
    float* sWo = sbg + 64;
    int tid = threadIdx.x, tx = tid & 31, ty = tid >> 5;
    int rowb = blockIdx.x * 64;

#pragma unroll 8
    for (int q = 0; q < 64; q++) {           // both weights transposed into smem
        int lin = tid + 256 * q;
        int o = lin >> 6, k = lin & 63;
        WsI[k * WST + o] = Wih[lin];
        WsH[k * WST + o] = Whh[lin];
    }
    if (tid < 128) sWg[tid] = Wg[tid];
    if (tid < 64) { sbg[tid] = bg[tid]; sWo[tid] = Wout[tid]; }
    if (tid < 64) {                           // preload xg for all 12 steps
        int R = rowb + tid;
        int b = R / Nn, n = R - b * Nn;
        int xib = n * Jj + b * (Tt * 2);
#pragma unroll
        for (int t = 0; t < Tt; t++) {
            sxa[t * 128 + 2 * tid]     = d_XGs[xib + 2 * t];
            sxa[t * 128 + 2 * tid + 1] = d_XGs[xib + 2 * t + 1];
        }
    }
    float2 bb[8];                             // bias pairs; col j -> o = (j>>1)*64+(j&1)*32+tx
#pragma unroll
    for (int j = 0; j < 8; j++) {
        int o = ((j >> 1) << 6) + ((j & 1) << 5) + tx;
        bb[j] = dup2(bih[o] + bhh[o]);
    }
    float2 cst[2][4];                         // cell state: [jj][rowpair]
#pragma unroll
    for (int jj = 0; jj < 2; jj++)
#pragma unroll
        for (int p = 0; p < 4; p++) cst[jj][p] = make_float2(0.f, 0.f);
    float2 acc[4][8];
    __syncthreads();

    for (int t = 0; t < Tt; t++) {
        // G tile: relu(x0*Wg[:,0] + x1*Wg[:,1] + bg), layout [h][r]
#pragma unroll
        for (int q = 0; q < 16; q++) {
            int lin = tid + 256 * q;
            int h = lin >> 6, r = lin & 63;
            float v = sxa[t * 128 + 2 * r] * sWg[2 * h]
                    + sxa[t * 128 + 2 * r + 1] * sWg[2 * h + 1] + sbg[h];
            Gt[h * RST + r] = v > 0.f ? v : 0.f;
        }
        __syncthreads();
#pragma unroll
        for (int p = 0; p < 4; p++)
#pragma unroll
            for (int j = 0; j < 8; j++) acc[p][j] = bb[j];
        // input projection: acc += G @ Wih^T
#pragma unroll 8
        for (int k = 0; k < 64; k++) {
            float4 a0 = *(float4*)&Gt[k * RST + ty * 8];
            float4 a1 = *(float4*)&Gt[k * RST + ty * 8 + 4];
            float2 ap[4] = {{a0.x, a0.y}, {a0.z, a0.w}, {a1.x, a1.y}, {a1.z, a1.w}};
#pragma unroll
            for (int j = 0; j < 8; j++) {
                float2 wj = dup2(WsI[k * WST + ((j >> 1) << 6) + ((j & 1) << 5) + tx]);
#pragma unroll
                for (int p = 0; p < 4; p++) acc[p][j] = ffma2(ap[p], wj, acc[p][j]);
            }
        }
        if (t > 0) {                          // recurrent: acc += H @ Whh^T
#pragma unroll 8
            for (int k = 0; k < 64; k++) {
                float4 a0 = *(float4*)&Hs[k * RST + ty * 8];
                float4 a1 = *(float4*)&Hs[k * RST + ty * 8 + 4];
                float2 ap[4] = {{a0.x, a0.y}, {a0.z, a0.w}, {a1.x, a1.y}, {a1.z, a1.w}};
#pragma unroll
                for (int j = 0; j < 8; j++) {
                    float2 wj = dup2(WsH[k * WST + ((j >> 1) << 6) + ((j & 1) << 5) + tx]);
#pragma unroll
                    for (int p = 0; p < 4; p++) acc[p][j] = ffma2(ap[p], wj, acc[p][j]);
                }
            }
        }
        // cell update: j = gate*2 + jj -> thread owns full i/f/g/o per (jj, rowpair)
        float2 hv[2][4];
#pragma unroll
        for (int p = 0; p < 4; p++) {
#pragma unroll
            for (int jj = 0; jj < 2; jj++) {
                float2 ig = acc[p][jj],     fg = acc[p][2 + jj];
                float2 gg = acc[p][4 + jj], og = acc[p][6 + jj];
                float2 cn, hn;
                cn.x = sigf(fg.x) * cst[jj][p].x + sigf(ig.x) * tanhfast(gg.x);
                cn.y = sigf(fg.y) * cst[jj][p].y + sigf(ig.y) * tanhfast(gg.y);
                cst[jj][p] = cn;
                hn.x = sigf(og.x) * tanhfast(cn.x);
                hn.y = sigf(og.y) * tanhfast(cn.y);
                hv[jj][p] = hn;
            }
        }
        __syncthreads();                      // all reads of old Hs / Gt done
#pragma unroll
        for (int jj = 0; jj < 2; jj++)
#pragma unroll
            for (int p = 0; p < 4; p++)
                *(float2*)&Hs[(tx + 32 * jj) * RST + ty * 8 + 2 * p] = hv[jj][p];
        __syncthreads();
    }
    // output head: out[r] = dot(H[r], Wout) + bout
    if (tid < 64) {
        float s = 0.f;
#pragma unroll 8
        for (int k = 0; k < 64; k++) s += Hs[k * RST + tid] * sWo[k];
        out[rowb + tid] = s + bout[0];
    }
}

// ---------------- launch ----------------
extern "C" void kernel_launch(void* const* d_in, const int* in_sizes, int n_in,
                              void* d_out, int out_size) {
    const float* x    = (const float*)d_in[0];
    const float* adj  = (const float*)d_in[1];
    const float* Wg   = (const float*)d_in[2];
    const float* bg   = (const float*)d_in[3];
    const float* Wih  = (const float*)d_in[4];
    const float* Whh  = (const float*)d_in[5];
    const float* bih  = (const float*)d_in[6];
    const float* bhh  = (const float*)d_in[7];
    const float* Wout = (const float*)d_in[8];
    const float* bout = (const float*)d_in[9];
    float* out = (float*)d_out;

    cudaFuncSetAttribute(lstm_fused, cudaFuncAttributeMaxDynamicSharedMemorySize, LSTM_SMEM);

    pack_kernel<<<(Nn * 96 + 255) / 256, 256>>>(x);
    dim3 ga(63, SPLITK);
    gemm_adj<<<ga, 256>>>(adj);
    reduce_xg<<<(NJ / 4 + 255) / 256, 256>>>();
    lstm_fused<<<BNr / 64, 256, LSTM_SMEM>>>(Wg, bg, Wih, Whh, bih, bhh, Wout, bout, out);
}

// round 4
// speedup vs baseline: 1.6118x; 1.0091x over previous
#include <cuda_runtime.h>

#define Tt 12
#define Nn 4000
#define Jj 192          // B*T*C
#define BNr 32000       // B*N
#define NJ (Nn*Jj)
#define SPLITK 5

// ---------------- scratch ----------------
__device__ float d_Bmat[NJ];              // packed x: [m][j], j = bt*2+c
__device__ float d_XGp[SPLITK * NJ];      // split-K partials of adj @ x
__device__ float d_XGs[NJ];               // summed adj @ x

// ---------------- packed f32x2 FMA ----------------
union F2U { float2 f; unsigned long long u; };
__device__ __forceinline__ float2 ffma2(float2 a, float2 b, float2 c) {
    F2U A, B, C, D; A.f = a; B.f = b; C.f = c;
    asm("fma.rn.f32x2 %0, %1, %2, %3;" : "=l"(D.u) : "l"(A.u), "l"(B.u), "l"(C.u));
    return D.f;
}
__device__ __forceinline__ float2 dup2(float x) { return make_float2(x, x); }

__device__ __forceinline__ float sigf(float x) {
    return __fdividef(1.f, 1.f + __expf(-x));
}
__device__ __forceinline__ float tanhfast(float x) {
    return 1.f - 2.f * __fdividef(1.f, __expf(2.f * x) + 1.f);
}

// ---------------- pack ----------------
__global__ void pack_kernel(const float* __restrict__ x) {
    int gid = blockIdx.x * blockDim.x + threadIdx.x;
    if (gid >= Nn * 96) return;
    int bt = gid / Nn, m = gid - bt * Nn;
    float2 v = *(const float2*)&x[(size_t)(bt * Nn + m) * 2];
    *(float2*)&d_Bmat[m * Jj + bt * 2] = v;
}

// ---------------- adj GEMM, split-K over 5 ----------------
__global__ __launch_bounds__(256) void gemm_adj(const float* __restrict__ adj) {
    __shared__ __align__(16) float As[32 * 68];
    __shared__ __align__(16) float Bs[32 * 192];
    int tid = threadIdx.x, tx = tid & 31, ty = tid >> 5;
    int rowb = blockIdx.x * 64;
    int kb0 = blockIdx.y * 800;
    float2 acc[4][6];
#pragma unroll
    for (int p = 0; p < 4; p++)
#pragma unroll
        for (int j = 0; j < 6; j++) acc[p][j] = make_float2(0.f, 0.f);
    for (int kt = 0; kt < 25; kt++) {
        int kb = kb0 + kt * 32;
#pragma unroll
        for (int q = 0; q < 8; q++) {
            int lin = tid + 256 * q;
            int r = lin >> 5, k = lin & 31;
            int gr = rowb + r;
            As[k * 68 + r] = (gr < Nn) ? adj[(size_t)gr * Nn + kb + k] : 0.f;
        }
#pragma unroll
        for (int q = 0; q < 24; q++) {
            int lin = tid + 256 * q;
            int k = lin / 192, c = lin - k * 192;
            Bs[lin] = d_Bmat[(kb + k) * Jj + c];
        }
        __syncthreads();
#pragma unroll 8
        for (int k = 0; k < 32; k++) {
            float4 a0 = *(float4*)&As[k * 68 + ty * 8];
            float4 a1 = *(float4*)&As[k * 68 + ty * 8 + 4];
            float2 ap[4] = {{a0.x, a0.y}, {a0.z, a0.w}, {a1.x, a1.y}, {a1.z, a1.w}};
#pragma unroll
            for (int j = 0; j < 6; j++) {
                float2 bj = dup2(Bs[k * 192 + tx + 32 * j]);
#pragma unroll
                for (int p = 0; p < 4; p++) acc[p][j] = ffma2(ap[p], bj, acc[p][j]);
            }
        }
        __syncthreads();
    }
    float* outp = d_XGp + (size_t)blockIdx.y * NJ;
#pragma unroll
    for (int p = 0; p < 4; p++) {
        int r0 = rowb + ty * 8 + 2 * p;
        if (r0 < Nn) {
#pragma unroll
            for (int j = 0; j < 6; j++) outp[r0 * Jj + tx + 32 * j] = acc[p][j].x;
        }
        if (r0 + 1 < Nn) {
#pragma unroll
            for (int j = 0; j < 6; j++) outp[(r0 + 1) * Jj + tx + 32 * j] = acc[p][j].y;
        }
    }
}

// ---------------- split-K reduce ----------------
__global__ void reduce_xg() {
    int i = blockIdx.x * blockDim.x + threadIdx.x;
    if (i >= NJ / 4) return;
    float4 s = ((const float4*)d_XGp)[i];
#pragma unroll
    for (int sp = 1; sp < SPLITK; sp++) {
        float4 v = ((const float4*)(d_XGp + (size_t)sp * NJ))[i];
        s.x += v.x; s.y += v.y; s.z += v.z; s.w += v.w;
    }
    ((float4*)d_XGs)[i] = s;
}

// ---------------- fused GCN + input-proj + 12-step LSTM + head ----------------
// 512 threads, 64 rows/block. Thread (tx,ty): rows ty*4..+3, col pairs
// (g*64 + 2tx, +1) for g=0..3 -> gate quadruples for h = {2tx, 2tx+1}.
#define WST 258
#define RST 68
#define SM_W (64 * WST)
#define SM_T (64 * RST)
#define LSTM_SMEM ((2*SM_W + 2*SM_T + 12*128 + 128 + 64 + 256 + 64) * 4)

__global__ __launch_bounds__(512, 1) void lstm_fused(
        const float* __restrict__ Wg,  const float* __restrict__ bg,
        const float* __restrict__ Wih, const float* __restrict__ Whh,
        const float* __restrict__ bih, const float* __restrict__ bhh,
        const float* __restrict__ Wout, const float* __restrict__ bout,
        float* __restrict__ out) {
    extern __shared__ __align__(16) float sm[];
    float* WsI = sm;                 // Wih^T [k][o], stride 258
    float* WsH = WsI + SM_W;         // Whh^T [k][o]
    float* Gt  = WsH + SM_W;         // G tile [h][r], stride 68
    float* Hs  = Gt + SM_T;          // H state [h][r]
    float* sxa = Hs + SM_T;          // xg per (t,r): 12*128
    float* sWg = sxa + 12 * 128;
    float* sbg = sWg + 128;
    float* sb  = sbg + 64;           // bih + bhh (256)
    float* sWo = sb + 256;
    int tid = threadIdx.x, tx = tid & 31, ty = tid >> 5;
    int rowb = blockIdx.x * 64;

#pragma unroll 8
    for (int q = 0; q < 32; q++) {           // both weights transposed into smem
        int lin = tid + 512 * q;
        int o = lin >> 6, k = lin & 63;
        WsI[k * WST + o] = Wih[lin];
        WsH[k * WST + o] = Whh[lin];
    }
    if (tid < 256) sb[tid] = bih[tid] + bhh[tid];
    if (tid < 128) sWg[tid] = Wg[tid];
    if (tid < 64) { sbg[tid] = bg[tid]; sWo[tid] = Wout[tid]; }
    if (tid < 64) {                           // preload xg for all 12 steps
        int R = rowb + tid;
        int b = R / Nn, n = R - b * Nn;
        int xib = n * Jj + b * (Tt * 2);
#pragma unroll
        for (int t = 0; t < Tt; t++) {
            sxa[t * 128 + 2 * tid]     = d_XGs[xib + 2 * t];
            sxa[t * 128 + 2 * tid + 1] = d_XGs[xib + 2 * t + 1];
        }
    }
    __syncthreads();

    float2 bb[4];                             // bias pairs per gate
#pragma unroll
    for (int g = 0; g < 4; g++) bb[g] = *(float2*)&sb[g * 64 + 2 * tx];
    float2 cst[4];                            // cell state: rows ty*4..+3, h={2tx,2tx+1}
#pragma unroll
    for (int r = 0; r < 4; r++) cst[r] = make_float2(0.f, 0.f);
    float2 acc[4][4];

    for (int t = 0; t < Tt; t++) {
        // (A) G tile: relu(x0*Wg[:,0] + x1*Wg[:,1] + bg), layout [h][r]
#pragma unroll
        for (int q = 0; q < 8; q++) {
            int lin = tid + 512 * q;
            int h = lin >> 6, r = lin & 63;
            float2 xv = *(float2*)&sxa[t * 128 + 2 * r];
            float2 wg = *(float2*)&sWg[2 * h];
            float v = xv.x * wg.x + xv.y * wg.y + sbg[h];
            Gt[h * RST + r] = v > 0.f ? v : 0.f;
        }
        __syncthreads();   // (B)
        // (C) gemms
#pragma unroll
        for (int r = 0; r < 4; r++)
#pragma unroll
            for (int g = 0; g < 4; g++) acc[r][g] = bb[g];
#pragma unroll 8
        for (int k = 0; k < 64; k++) {        // input projection
            float4 a4 = *(float4*)&Gt[k * RST + ty * 4];   // warp-broadcast
            float2 ad[4] = {dup2(a4.x), dup2(a4.y), dup2(a4.z), dup2(a4.w)};
#pragma unroll
            for (int g = 0; g < 4; g++) {
                float2 w = *(float2*)&WsI[k * WST + g * 64 + 2 * tx];
#pragma unroll
                for (int r = 0; r < 4; r++) acc[r][g] = ffma2(ad[r], w, acc[r][g]);
            }
        }
        if (t > 0) {                          // recurrent
#pragma unroll 8
            for (int k = 0; k < 64; k++) {
                float4 a4 = *(float4*)&Hs[k * RST + ty * 4];
                float2 ad[4] = {dup2(a4.x), dup2(a4.y), dup2(a4.z), dup2(a4.w)};
#pragma unroll
                for (int g = 0; g < 4; g++) {
                    float2 w = *(float2*)&WsH[k * WST + g * 64 + 2 * tx];
#pragma unroll
                    for (int r = 0; r < 4; r++) acc[r][g] = ffma2(ad[r], w, acc[r][g]);
                }
            }
        }
        // (D) cell update: acc[r] = {i, f, g, o}, each float2 over (h, h+1)
        float2 hn[4];
#pragma unroll
        for (int r = 0; r < 4; r++) {
            float2 ig = acc[r][0], fg = acc[r][1], gg = acc[r][2], og = acc[r][3];
            float2 cn;
            cn.x = sigf(fg.x) * cst[r].x + sigf(ig.x) * tanhfast(gg.x);
            cn.y = sigf(fg.y) * cst[r].y + sigf(ig.y) * tanhfast(gg.y);
            cst[r] = cn;
            hn[r].x = sigf(og.x) * tanhfast(cn.x);
            hn[r].y = sigf(og.y) * tanhfast(cn.y);
        }
        __syncthreads();   // (E) all reads of old Hs/Gt done
        // (F) store new H: per h value, 4 consecutive rows -> STS.128
        {
            float4 v0 = {hn[0].x, hn[1].x, hn[2].x, hn[3].x};
            float4 v1 = {hn[0].y, hn[1].y, hn[2].y, hn[3].y};
            *(float4*)&Hs[(2 * tx)     * RST + ty * 4] = v0;
            *(float4*)&Hs[(2 * tx + 1) * RST + ty * 4] = v1;
        }
    }
    __syncthreads();
    // output head
    if (tid < 64) {
        float s = 0.f;
#pragma unroll 8
        for (int k = 0; k < 64; k++) s += Hs[k * RST + tid] * sWo[k];
        out[rowb + tid] = s + bout[0];
    }
}

// ---------------- launch ----------------
extern "C" void kernel_launch(void* const* d_in, const int* in_sizes, int n_in,
                              void* d_out, int out_size) {
    const float* x    = (const float*)d_in[0];
    const float* adj  = (const float*)d_in[1];
    const float* Wg   = (const float*)d_in[2];
    const float* bg   = (const float*)d_in[3];
    const float* Wih  = (const float*)d_in[4];
    const float* Whh  = (const float*)d_in[5];
    const float* bih  = (const float*)d_in[6];
    const float* bhh  = (const float*)d_in[7];
    const float* Wout = (const float*)d_in[8];
    const float* bout = (const float*)d_in[9];
    float* out = (float*)d_out;

    cudaFuncSetAttribute(lstm_fused, cudaFuncAttributeMaxDynamicSharedMemorySize, LSTM_SMEM);

    pack_kernel<<<(Nn * 96 + 255) / 256, 256>>>(x);
    dim3 ga(63, SPLITK);
    gemm_adj<<<ga, 256>>>(adj);
    reduce_xg<<<(NJ / 4 + 255) / 256, 256>>>();
    lstm_fused<<<BNr / 64, 512, LSTM_SMEM>>>(Wg, bg, Wih, Whh, bih, bhh, Wout, bout, out);
}

// round 6
// speedup vs baseline: 2.6507x; 1.6445x over previous
#include <cuda_runtime.h>
#include <cuda_bf16.h>
#include <stdint.h>

#define Tt 12
#define Nn 4000
#define Jj 192          // B*T*C
#define BNr 32000       // B*N
#define NJ (Nn*Jj)
#define SPLITK 5

// ---------------- scratch ----------------
__device__ float d_Bmat[NJ];
__device__ float d_XGp[SPLITK * NJ];
__device__ float d_XGs[NJ];

// ---------------- helpers ----------------
union F2U { float2 f; unsigned long long u; };
__device__ __forceinline__ float2 ffma2(float2 a, float2 b, float2 c) {
    F2U A, B, C, D; A.f = a; B.f = b; C.f = c;
    asm("fma.rn.f32x2 %0, %1, %2, %3;" : "=l"(D.u) : "l"(A.u), "l"(B.u), "l"(C.u));
    return D.f;
}
__device__ __forceinline__ float2 dup2(float x) { return make_float2(x, x); }
__device__ __forceinline__ float sigf(float x) {
    return __fdividef(1.f, 1.f + __expf(-x));
}
__device__ __forceinline__ float tanhfast(float x) {
    return 1.f - 2.f * __fdividef(1.f, __expf(2.f * x) + 1.f);
}
__device__ __forceinline__ void split_bf(float z, __nv_bfloat16& h, __nv_bfloat16& l) {
    h = __float2bfloat16(z);
    l = __float2bfloat16(z - __bfloat162float(h));
}
__device__ __forceinline__ uint32_t pack2(__nv_bfloat16 a, __nv_bfloat16 b) {
    __nv_bfloat162 v; v.x = a; v.y = b;
    return *(uint32_t*)&v;
}
__device__ __forceinline__ void bmma(float& d0, float& d1, float& d2, float& d3,
                                     uint32_t a0, uint32_t a1, uint32_t a2, uint32_t a3,
                                     uint32_t b0, uint32_t b1) {
    asm volatile("mma.sync.aligned.m16n8k16.row.col.f32.bf16.bf16.f32 "
        "{%0,%1,%2,%3}, {%4,%5,%6,%7}, {%8,%9}, {%0,%1,%2,%3};"
        : "+f"(d0), "+f"(d1), "+f"(d2), "+f"(d3)
        : "r"(a0), "r"(a1), "r"(a2), "r"(a3), "r"(b0), "r"(b1));
}

// ---------------- pack ----------------
__global__ void pack_kernel(const float* __restrict__ x) {
    int gid = blockIdx.x * blockDim.x + threadIdx.x;
    if (gid >= Nn * 96) return;
    int bt = gid / Nn, m = gid - bt * Nn;
    float2 v = *(const float2*)&x[(size_t)(bt * Nn + m) * 2];
    *(float2*)&d_Bmat[m * Jj + bt * 2] = v;
}

// ---------------- adj GEMM (FFMA2, split-K=5) ----------------
__global__ __launch_bounds__(256) void gemm_adj(const float* __restrict__ adj) {
    __shared__ __align__(16) float As[32 * 68];
    __shared__ __align__(16) float Bs[32 * 192];
    int tid = threadIdx.x, tx = tid & 31, ty = tid >> 5;
    int rowb = blockIdx.x * 64;
    int kb0 = blockIdx.y * 800;
    float2 acc[4][6];
#pragma unroll
    for (int p = 0; p < 4; p++)
#pragma unroll
        for (int j = 0; j < 6; j++) acc[p][j] = make_float2(0.f, 0.f);
    for (int kt = 0; kt < 25; kt++) {
        int kb = kb0 + kt * 32;
#pragma unroll
        for (int q = 0; q < 8; q++) {
            int lin = tid + 256 * q;
            int r = lin >> 5, k = lin & 31;
            int gr = rowb + r;
            As[k * 68 + r] = (gr < Nn) ? adj[(size_t)gr * Nn + kb + k] : 0.f;
        }
#pragma unroll
        for (int q = 0; q < 24; q++) {
            int lin = tid + 256 * q;
            int k = lin / 192, c = lin - k * 192;
            Bs[lin] = d_Bmat[(kb + k) * Jj + c];
        }
        __syncthreads();
#pragma unroll 8
        for (int k = 0; k < 32; k++) {
            float4 a0 = *(float4*)&As[k * 68 + ty * 8];
            float4 a1 = *(float4*)&As[k * 68 + ty * 8 + 4];
            float2 ap[4] = {{a0.x, a0.y}, {a0.z, a0.w}, {a1.x, a1.y}, {a1.z, a1.w}};
#pragma unroll
            for (int j = 0; j < 6; j++) {
                float2 bj = dup2(Bs[k * 192 + tx + 32 * j]);
#pragma unroll
                for (int p = 0; p < 4; p++) acc[p][j] = ffma2(ap[p], bj, acc[p][j]);
            }
        }
        __syncthreads();
    }
    float* outp = d_XGp + (size_t)blockIdx.y * NJ;
#pragma unroll
    for (int p = 0; p < 4; p++) {
        int r0 = rowb + ty * 8 + 2 * p;
        if (r0 < Nn) {
#pragma unroll
            for (int j = 0; j < 6; j++) outp[r0 * Jj + tx + 32 * j] = acc[p][j].x;
        }
        if (r0 + 1 < Nn) {
#pragma unroll
            for (int j = 0; j < 6; j++) outp[(r0 + 1) * Jj + tx + 32 * j] = acc[p][j].y;
        }
    }
}

__global__ void reduce_xg() {
    int i = blockIdx.x * blockDim.x + threadIdx.x;
    if (i >= NJ / 4) return;
    float4 s = ((const float4*)d_XGp)[i];
#pragma unroll
    for (int sp = 1; sp < SPLITK; sp++) {
        float4 v = ((const float4*)(d_XGp + (size_t)sp * NJ))[i];
        s.x += v.x; s.y += v.y; s.z += v.z; s.w += v.w;
    }
    ((float4*)d_XGs)[i] = s;
}

// ---------------- mma.sync LSTM: 64 rows/block, 8 warps, N=256 gates ----------------
#define WTS 72                 // k-stride (bf16 elems) for all tiles
#define WMAT_B (256 * WTS * 2) // 36864 bytes per weight matrix
#define AT_B   (64 * WTS * 2)  // 9216 bytes per activation tile
#define OFF_WIH_H 0u
#define OFF_WIH_L 36864u
#define OFF_WHH_H 73728u
#define OFF_WHH_L 110592u
#define OFF_GH 147456u
#define OFF_GL 156672u
#define OFF_HH 165888u
#define OFF_HL 175104u
#define OFF_SXA 184320u        // 12*64*2 floats = 6144B
#define OFF_BIAS 190464u       // 256 floats
#define OFF_WG 191488u         // 128 floats
#define OFF_BG 192000u         // 64 floats
#define OFF_WO 192256u         // 64 floats
#define OFF_OUTP 192512u       // 8*66 floats = 2112B
#define LSTM_SMEM 194624u

// 3-term split pass: acc += Ah@Bh + Al@Bh + Ah@Bl  (K=64, M=64, warp n-slice 32)
__device__ __forceinline__ void mma_pass(float (*acc)[4][4],
        const __nv_bfloat16* Ah, const __nv_bfloat16* Al,
        const __nv_bfloat16* Bh, const __nv_bfloat16* Bl,
        int g, int t4, int w) {
#pragma unroll
    for (int kc = 0; kc < 4; kc++) {
        int kk = kc * 16 + 2 * t4;
        uint32_t ah[4][4], al[4][4];
#pragma unroll
        for (int mt = 0; mt < 4; mt++) {
            const __nv_bfloat16* p0 = Ah + (16 * mt + g) * WTS + kk;
            const __nv_bfloat16* p1 = Ah + (16 * mt + 8 + g) * WTS + kk;
            ah[mt][0] = *(const uint32_t*)p0;
            ah[mt][1] = *(const uint32_t*)p1;
            ah[mt][2] = *(const uint32_t*)(p0 + 8);
            ah[mt][3] = *(const uint32_t*)(p1 + 8);
            const __nv_bfloat16* q0 = Al + (16 * mt + g) * WTS + kk;
            const __nv_bfloat16* q1 = Al + (16 * mt + 8 + g) * WTS + kk;
            al[mt][0] = *(const uint32_t*)q0;
            al[mt][1] = *(const uint32_t*)q1;
            al[mt][2] = *(const uint32_t*)(q0 + 8);
            al[mt][3] = *(const uint32_t*)(q1 + 8);
        }
#pragma unroll
        for (int nt = 0; nt < 4; nt++) {
            const __nv_bfloat16* pb = Bh + (w * 32 + nt * 8 + g) * WTS + kk;
            const __nv_bfloat16* pl = Bl + (w * 32 + nt * 8 + g) * WTS + kk;
            uint32_t bh0 = *(const uint32_t*)pb, bh1 = *(const uint32_t*)(pb + 8);
            uint32_t bl0 = *(const uint32_t*)pl, bl1 = *(const uint32_t*)(pl + 8);
#pragma unroll
            for (int mt = 0; mt < 4; mt++) {
                bmma(acc[mt][nt][0], acc[mt][nt][1], acc[mt][nt][2], acc[mt][nt][3],
                     ah[mt][0], ah[mt][1], ah[mt][2], ah[mt][3], bh0, bh1);
                bmma(acc[mt][nt][0], acc[mt][nt][1], acc[mt][nt][2], acc[mt][nt][3],
                     al[mt][0], al[mt][1], al[mt][2], al[mt][3], bh0, bh1);
                bmma(acc[mt][nt][0], acc[mt][nt][1], acc[mt][nt][2], acc[mt][nt][3],
                     ah[mt][0], ah[mt][1], ah[mt][2], ah[mt][3], bl0, bl1);
            }
        }
    }
}

__global__ __launch_bounds__(256) void lstm_mma(
        const float* __restrict__ Wg,  const float* __restrict__ bg,
        const float* __restrict__ Wih, const float* __restrict__ Whh,
        const float* __restrict__ bih, const float* __restrict__ bhh,
        const float* __restrict__ Wout, const float* __restrict__ bout,
        float* __restrict__ out) {
    extern __shared__ __align__(16) char smc[];
    __nv_bfloat16* WIHh = (__nv_bfloat16*)(smc + OFF_WIH_H);
    __nv_bfloat16* WIHl = (__nv_bfloat16*)(smc + OFF_WIH_L);
    __nv_bfloat16* WHHh = (__nv_bfloat16*)(smc + OFF_WHH_H);
    __nv_bfloat16* WHHl = (__nv_bfloat16*)(smc + OFF_WHH_L);
    __nv_bfloat16* Gh = (__nv_bfloat16*)(smc + OFF_GH);
    __nv_bfloat16* Gl = (__nv_bfloat16*)(smc + OFF_GL);
    __nv_bfloat16* Hh = (__nv_bfloat16*)(smc + OFF_HH);
    __nv_bfloat16* Hl = (__nv_bfloat16*)(smc + OFF_HL);
    float* sxa   = (float*)(smc + OFF_SXA);
    float* sbias = (float*)(smc + OFF_BIAS);
    float* sWg   = (float*)(smc + OFF_WG);
    float* sbg   = (float*)(smc + OFF_BG);
    float* sWo   = (float*)(smc + OFF_WO);
    float* outp  = (float*)(smc + OFF_OUTP);

    int tid = threadIdx.x, wid = tid >> 5, lane = tid & 31;
    int g = lane >> 2, t4 = lane & 3;
    int rowb = blockIdx.x * 64;

    // weight split + permute: n = w*32 + gate*8 + p, (gate = o>>6, h = o&63, w=h>>3, p=h&7)
    for (int idx = tid; idx < 16384; idx += 256) {
        int o = idx >> 6, k = idx & 63;
        int gate = o >> 6, h = o & 63;
        int n = (h >> 3) * 32 + gate * 8 + (h & 7);
        __nv_bfloat16 hi, lo;
        split_bf(Wih[idx], hi, lo);
        WIHh[n * WTS + k] = hi; WIHl[n * WTS + k] = lo;
        split_bf(Whh[idx], hi, lo);
        WHHh[n * WTS + k] = hi; WHHl[n * WTS + k] = lo;
    }
    if (tid < 256) {
        int n = tid;
        int gate = (n >> 3) & 3, h = (n >> 5) * 8 + (n & 7);
        int o = gate * 64 + h;
        sbias[n] = bih[o] + bhh[o];
    }
    if (tid < 128) sWg[tid] = Wg[tid];
    if (tid < 64) { sbg[tid] = bg[tid]; sWo[tid] = Wout[tid]; }
    if (tid < 64) {
        int R = rowb + tid;
        int b = R / Nn, n = R - b * Nn;
        int base = n * Jj + b * (Tt * 2);
#pragma unroll
        for (int t = 0; t < Tt; t++) {
            sxa[(t * 64 + tid) * 2]     = d_XGs[base + 2 * t];
            sxa[(t * 64 + tid) * 2 + 1] = d_XGs[base + 2 * t + 1];
        }
    }
    __syncthreads();

    // per-thread constants
    float bias_r[4][2], wo0, wo1;
#pragma unroll
    for (int nt = 0; nt < 4; nt++) {
        bias_r[nt][0] = sbias[wid * 32 + nt * 8 + 2 * t4];
        bias_r[nt][1] = sbias[wid * 32 + nt * 8 + 2 * t4 + 1];
    }
    wo0 = sWo[wid * 8 + 2 * t4];
    wo1 = sWo[wid * 8 + 2 * t4 + 1];

    float cst[4][4];
#pragma unroll
    for (int mt = 0; mt < 4; mt++)
#pragma unroll
        for (int q = 0; q < 4; q++) cst[mt][q] = 0.f;

    for (int t = 0; t < Tt; t++) {
        // ---- build G tile (relu GCN), bf16 hi/lo ----
        {
            int wr = g;                      // row within warp's 8
            int kq = t4;
            int grow = wid * 8 + wr;
            float x0 = sxa[(t * 64 + grow) * 2];
            float x1 = sxa[(t * 64 + grow) * 2 + 1];
#pragma unroll
            for (int j = 0; j < 8; j++) {
                int k = kq * 2 + 8 * j;
                float z0 = fmaf(x0, sWg[2 * k],     fmaf(x1, sWg[2 * k + 1], sbg[k]));
                float z1 = fmaf(x0, sWg[2 * k + 2], fmaf(x1, sWg[2 * k + 3], sbg[k + 1]));
                z0 = fmaxf(z0, 0.f); z1 = fmaxf(z1, 0.f);
                __nv_bfloat16 h0, l0, h1, l1;
                split_bf(z0, h0, l0); split_bf(z1, h1, l1);
                *(uint32_t*)(Gh + grow * WTS + k) = pack2(h0, h1);
                *(uint32_t*)(Gl + grow * WTS + k) = pack2(l0, l1);
            }
        }
        __syncthreads();
        // ---- gemms ----
        float acc[4][4][4];
#pragma unroll
        for (int mt = 0; mt < 4; mt++)
#pragma unroll
            for (int nt = 0; nt < 4; nt++)
#pragma unroll
                for (int q = 0; q < 4; q++) acc[mt][nt][q] = 0.f;
        mma_pass(acc, Gh, Gl, WIHh, WIHl, g, t4, wid);
        if (t > 0) mma_pass(acc, Hh, Hl, WHHh, WHHl, g, t4, wid);
        // ---- cell update (registers): nt = gate, d = 2s+j ----
        float hnew[4][4];
#pragma unroll
        for (int mt = 0; mt < 4; mt++) {
#pragma unroll
            for (int s = 0; s < 2; s++) {
#pragma unroll
                for (int j = 0; j < 2; j++) {
                    int d = 2 * s + j;
                    float ig = acc[mt][0][d] + bias_r[0][j];
                    float fg = acc[mt][1][d] + bias_r[1][j];
                    float gg = acc[mt][2][d] + bias_r[2][j];
                    float og = acc[mt][3][d] + bias_r[3][j];
                    float cn = sigf(fg) * cst[mt][d] + sigf(ig) * tanhfast(gg);
                    cst[mt][d] = cn;
                    hnew[mt][d] = sigf(og) * tanhfast(cn);
                }
            }
        }
        __syncthreads();   // all reads of Gh/Gl/Hh/Hl done
        if (t < Tt - 1) {
            // store new H (bf16 hi/lo) for next step's recurrent pass
#pragma unroll
            for (int mt = 0; mt < 4; mt++) {
#pragma unroll
                for (int s = 0; s < 2; s++) {
                    int row = 16 * mt + 8 * s + g;
                    float z0 = hnew[mt][2 * s], z1 = hnew[mt][2 * s + 1];
                    __nv_bfloat16 h0, l0, h1, l1;
                    split_bf(z0, h0, l0); split_bf(z1, h1, l1);
                    *(uint32_t*)(Hh + row * WTS + wid * 8 + 2 * t4) = pack2(h0, h1);
                    *(uint32_t*)(Hl + row * WTS + wid * 8 + 2 * t4) = pack2(l0, l1);
                }
            }
        } else {
            // output head partials: per row, this warp covers h = wid*8 .. +7
#pragma unroll
            for (int mt = 0; mt < 4; mt++) {
#pragma unroll
                for (int s = 0; s < 2; s++) {
                    int row = 16 * mt + 8 * s + g;
                    float c = hnew[mt][2 * s] * wo0 + hnew[mt][2 * s + 1] * wo1;
                    c += __shfl_down_sync(0xffffffffu, c, 2, 4);
                    c += __shfl_down_sync(0xffffffffu, c, 1, 4);
                    if (t4 == 0) outp[wid * 66 + row] = c;
                }
            }
        }
    }
    __syncthreads();
    if (tid < 64) {
        float s = 0.f;
#pragma unroll
        for (int w = 0; w < 8; w++) s += outp[w * 66 + tid];
        out[rowb + tid] = s + bout[0];
    }
}

// ---------------- launch ----------------
extern "C" void kernel_launch(void* const* d_in, const int* in_sizes, int n_in,
                              void* d_out, int out_size) {
    const float* x    = (const float*)d_in[0];
    const float* adj  = (const float*)d_in[1];
    const float* Wg   = (const float*)d_in[2];
    const float* bg   = (const float*)d_in[3];
    const float* Wih  = (const float*)d_in[4];
    const float* Whh  = (const float*)d_in[5];
    const float* bih  = (const float*)d_in[6];
    const float* bhh  = (const float*)d_in[7];
    const float* Wout = (const float*)d_in[8];
    const float* bout = (const float*)d_in[9];
    float* out = (float*)d_out;

    cudaFuncSetAttribute(lstm_mma, cudaFuncAttributeMaxDynamicSharedMemorySize, LSTM_SMEM);

    pack_kernel<<<(Nn * 96 + 255) / 256, 256>>>(x);
    dim3 ga(63, SPLITK);
    gemm_adj<<<ga, 256>>>(adj);
    reduce_xg<<<(NJ / 4 + 255) / 256, 256>>>();
    lstm_mma<<<BNr / 64, 256, LSTM_SMEM>>>(Wg, bg, Wih, Whh, bih, bhh, Wout, bout, out);
}

// round 7
// speedup vs baseline: 3.4458x; 1.3000x over previous
#include <cuda_runtime.h>
#include <cuda_bf16.h>
#include <stdint.h>

#define Tt 12
#define Nn 4000
#define Jj 192          // B*T*C
#define BNr 32000       // B*N
#define NJ (Nn*Jj)
#define SPLITK 5

// ---------------- scratch ----------------
__device__ uint32_t d_XTh32[Jj * 2000];   // x^T hi: [j][m-pair] packed bf16x2
__device__ uint32_t d_XTl32[Jj * 2000];   // x^T lo
__device__ float d_XGp[SPLITK * NJ];      // split-K partials of adj @ x
__device__ float d_XGs[NJ];               // summed adj @ x
__device__ __align__(16) char d_Wall[147456];  // pre-split/permuted lstm weights (smem image)

// ---------------- helpers ----------------
__device__ __forceinline__ float sigf(float x) {
    return __fdividef(1.f, 1.f + __expf(-x));
}
__device__ __forceinline__ float tanhfast(float x) {
    return 1.f - 2.f * __fdividef(1.f, __expf(2.f * x) + 1.f);
}
__device__ __forceinline__ void split_bf(float z, __nv_bfloat16& h, __nv_bfloat16& l) {
    h = __float2bfloat16(z);
    l = __float2bfloat16(z - __bfloat162float(h));
}
__device__ __forceinline__ uint32_t pack2(__nv_bfloat16 a, __nv_bfloat16 b) {
    __nv_bfloat162 v; v.x = a; v.y = b;
    return *(uint32_t*)&v;
}
__device__ __forceinline__ void bmma(float& d0, float& d1, float& d2, float& d3,
                                     uint32_t a0, uint32_t a1, uint32_t a2, uint32_t a3,
                                     uint32_t b0, uint32_t b1) {
    asm volatile("mma.sync.aligned.m16n8k16.row.col.f32.bf16.bf16.f32 "
        "{%0,%1,%2,%3}, {%4,%5,%6,%7}, {%8,%9}, {%0,%1,%2,%3};"
        : "+f"(d0), "+f"(d1), "+f"(d2), "+f"(d3)
        : "r"(a0), "r"(a1), "r"(a2), "r"(a3), "r"(b0), "r"(b1));
}

// ---------------- prep: weight split+permute into smem image ----------------
// layout n = w*32 + gate*8 + p (gate = o>>6, h = o&63, w=h>>3, p=h&7), stride 72 bf16
__global__ void prep_w(const float* __restrict__ Wih, const float* __restrict__ Whh) {
    int idx = blockIdx.x * 256 + threadIdx.x;   // 16384 threads
    if (idx >= 16384) return;
    int o = idx >> 6, k = idx & 63;
    int gate = o >> 6, h = o & 63;
    int n = (h >> 3) * 32 + gate * 8 + (h & 7);
    __nv_bfloat16 hi, lo;
    split_bf(Wih[idx], hi, lo);
    *(__nv_bfloat16*)(d_Wall +          (n * 72 + k) * 2) = hi;
    *(__nv_bfloat16*)(d_Wall + 36864u + (n * 72 + k) * 2) = lo;
    split_bf(Whh[idx], hi, lo);
    *(__nv_bfloat16*)(d_Wall + 73728u + (n * 72 + k) * 2) = hi;
    *(__nv_bfloat16*)(d_Wall + 110592u + (n * 72 + k) * 2) = lo;
}

// ---------------- pack x: transpose + bf16 hi/lo split, [j][m] pairs ----------------
__global__ void pack_x(const float* __restrict__ x) {
    int gid = blockIdx.x * blockDim.x + threadIdx.x;
    if (gid >= Jj * 2000) return;
    int j = gid / 2000, m2 = gid - j * 2000;
    int bt = j >> 1, c = j & 1;
    size_t base = (size_t)bt * Nn * 2 + c;
    float v0 = x[base + (size_t)(2 * m2) * 2];
    float v1 = x[base + (size_t)(2 * m2 + 1) * 2];
    __nv_bfloat16 h0, l0, h1, l1;
    split_bf(v0, h0, l0); split_bf(v1, h1, l1);
    d_XTh32[gid] = pack2(h0, h1);
    d_XTl32[gid] = pack2(l0, l1);
}

// ---------------- adj GEMM via mma.sync (bf16 3-term split, split-K=5) ----------------
// BM=64, BN=192 (warp n-slice 24), BK=32, 25 iters of 800-K chunk.
#define BTS 40      // bf16 k-stride in smem tiles
__global__ __launch_bounds__(256) void gemm_adj_mma(const float* __restrict__ adj) {
    __shared__ __align__(16) __nv_bfloat16 Ah[64 * BTS], Al[64 * BTS];
    __shared__ __align__(16) __nv_bfloat16 Bh[192 * BTS], Bl[192 * BTS];
    int tid = threadIdx.x, wid = tid >> 5, lane = tid & 31;
    int g = lane >> 2, t4 = lane & 3;
    int rowb = blockIdx.x * 64;
    int kb0 = blockIdx.y * 800;
    float acc[4][3][4];
#pragma unroll
    for (int mt = 0; mt < 4; mt++)
#pragma unroll
        for (int nt = 0; nt < 3; nt++)
#pragma unroll
            for (int q = 0; q < 4; q++) acc[mt][nt][q] = 0.f;

    for (int it = 0; it < 25; it++) {
        int kb = kb0 + it * 32;
        // A tile: 64 rows x 16 words, fp32->bf16 split
#pragma unroll
        for (int q = 0; q < 4; q++) {
            int lin = tid + 256 * q;
            int r = lin >> 4, w = lin & 15;
            int gr = rowb + r;
            float2 v = (gr < Nn) ? *(const float2*)&adj[(size_t)gr * Nn + kb + 2 * w]
                                 : make_float2(0.f, 0.f);
            __nv_bfloat16 h0, l0, h1, l1;
            split_bf(v.x, h0, l0); split_bf(v.y, h1, l1);
            ((uint32_t*)Ah)[r * (BTS/2) + w] = pack2(h0, h1);
            ((uint32_t*)Al)[r * (BTS/2) + w] = pack2(l0, l1);
        }
        // B tile: 192 rows x 16 words, already split
        int kw = kb >> 1;
#pragma unroll
        for (int q = 0; q < 12; q++) {
            int lin = tid + 256 * q;
            int j = lin >> 4, w = lin & 15;
            ((uint32_t*)Bh)[j * (BTS/2) + w] = d_XTh32[j * 2000 + kw + w];
            ((uint32_t*)Bl)[j * (BTS/2) + w] = d_XTl32[j * 2000 + kw + w];
        }
        __syncthreads();
#pragma unroll
        for (int kc = 0; kc < 2; kc++) {
            int kk = kc * 16 + 2 * t4;
            uint32_t ah[4][4], al[4][4];
#pragma unroll
            for (int mt = 0; mt < 4; mt++) {
                const __nv_bfloat16* p0 = Ah + (16 * mt + g) * BTS + kk;
                const __nv_bfloat16* p1 = Ah + (16 * mt + 8 + g) * BTS + kk;
                ah[mt][0] = *(const uint32_t*)p0;
                ah[mt][1] = *(const uint32_t*)p1;
                ah[mt][2] = *(const uint32_t*)(p0 + 8);
                ah[mt][3] = *(const uint32_t*)(p1 + 8);
                const __nv_bfloat16* q0 = Al + (16 * mt + g) * BTS + kk;
                const __nv_bfloat16* q1 = Al + (16 * mt + 8 + g) * BTS + kk;
                al[mt][0] = *(const uint32_t*)q0;
                al[mt][1] = *(const uint32_t*)q1;
                al[mt][2] = *(const uint32_t*)(q0 + 8);
                al[mt][3] = *(const uint32_t*)(q1 + 8);
            }
#pragma unroll
            for (int nt = 0; nt < 3; nt++) {
                int n = wid * 24 + nt * 8 + g;
                const __nv_bfloat16* pb = Bh + n * BTS + kk;
                const __nv_bfloat16* pl = Bl + n * BTS + kk;
                uint32_t bh0 = *(const uint32_t*)pb, bh1 = *(const uint32_t*)(pb + 8);
                uint32_t bl0 = *(const uint32_t*)pl, bl1 = *(const uint32_t*)(pl + 8);
#pragma unroll
                for (int mt = 0; mt < 4; mt++)
                    bmma(acc[mt][nt][0], acc[mt][nt][1], acc[mt][nt][2], acc[mt][nt][3],
                         ah[mt][0], ah[mt][1], ah[mt][2], ah[mt][3], bh0, bh1);
#pragma unroll
                for (int mt = 0; mt < 4; mt++)
                    bmma(acc[mt][nt][0], acc[mt][nt][1], acc[mt][nt][2], acc[mt][nt][3],
                         al[mt][0], al[mt][1], al[mt][2], al[mt][3], bh0, bh1);
#pragma unroll
                for (int mt = 0; mt < 4; mt++)
                    bmma(acc[mt][nt][0], acc[mt][nt][1], acc[mt][nt][2], acc[mt][nt][3],
                         ah[mt][0], ah[mt][1], ah[mt][2], ah[mt][3], bl0, bl1);
            }
        }
        __syncthreads();
    }
    float* outp = d_XGp + (size_t)blockIdx.y * NJ;
#pragma unroll
    for (int mt = 0; mt < 4; mt++) {
#pragma unroll
        for (int nt = 0; nt < 3; nt++) {
            int r0 = rowb + 16 * mt + g;
            int col = wid * 24 + nt * 8 + 2 * t4;
            if (r0 < Nn) {
                float2 v = {acc[mt][nt][0], acc[mt][nt][1]};
                *(float2*)&outp[r0 * Jj + col] = v;
            }
            if (r0 + 8 < Nn) {
                float2 v = {acc[mt][nt][2], acc[mt][nt][3]};
                *(float2*)&outp[(r0 + 8) * Jj + col] = v;
            }
        }
    }
}

__global__ void reduce_xg() {
    int i = blockIdx.x * blockDim.x + threadIdx.x;
    if (i >= NJ / 4) return;
    float4 s = ((const float4*)d_XGp)[i];
#pragma unroll
    for (int sp = 1; sp < SPLITK; sp++) {
        float4 v = ((const float4*)(d_XGp + (size_t)sp * NJ))[i];
        s.x += v.x; s.y += v.y; s.z += v.z; s.w += v.w;
    }
    ((float4*)d_XGs)[i] = s;
}

// ---------------- mma.sync LSTM: 64 rows/block, 8 warps, N=256 gates ----------------
#define WTS 72
#define OFF_WIH_H 0u
#define OFF_WIH_L 36864u
#define OFF_WHH_H 73728u
#define OFF_WHH_L 110592u
#define OFF_GH 147456u
#define OFF_GL 156672u
#define OFF_HH 165888u
#define OFF_HL 175104u
#define OFF_SXA 184320u        // 12*64*2 floats
#define OFF_BIAS 190464u       // 256 floats
#define OFF_WG 191488u
#define OFF_BG 192000u
#define OFF_WO 192256u
#define OFF_OUTP 192512u       // 8*66 floats
#define LSTM_SMEM 194624u

// 3-term split pass, term-outer / mt-inner (dependency distance 4)
__device__ __forceinline__ void mma_pass(float (*acc)[4][4],
        const __nv_bfloat16* Ah, const __nv_bfloat16* Al,
        const __nv_bfloat16* Bh, const __nv_bfloat16* Bl,
        int g, int t4, int w) {
#pragma unroll
    for (int kc = 0; kc < 4; kc++) {
        int kk = kc * 16 + 2 * t4;
        uint32_t ah[4][4], al[4][4];
#pragma unroll
        for (int mt = 0; mt < 4; mt++) {
            const __nv_bfloat16* p0 = Ah + (16 * mt + g) * WTS + kk;
            const __nv_bfloat16* p1 = Ah + (16 * mt + 8 + g) * WTS + kk;
            ah[mt][0] = *(const uint32_t*)p0;
            ah[mt][1] = *(const uint32_t*)p1;
            ah[mt][2] = *(const uint32_t*)(p0 + 8);
            ah[mt][3] = *(const uint32_t*)(p1 + 8);
            const __nv_bfloat16* q0 = Al + (16 * mt + g) * WTS + kk;
            const __nv_bfloat16* q1 = Al + (16 * mt + 8 + g) * WTS + kk;
            al[mt][0] = *(const uint32_t*)q0;
            al[mt][1] = *(const uint32_t*)q1;
            al[mt][2] = *(const uint32_t*)(q0 + 8);
            al[mt][3] = *(const uint32_t*)(q1 + 8);
        }
#pragma unroll
        for (int nt = 0; nt < 4; nt++) {
            const __nv_bfloat16* pb = Bh + (w * 32 + nt * 8 + g) * WTS + kk;
            const __nv_bfloat16* pl = Bl + (w * 32 + nt * 8 + g) * WTS + kk;
            uint32_t bh0 = *(const uint32_t*)pb, bh1 = *(const uint32_t*)(pb + 8);
            uint32_t bl0 = *(const uint32_t*)pl, bl1 = *(const uint32_t*)(pl + 8);
#pragma unroll
            for (int mt = 0; mt < 4; mt++)
                bmma(acc[mt][nt][0], acc[mt][nt][1], acc[mt][nt][2], acc[mt][nt][3],
                     ah[mt][0], ah[mt][1], ah[mt][2], ah[mt][3], bh0, bh1);
#pragma unroll
            for (int mt = 0; mt < 4; mt++)
                bmma(acc[mt][nt][0], acc[mt][nt][1], acc[mt][nt][2], acc[mt][nt][3],
                     al[mt][0], al[mt][1], al[mt][2], al[mt][3], bh0, bh1);
#pragma unroll
            for (int mt = 0; mt < 4; mt++)
                bmma(acc[mt][nt][0], acc[mt][nt][1], acc[mt][nt][2], acc[mt][nt][3],
                     ah[mt][0], ah[mt][1], ah[mt][2], ah[mt][3], bl0, bl1);
        }
    }
}

__global__ __launch_bounds__(256) void lstm_mma(
        const float* __restrict__ Wg,  const float* __restrict__ bg,
        const float* __restrict__ bih, const float* __restrict__ bhh,
        const float* __restrict__ Wout, const float* __restrict__ bout,
        float* __restrict__ out) {
    extern __shared__ __align__(16) char smc[];
    __nv_bfloat16* WIHh = (__nv_bfloat16*)(smc + OFF_WIH_H);
    __nv_bfloat16* WIHl = (__nv_bfloat16*)(smc + OFF_WIH_L);
    __nv_bfloat16* WHHh = (__nv_bfloat16*)(smc + OFF_WHH_H);
    __nv_bfloat16* WHHl = (__nv_bfloat16*)(smc + OFF_WHH_L);
    __nv_bfloat16* Gh = (__nv_bfloat16*)(smc + OFF_GH);
    __nv_bfloat16* Gl = (__nv_bfloat16*)(smc + OFF_GL);
    __nv_bfloat16* Hh = (__nv_bfloat16*)(smc + OFF_HH);
    __nv_bfloat16* Hl = (__nv_bfloat16*)(smc + OFF_HL);
    float* sxa   = (float*)(smc + OFF_SXA);
    float* sbias = (float*)(smc + OFF_BIAS);
    float* sWg   = (float*)(smc + OFF_WG);
    float* sbg   = (float*)(smc + OFF_BG);
    float* sWo   = (float*)(smc + OFF_WO);
    float* outp  = (float*)(smc + OFF_OUTP);

    int tid = threadIdx.x, wid = tid >> 5, lane = tid & 31;
    int g = lane >> 2, t4 = lane & 3;
    int rowb = blockIdx.x * 64;

    // linear copy of pre-split weight image
    {
        const uint4* src = (const uint4*)d_Wall;
        uint4* dst = (uint4*)smc;
#pragma unroll
        for (int q = 0; q < 36; q++) dst[tid + 256 * q] = src[tid + 256 * q];
    }
    if (tid < 256) {
        int n = tid;
        int gate = (n >> 3) & 3, h = (n >> 5) * 8 + (n & 7);
        int o = gate * 64 + h;
        sbias[n] = bih[o] + bhh[o];
    }
    if (tid < 128) sWg[tid] = Wg[tid];
    if (tid < 64) { sbg[tid] = bg[tid]; sWo[tid] = Wout[tid]; }
    if (tid < 64) {
        int R = rowb + tid;
        int b = R / Nn, n = R - b * Nn;
        int base = n * Jj + b * (Tt * 2);
#pragma unroll
        for (int t = 0; t < Tt; t++) {
            sxa[(t * 64 + tid) * 2]     = d_XGs[base + 2 * t];
            sxa[(t * 64 + tid) * 2 + 1] = d_XGs[base + 2 * t + 1];
        }
    }
    __syncthreads();

    float bias_r[4][2], wo0, wo1;
#pragma unroll
    for (int nt = 0; nt < 4; nt++) {
        bias_r[nt][0] = sbias[wid * 32 + nt * 8 + 2 * t4];
        bias_r[nt][1] = sbias[wid * 32 + nt * 8 + 2 * t4 + 1];
    }
    wo0 = sWo[wid * 8 + 2 * t4];
    wo1 = sWo[wid * 8 + 2 * t4 + 1];

    float cst[4][4];
#pragma unroll
    for (int mt = 0; mt < 4; mt++)
#pragma unroll
        for (int q = 0; q < 4; q++) cst[mt][q] = 0.f;

    for (int t = 0; t < Tt; t++) {
        // G tile (relu GCN), bf16 hi/lo
        {
            int grow = wid * 8 + g;
            float x0 = sxa[(t * 64 + grow) * 2];
            float x1 = sxa[(t * 64 + grow) * 2 + 1];
#pragma unroll
            for (int j = 0; j < 8; j++) {
                int k = t4 * 2 + 8 * j;
                float z0 = fmaf(x0, sWg[2 * k],     fmaf(x1, sWg[2 * k + 1], sbg[k]));
                float z1 = fmaf(x0, sWg[2 * k + 2], fmaf(x1, sWg[2 * k + 3], sbg[k + 1]));
                z0 = fmaxf(z0, 0.f); z1 = fmaxf(z1, 0.f);
                __nv_bfloat16 h0, l0, h1, l1;
                split_bf(z0, h0, l0); split_bf(z1, h1, l1);
                *(uint32_t*)(Gh + grow * WTS + k) = pack2(h0, h1);
                *(uint32_t*)(Gl + grow * WTS + k) = pack2(l0, l1);
            }
        }
        __syncthreads();
        float acc[4][4][4];
#pragma unroll
        for (int mt = 0; mt < 4; mt++)
#pragma unroll
            for (int nt = 0; nt < 4; nt++)
#pragma unroll
                for (int q = 0; q < 4; q++) acc[mt][nt][q] = 0.f;
        mma_pass(acc, Gh, Gl, WIHh, WIHl, g, t4, wid);
        if (t > 0) mma_pass(acc, Hh, Hl, WHHh, WHHl, g, t4, wid);
        // cell update
        float hnew[4][4];
#pragma unroll
        for (int mt = 0; mt < 4; mt++) {
#pragma unroll
            for (int s = 0; s < 2; s++) {
#pragma unroll
                for (int j = 0; j < 2; j++) {
                    int d = 2 * s + j;
                    float ig = acc[mt][0][d] + bias_r[0][j];
                    float fg = acc[mt][1][d] + bias_r[1][j];
                    float gg = acc[mt][2][d] + bias_r[2][j];
                    float og = acc[mt][3][d] + bias_r[3][j];
                    float cn = sigf(fg) * cst[mt][d] + sigf(ig) * tanhfast(gg);
                    cst[mt][d] = cn;
                    hnew[mt][d] = sigf(og) * tanhfast(cn);
                }
            }
        }
        __syncthreads();
        if (t < Tt - 1) {
#pragma unroll
            for (int mt = 0; mt < 4; mt++) {
#pragma unroll
                for (int s = 0; s < 2; s++) {
                    int row = 16 * mt + 8 * s + g;
                    float z0 = hnew[mt][2 * s], z1 = hnew[mt][2 * s + 1];
                    __nv_bfloat16 h0, l0, h1, l1;
                    split_bf(z0, h0, l0); split_bf(z1, h1, l1);
                    *(uint32_t*)(Hh + row * WTS + wid * 8 + 2 * t4) = pack2(h0, h1);
                    *(uint32_t*)(Hl + row * WTS + wid * 8 + 2 * t4) = pack2(l0, l1);
                }
            }
        } else {
#pragma unroll
            for (int mt = 0; mt < 4; mt++) {
#pragma unroll
                for (int s = 0; s < 2; s++) {
                    int row = 16 * mt + 8 * s + g;
                    float c = hnew[mt][2 * s] * wo0 + hnew[mt][2 * s + 1] * wo1;
                    c += __shfl_down_sync(0xffffffffu, c, 2, 4);
                    c += __shfl_down_sync(0xffffffffu, c, 1, 4);
                    if (t4 == 0) outp[wid * 66 + row] = c;
                }
            }
        }
    }
    __syncthreads();
    if (tid < 64) {
        float s = 0.f;
#pragma unroll
        for (int w = 0; w < 8; w++) s += outp[w * 66 + tid];
        out[rowb + tid] = s + bout[0];
    }
}

// ---------------- launch ----------------
extern "C" void kernel_launch(void* const* d_in, const int* in_sizes, int n_in,
                              void* d_out, int out_size) {
    const float* x    = (const float*)d_in[0];
    const float* adj  = (const float*)d_in[1];
    const float* Wg   = (const float*)d_in[2];
    const float* bg   = (const float*)d_in[3];
    const float* Wih  = (const float*)d_in[4];
    const float* Whh  = (const float*)d_in[5];
    const float* bih  = (const float*)d_in[6];
    const float* bhh  = (const float*)d_in[7];
    const float* Wout = (const float*)d_in[8];
    const float* bout = (const float*)d_in[9];
    float* out = (float*)d_out;

    cudaFuncSetAttribute(lstm_mma, cudaFuncAttributeMaxDynamicSharedMemorySize, LSTM_SMEM);

    prep_w<<<64, 256>>>(Wih, Whh);
    pack_x<<<(Jj * 2000 + 255) / 256, 256>>>(x);
    dim3 ga(63, SPLITK);
    gemm_adj_mma<<<ga, 256>>>(adj);
    reduce_xg<<<(NJ / 4 + 255) / 256, 256>>>();
    lstm_mma<<<BNr / 64, 256, LSTM_SMEM>>>(Wg, bg, bih, bhh, Wout, bout, out);
}

// round 8
// speedup vs baseline: 3.7765x; 1.0960x over previous
#include <cuda_runtime.h>
#include <cuda_bf16.h>
#include <stdint.h>

#define Tt 12
#define Nn 4000
#define Jj 192          // B*T*C
#define BNr 32000       // B*N
#define NJ (Nn*Jj)
#define SPLITK 5

// ---------------- scratch ----------------
__device__ uint32_t d_XTh32[Jj * 2000];   // x^T hi: [j][m-pair] packed bf16x2
__device__ uint32_t d_XTl32[Jj * 2000];   // x^T lo
__device__ float d_XGp[SPLITK * NJ];      // split-K partials of adj @ x
__device__ float d_XGs[NJ];               // summed adj @ x
__device__ __align__(16) char d_Wall[147456];  // pre-split/permuted lstm weights

// ---------------- helpers ----------------
__device__ __forceinline__ float sigf(float x) {
    return __fdividef(1.f, 1.f + __expf(-x));
}
__device__ __forceinline__ float tanhfast(float x) {
    return 1.f - 2.f * __fdividef(1.f, __expf(2.f * x) + 1.f);
}
__device__ __forceinline__ void split_bf(float z, __nv_bfloat16& h, __nv_bfloat16& l) {
    h = __float2bfloat16(z);
    l = __float2bfloat16(z - __bfloat162float(h));
}
__device__ __forceinline__ uint32_t pack2(__nv_bfloat16 a, __nv_bfloat16 b) {
    __nv_bfloat162 v; v.x = a; v.y = b;
    return *(uint32_t*)&v;
}
__device__ __forceinline__ void bmma(float& d0, float& d1, float& d2, float& d3,
                                     uint32_t a0, uint32_t a1, uint32_t a2, uint32_t a3,
                                     uint32_t b0, uint32_t b1) {
    asm volatile("mma.sync.aligned.m16n8k16.row.col.f32.bf16.bf16.f32 "
        "{%0,%1,%2,%3}, {%4,%5,%6,%7}, {%8,%9}, {%0,%1,%2,%3};"
        : "+f"(d0), "+f"(d1), "+f"(d2), "+f"(d3)
        : "r"(a0), "r"(a1), "r"(a2), "r"(a3), "r"(b0), "r"(b1));
}

// ---------------- prep: weight split+permute into smem image ----------------
__global__ void prep_w(const float* __restrict__ Wih, const float* __restrict__ Whh) {
    int idx = blockIdx.x * 256 + threadIdx.x;
    if (idx >= 16384) return;
    int o = idx >> 6, k = idx & 63;
    int gate = o >> 6, h = o & 63;
    int n = (h >> 3) * 32 + gate * 8 + (h & 7);
    __nv_bfloat16 hi, lo;
    split_bf(Wih[idx], hi, lo);
    *(__nv_bfloat16*)(d_Wall +          (n * 72 + k) * 2) = hi;
    *(__nv_bfloat16*)(d_Wall + 36864u + (n * 72 + k) * 2) = lo;
    split_bf(Whh[idx], hi, lo);
    *(__nv_bfloat16*)(d_Wall + 73728u + (n * 72 + k) * 2) = hi;
    *(__nv_bfloat16*)(d_Wall + 110592u + (n * 72 + k) * 2) = lo;
}

// ---------------- pack x: transpose + bf16 hi/lo split ----------------
__global__ void pack_x(const float* __restrict__ x) {
    int gid = blockIdx.x * blockDim.x + threadIdx.x;
    if (gid >= Jj * 2000) return;
    int j = gid / 2000, m2 = gid - j * 2000;
    int bt = j >> 1, c = j & 1;
    size_t base = (size_t)bt * Nn * 2 + c;
    float v0 = x[base + (size_t)(2 * m2) * 2];
    float v1 = x[base + (size_t)(2 * m2 + 1) * 2];
    __nv_bfloat16 h0, l0, h1, l1;
    split_bf(v0, h0, l0); split_bf(v1, h1, l1);
    d_XTh32[gid] = pack2(h0, h1);
    d_XTl32[gid] = pack2(l0, l1);
}

// ---------------- adj GEMM via mma.sync: BM=80, 250 blocks (one wave) ----------------
#define BTS 40
__global__ __launch_bounds__(256, 2) void gemm_adj_mma(const float* __restrict__ adj) {
    __shared__ __align__(16) __nv_bfloat16 Ah[80 * BTS], Al[80 * BTS];
    __shared__ __align__(16) __nv_bfloat16 Bh[192 * BTS], Bl[192 * BTS];
    int tid = threadIdx.x, wid = tid >> 5, lane = tid & 31;
    int g = lane >> 2, t4 = lane & 3;
    int rowb = blockIdx.x * 80;
    int kb0 = blockIdx.y * 800;
    float acc[5][3][4];
#pragma unroll
    for (int mt = 0; mt < 5; mt++)
#pragma unroll
        for (int nt = 0; nt < 3; nt++)
#pragma unroll
            for (int q = 0; q < 4; q++) acc[mt][nt][q] = 0.f;

    for (int it = 0; it < 25; it++) {
        int kb = kb0 + it * 32;
#pragma unroll
        for (int q = 0; q < 5; q++) {            // A: 80 rows x 16 float2
            int lin = tid + 256 * q;
            int r = lin >> 4, w = lin & 15;
            float2 v = *(const float2*)&adj[(size_t)(rowb + r) * Nn + kb + 2 * w];
            __nv_bfloat16 h0, l0, h1, l1;
            split_bf(v.x, h0, l0); split_bf(v.y, h1, l1);
            ((uint32_t*)Ah)[r * (BTS/2) + w] = pack2(h0, h1);
            ((uint32_t*)Al)[r * (BTS/2) + w] = pack2(l0, l1);
        }
        int kw = kb >> 1;
#pragma unroll
        for (int q = 0; q < 12; q++) {           // B: 192 rows x 16 words
            int lin = tid + 256 * q;
            int j = lin >> 4, w = lin & 15;
            ((uint32_t*)Bh)[j * (BTS/2) + w] = d_XTh32[j * 2000 + kw + w];
            ((uint32_t*)Bl)[j * (BTS/2) + w] = d_XTl32[j * 2000 + kw + w];
        }
        __syncthreads();
#pragma unroll
        for (int kc = 0; kc < 2; kc++) {
            int kk = kc * 16 + 2 * t4;
            uint32_t ah[5][4];
#pragma unroll
            for (int mt = 0; mt < 5; mt++) {
                const __nv_bfloat16* p0 = Ah + (16 * mt + g) * BTS + kk;
                const __nv_bfloat16* p1 = Ah + (16 * mt + 8 + g) * BTS + kk;
                ah[mt][0] = *(const uint32_t*)p0;
                ah[mt][1] = *(const uint32_t*)p1;
                ah[mt][2] = *(const uint32_t*)(p0 + 8);
                ah[mt][3] = *(const uint32_t*)(p1 + 8);
            }
#pragma unroll
            for (int nt = 0; nt < 3; nt++) {
                int n = wid * 24 + nt * 8 + g;
                const __nv_bfloat16* pb = Bh + n * BTS + kk;
                const __nv_bfloat16* pl = Bl + n * BTS + kk;
                uint32_t bh0 = *(const uint32_t*)pb, bh1 = *(const uint32_t*)(pb + 8);
                uint32_t bl0 = *(const uint32_t*)pl, bl1 = *(const uint32_t*)(pl + 8);
#pragma unroll
                for (int mt = 0; mt < 5; mt++)
                    bmma(acc[mt][nt][0], acc[mt][nt][1], acc[mt][nt][2], acc[mt][nt][3],
                         ah[mt][0], ah[mt][1], ah[mt][2], ah[mt][3], bh0, bh1);
#pragma unroll
                for (int mt = 0; mt < 5; mt++) {
                    const __nv_bfloat16* q0 = Al + (16 * mt + g) * BTS + kk;
                    const __nv_bfloat16* q1 = Al + (16 * mt + 8 + g) * BTS + kk;
                    uint32_t a0 = *(const uint32_t*)q0, a1 = *(const uint32_t*)q1;
                    uint32_t a2 = *(const uint32_t*)(q0 + 8), a3 = *(const uint32_t*)(q1 + 8);
                    bmma(acc[mt][nt][0], acc[mt][nt][1], acc[mt][nt][2], acc[mt][nt][3],
                         a0, a1, a2, a3, bh0, bh1);
                }
#pragma unroll
                for (int mt = 0; mt < 5; mt++)
                    bmma(acc[mt][nt][0], acc[mt][nt][1], acc[mt][nt][2], acc[mt][nt][3],
                         ah[mt][0], ah[mt][1], ah[mt][2], ah[mt][3], bl0, bl1);
            }
        }
        __syncthreads();
    }
    float* outp = d_XGp + (size_t)blockIdx.y * NJ;
#pragma unroll
    for (int mt = 0; mt < 5; mt++) {
#pragma unroll
        for (int nt = 0; nt < 3; nt++) {
            int r0 = rowb + 16 * mt + g;
            int col = wid * 24 + nt * 8 + 2 * t4;
            float2 v0 = {acc[mt][nt][0], acc[mt][nt][1]};
            float2 v1 = {acc[mt][nt][2], acc[mt][nt][3]};
            *(float2*)&outp[r0 * Jj + col] = v0;
            *(float2*)&outp[(r0 + 8) * Jj + col] = v1;
        }
    }
}

__global__ void reduce_xg() {
    int i = blockIdx.x * blockDim.x + threadIdx.x;
    if (i >= NJ / 4) return;
    float4 s = ((const float4*)d_XGp)[i];
#pragma unroll
    for (int sp = 1; sp < SPLITK; sp++) {
        float4 v = ((const float4*)(d_XGp + (size_t)sp * NJ))[i];
        s.x += v.x; s.y += v.y; s.z += v.z; s.w += v.w;
    }
    ((float4*)d_XGs)[i] = s;
}

// ---------------- mma.sync LSTM: 128 rows/block, 16 warps ----------------
#define WTS 72
#define OFF_WIH_H 0u
#define OFF_WIH_L 36864u
#define OFF_WHH_H 73728u
#define OFF_WHH_L 110592u
#define OFF_GH 147456u         // 128*72*2 = 18432 each
#define OFF_GL 165888u
#define OFF_HH 184320u
#define OFF_HL 202752u
#define OFF_BIAS 221184u       // 256 f
#define OFF_WG 222208u         // 128 f
#define OFF_BG 222720u         // 64 f
#define OFF_WO 222976u         // 64 f
#define LSTM_SMEM 223232u

// 3-term split pass: al streamed (register budget). A = m-half base, warp n-slice = wq*32.
__device__ __forceinline__ void mma_pass(float (*acc)[4][4],
        const __nv_bfloat16* Ah, const __nv_bfloat16* Al,
        const __nv_bfloat16* Bh, const __nv_bfloat16* Bl,
        int g, int t4, int wq) {
#pragma unroll
    for (int kc = 0; kc < 4; kc++) {
        int kk = kc * 16 + 2 * t4;
        uint32_t ah[4][4];
#pragma unroll
        for (int mt = 0; mt < 4; mt++) {
            const __nv_bfloat16* p0 = Ah + (16 * mt + g) * WTS + kk;
            const __nv_bfloat16* p1 = Ah + (16 * mt + 8 + g) * WTS + kk;
            ah[mt][0] = *(const uint32_t*)p0;
            ah[mt][1] = *(const uint32_t*)p1;
            ah[mt][2] = *(const uint32_t*)(p0 + 8);
            ah[mt][3] = *(const uint32_t*)(p1 + 8);
        }
#pragma unroll
        for (int nt = 0; nt < 4; nt++) {
            const __nv_bfloat16* pb = Bh + (wq * 32 + nt * 8 + g) * WTS + kk;
            const __nv_bfloat16* pl = Bl + (wq * 32 + nt * 8 + g) * WTS + kk;
            uint32_t bh0 = *(const uint32_t*)pb, bh1 = *(const uint32_t*)(pb + 8);
            uint32_t bl0 = *(const uint32_t*)pl, bl1 = *(const uint32_t*)(pl + 8);
#pragma unroll
            for (int mt = 0; mt < 4; mt++)
                bmma(acc[mt][nt][0], acc[mt][nt][1], acc[mt][nt][2], acc[mt][nt][3],
                     ah[mt][0], ah[mt][1], ah[mt][2], ah[mt][3], bh0, bh1);
#pragma unroll
            for (int mt = 0; mt < 4; mt++) {
                const __nv_bfloat16* q0 = Al + (16 * mt + g) * WTS + kk;
                const __nv_bfloat16* q1 = Al + (16 * mt + 8 + g) * WTS + kk;
                uint32_t a0 = *(const uint32_t*)q0, a1 = *(const uint32_t*)q1;
                uint32_t a2 = *(const uint32_t*)(q0 + 8), a3 = *(const uint32_t*)(q1 + 8);
                bmma(acc[mt][nt][0], acc[mt][nt][1], acc[mt][nt][2], acc[mt][nt][3],
                     a0, a1, a2, a3, bh0, bh1);
            }
#pragma unroll
            for (int mt = 0; mt < 4; mt++)
                bmma(acc[mt][nt][0], acc[mt][nt][1], acc[mt][nt][2], acc[mt][nt][3],
                     ah[mt][0], ah[mt][1], ah[mt][2], ah[mt][3], bl0, bl1);
        }
    }
}

__global__ __launch_bounds__(512, 1) void lstm_mma(
        const float* __restrict__ Wg,  const float* __restrict__ bg,
        const float* __restrict__ bih, const float* __restrict__ bhh,
        const float* __restrict__ Wout, const float* __restrict__ bout,
        float* __restrict__ out) {
    extern __shared__ __align__(16) char smc[];
    __nv_bfloat16* WIHh = (__nv_bfloat16*)(smc + OFF_WIH_H);
    __nv_bfloat16* WIHl = (__nv_bfloat16*)(smc + OFF_WIH_L);
    __nv_bfloat16* WHHh = (__nv_bfloat16*)(smc + OFF_WHH_H);
    __nv_bfloat16* WHHl = (__nv_bfloat16*)(smc + OFF_WHH_L);
    __nv_bfloat16* Gh = (__nv_bfloat16*)(smc + OFF_GH);
    __nv_bfloat16* Gl = (__nv_bfloat16*)(smc + OFF_GL);
    __nv_bfloat16* Hh = (__nv_bfloat16*)(smc + OFF_HH);
    __nv_bfloat16* Hl = (__nv_bfloat16*)(smc + OFF_HL);
    float* sbias = (float*)(smc + OFF_BIAS);
    float* sWg   = (float*)(smc + OFF_WG);
    float* sbg   = (float*)(smc + OFF_BG);
    float* sWo   = (float*)(smc + OFF_WO);
    float* outp  = (float*)(smc + OFF_GH);   // reused after final MMA

    int tid = threadIdx.x, wid = tid >> 5, lane = tid & 31;
    int g = lane >> 2, t4 = lane & 3;
    int wm = wid >> 3, wq = wid & 7;
    int rowb = blockIdx.x * 128;

    {   // linear copy of pre-split weight image: 9216 uint4
        const uint4* src = (const uint4*)d_Wall;
        uint4* dst = (uint4*)smc;
#pragma unroll
        for (int q = 0; q < 18; q++) dst[tid + 512 * q] = src[tid + 512 * q];
    }
    if (tid < 256) {
        int n = tid;
        int gate = (n >> 3) & 3, h = (n >> 5) * 8 + (n & 7);
        int o = gate * 64 + h;
        sbias[n] = bih[o] + bhh[o];
    }
    if (tid < 128) sWg[tid] = Wg[tid];
    if (tid < 64) { sbg[tid] = bg[tid]; sWo[tid] = Wout[tid]; }

    // per-thread x source (row = tid>>2)
    int grow = tid >> 2, t4b = tid & 3;
    int R = rowb + grow;
    int bb = R / Nn, nn = R - bb * Nn;
    const float* xsrc = d_XGs + nn * Jj + bb * (Tt * 2);
    __syncthreads();

    float cst[4][4];
#pragma unroll
    for (int mt = 0; mt < 4; mt++)
#pragma unroll
        for (int q = 0; q < 4; q++) cst[mt][q] = 0.f;

    const __nv_bfloat16* Ahm = Gh + wm * 64 * WTS;
    const __nv_bfloat16* Alm = Gl + wm * 64 * WTS;
    const __nv_bfloat16* Hhm = Hh + wm * 64 * WTS;
    const __nv_bfloat16* Hlm = Hl + wm * 64 * WTS;

    for (int t = 0; t < Tt; t++) {
        // ---- G tile build (relu GCN), 512 threads: row = tid>>2 ----
        {
            float2 xv = *(const float2*)&xsrc[2 * t];
#pragma unroll
            for (int j = 0; j < 8; j++) {
                int k = t4b * 2 + 8 * j;
                float z0 = fmaf(xv.x, sWg[2 * k],     fmaf(xv.y, sWg[2 * k + 1], sbg[k]));
                float z1 = fmaf(xv.x, sWg[2 * k + 2], fmaf(xv.y, sWg[2 * k + 3], sbg[k + 1]));
                z0 = fmaxf(z0, 0.f); z1 = fmaxf(z1, 0.f);
                __nv_bfloat16 h0, l0, h1, l1;
                split_bf(z0, h0, l0); split_bf(z1, h1, l1);
                *(uint32_t*)(Gh + grow * WTS + k) = pack2(h0, h1);
                *(uint32_t*)(Gl + grow * WTS + k) = pack2(l0, l1);
            }
        }
        __syncthreads();
        float acc[4][4][4];
#pragma unroll
        for (int mt = 0; mt < 4; mt++)
#pragma unroll
            for (int nt = 0; nt < 4; nt++)
#pragma unroll
                for (int q = 0; q < 4; q++) acc[mt][nt][q] = 0.f;
        mma_pass(acc, Ahm, Alm, WIHh, WIHl, g, t4, wq);
        if (t > 0) mma_pass(acc, Hhm, Hlm, WHHh, WHHl, g, t4, wq);
        // ---- cell update; biases from smem ----
        float hnew[4][4];
#pragma unroll
        for (int mt = 0; mt < 4; mt++) {
#pragma unroll
            for (int s = 0; s < 2; s++) {
#pragma unroll
                for (int j = 0; j < 2; j++) {
                    int d = 2 * s + j;
                    float ig = acc[mt][0][d] + sbias[wq * 32 +  0 + 2 * t4 + j];
                    float fg = acc[mt][1][d] + sbias[wq * 32 +  8 + 2 * t4 + j];
                    float gg = acc[mt][2][d] + sbias[wq * 32 + 16 + 2 * t4 + j];
                    float og = acc[mt][3][d] + sbias[wq * 32 + 24 + 2 * t4 + j];
                    float cn = sigf(fg) * cst[mt][d] + sigf(ig) * tanhfast(gg);
                    cst[mt][d] = cn;
                    hnew[mt][d] = sigf(og) * tanhfast(cn);
                }
            }
        }
        __syncthreads();
        if (t < Tt - 1) {
            // store new H (bf16 hi/lo): h = wq*8 + 2*t4 (+1)
#pragma unroll
            for (int mt = 0; mt < 4; mt++) {
#pragma unroll
                for (int s = 0; s < 2; s++) {
                    int row = wm * 64 + 16 * mt + 8 * s + g;
                    float z0 = hnew[mt][2 * s], z1 = hnew[mt][2 * s + 1];
                    __nv_bfloat16 h0, l0, h1, l1;
                    split_bf(z0, h0, l0); split_bf(z1, h1, l1);
                    *(uint32_t*)(Hh + row * WTS + wq * 8 + 2 * t4) = pack2(h0, h1);
                    *(uint32_t*)(Hl + row * WTS + wq * 8 + 2 * t4) = pack2(l0, l1);
                }
            }
        } else {
            // output head partials into reused Gh area
            float wo0 = sWo[wq * 8 + 2 * t4], wo1 = sWo[wq * 8 + 2 * t4 + 1];
#pragma unroll
            for (int mt = 0; mt < 4; mt++) {
#pragma unroll
                for (int s = 0; s < 2; s++) {
                    int row64 = 16 * mt + 8 * s + g;
                    float c = hnew[mt][2 * s] * wo0 + hnew[mt][2 * s + 1] * wo1;
                    c += __shfl_down_sync(0xffffffffu, c, 2, 4);
                    c += __shfl_down_sync(0xffffffffu, c, 1, 4);
                    if (t4 == 0) outp[(wm * 8 + wq) * 68 + row64] = c;
                }
            }
        }
    }
    __syncthreads();
    if (tid < 128) {
        int half = tid >> 6, row64 = tid & 63;
        float s = 0.f;
#pragma unroll
        for (int w = 0; w < 8; w++) s += outp[(half * 8 + w) * 68 + row64];
        out[rowb + tid] = s + bout[0];
    }
}

// ---------------- launch ----------------
extern "C" void kernel_launch(void* const* d_in, const int* in_sizes, int n_in,
                              void* d_out, int out_size) {
    const float* x    = (const float*)d_in[0];
    const float* adj  = (const float*)d_in[1];
    const float* Wg   = (const float*)d_in[2];
    const float* bg   = (const float*)d_in[3];
    const float* Wih  = (const float*)d_in[4];
    const float* Whh  = (const float*)d_in[5];
    const float* bih  = (const float*)d_in[6];
    const float* bhh  = (const float*)d_in[7];
    const float* Wout = (const float*)d_in[8];
    const float* bout = (const float*)d_in[9];
    float* out = (float*)d_out;

    cudaFuncSetAttribute(lstm_mma, cudaFuncAttributeMaxDynamicSharedMemorySize, LSTM_SMEM);

    prep_w<<<64, 256>>>(Wih, Whh);
    pack_x<<<(Jj * 2000 + 255) / 256, 256>>>(x);
    dim3 ga(50, SPLITK);
    gemm_adj_mma<<<ga, 256>>>(adj);
    reduce_xg<<<(NJ / 4 + 255) / 256, 256>>>();
    lstm_mma<<<BNr / 128, 512, LSTM_SMEM>>>(Wg, bg, bih, bhh, Wout, bout, out);
}

// round 9
// speedup vs baseline: 3.9747x; 1.0525x over previous
#include <cuda_runtime.h>
#include <cuda_bf16.h>
#include <stdint.h>

#define Tt 12
#define Nn 4000
#define Jj 192          // B*T*C
#define BNr 32000       // B*N
#define NJ (Nn*Jj)
#define SPLITK 5

// ---------------- scratch ----------------
__device__ uint32_t d_XTh32[Jj * 2000];   // x^T hi: [j][m-pair] packed bf16x2
__device__ uint32_t d_XTl32[Jj * 2000];   // x^T lo
__device__ float d_XGp[SPLITK * NJ];      // split-K partials of adj @ x
__device__ float d_XGs[NJ];               // summed adj @ x
__device__ __align__(16) char d_Wall[147456];  // pre-split/permuted lstm weights

// ---------------- helpers ----------------
__device__ __forceinline__ float sigf(float x) {
    return __fdividef(1.f, 1.f + __expf(-x));
}
__device__ __forceinline__ float tanhfast(float x) {
    return 1.f - 2.f * __fdividef(1.f, __expf(2.f * x) + 1.f);
}
__device__ __forceinline__ void split_bf(float z, __nv_bfloat16& h, __nv_bfloat16& l) {
    h = __float2bfloat16(z);
    l = __float2bfloat16(z - __bfloat162float(h));
}
__device__ __forceinline__ uint32_t pack2(__nv_bfloat16 a, __nv_bfloat16 b) {
    __nv_bfloat162 v; v.x = a; v.y = b;
    return *(uint32_t*)&v;
}
__device__ __forceinline__ void bmma(float& d0, float& d1, float& d2, float& d3,
                                     uint32_t a0, uint32_t a1, uint32_t a2, uint32_t a3,
                                     uint32_t b0, uint32_t b1) {
    asm volatile("mma.sync.aligned.m16n8k16.row.col.f32.bf16.bf16.f32 "
        "{%0,%1,%2,%3}, {%4,%5,%6,%7}, {%8,%9}, {%0,%1,%2,%3};"
        : "+f"(d0), "+f"(d1), "+f"(d2), "+f"(d3)
        : "r"(a0), "r"(a1), "r"(a2), "r"(a3), "r"(b0), "r"(b1));
}

// ---------------- prep: weight split+permute into smem image ----------------
__global__ void prep_w(const float* __restrict__ Wih, const float* __restrict__ Whh) {
    int idx = blockIdx.x * 256 + threadIdx.x;
    if (idx >= 16384) return;
    int o = idx >> 6, k = idx & 63;
    int gate = o >> 6, h = o & 63;
    int n = (h >> 3) * 32 + gate * 8 + (h & 7);
    __nv_bfloat16 hi, lo;
    split_bf(Wih[idx], hi, lo);
    *(__nv_bfloat16*)(d_Wall +          (n * 72 + k) * 2) = hi;
    *(__nv_bfloat16*)(d_Wall + 36864u + (n * 72 + k) * 2) = lo;
    split_bf(Whh[idx], hi, lo);
    *(__nv_bfloat16*)(d_Wall + 73728u + (n * 72 + k) * 2) = hi;
    *(__nv_bfloat16*)(d_Wall + 110592u + (n * 72 + k) * 2) = lo;
}

// ---------------- pack x: transpose + bf16 hi/lo split ----------------
__global__ void pack_x(const float* __restrict__ x) {
    int gid = blockIdx.x * blockDim.x + threadIdx.x;
    if (gid >= Jj * 2000) return;
    int j = gid / 2000, m2 = gid - j * 2000;
    int bt = j >> 1, c = j & 1;
    size_t base = (size_t)bt * Nn * 2 + c;
    float v0 = x[base + (size_t)(2 * m2) * 2];
    float v1 = x[base + (size_t)(2 * m2 + 1) * 2];
    __nv_bfloat16 h0, l0, h1, l1;
    split_bf(v0, h0, l0); split_bf(v1, h1, l1);
    d_XTh32[gid] = pack2(h0, h1);
    d_XTl32[gid] = pack2(l0, l1);
}

// ---------------- adj GEMM via mma.sync: BM=80, 250 blocks ----------------
#define BTS 40
__global__ __launch_bounds__(256, 2) void gemm_adj_mma(const float* __restrict__ adj) {
    __shared__ __align__(16) __nv_bfloat16 Ah[80 * BTS], Al[80 * BTS];
    __shared__ __align__(16) __nv_bfloat16 Bh[192 * BTS], Bl[192 * BTS];
    int tid = threadIdx.x, wid = tid >> 5, lane = tid & 31;
    int g = lane >> 2, t4 = lane & 3;
    int rowb = blockIdx.x * 80;
    int kb0 = blockIdx.y * 800;
    float acc[5][3][4];
#pragma unroll
    for (int mt = 0; mt < 5; mt++)
#pragma unroll
        for (int nt = 0; nt < 3; nt++)
#pragma unroll
            for (int q = 0; q < 4; q++) acc[mt][nt][q] = 0.f;

    for (int it = 0; it < 25; it++) {
        int kb = kb0 + it * 32;
#pragma unroll
        for (int q = 0; q < 5; q++) {            // A: 80 rows x 16 float2
            int lin = tid + 256 * q;
            int r = lin >> 4, w = lin & 15;
            float2 v = *(const float2*)&adj[(size_t)(rowb + r) * Nn + kb + 2 * w];
            __nv_bfloat16 h0, l0, h1, l1;
            split_bf(v.x, h0, l0); split_bf(v.y, h1, l1);
            ((uint32_t*)Ah)[r * (BTS/2) + w] = pack2(h0, h1);
            ((uint32_t*)Al)[r * (BTS/2) + w] = pack2(l0, l1);
        }
        int kw = kb >> 1;
#pragma unroll
        for (int q = 0; q < 12; q++) {           // B: 192 rows x 16 words
            int lin = tid + 256 * q;
            int j = lin >> 4, w = lin & 15;
            ((uint32_t*)Bh)[j * (BTS/2) + w] = d_XTh32[j * 2000 + kw + w];
            ((uint32_t*)Bl)[j * (BTS/2) + w] = d_XTl32[j * 2000 + kw + w];
        }
        __syncthreads();
#pragma unroll
        for (int kc = 0; kc < 2; kc++) {
            int kk = kc * 16 + 2 * t4;
            uint32_t ah[5][4], al[5][4];         // both resident: A bytes read once
#pragma unroll
            for (int mt = 0; mt < 5; mt++) {
                const __nv_bfloat16* p0 = Ah + (16 * mt + g) * BTS + kk;
                const __nv_bfloat16* p1 = Ah + (16 * mt + 8 + g) * BTS + kk;
                ah[mt][0] = *(const uint32_t*)p0;
                ah[mt][1] = *(const uint32_t*)p1;
                ah[mt][2] = *(const uint32_t*)(p0 + 8);
                ah[mt][3] = *(const uint32_t*)(p1 + 8);
                const __nv_bfloat16* q0 = Al + (16 * mt + g) * BTS + kk;
                const __nv_bfloat16* q1 = Al + (16 * mt + 8 + g) * BTS + kk;
                al[mt][0] = *(const uint32_t*)q0;
                al[mt][1] = *(const uint32_t*)q1;
                al[mt][2] = *(const uint32_t*)(q0 + 8);
                al[mt][3] = *(const uint32_t*)(q1 + 8);
            }
#pragma unroll
            for (int nt = 0; nt < 3; nt++) {
                int n = wid * 24 + nt * 8 + g;
                const __nv_bfloat16* pb = Bh + n * BTS + kk;
                const __nv_bfloat16* pl = Bl + n * BTS + kk;
                uint32_t bh0 = *(const uint32_t*)pb, bh1 = *(const uint32_t*)(pb + 8);
                uint32_t bl0 = *(const uint32_t*)pl, bl1 = *(const uint32_t*)(pl + 8);
#pragma unroll
                for (int mt = 0; mt < 5; mt++)
                    bmma(acc[mt][nt][0], acc[mt][nt][1], acc[mt][nt][2], acc[mt][nt][3],
                         ah[mt][0], ah[mt][1], ah[mt][2], ah[mt][3], bh0, bh1);
#pragma unroll
                for (int mt = 0; mt < 5; mt++)
                    bmma(acc[mt][nt][0], acc[mt][nt][1], acc[mt][nt][2], acc[mt][nt][3],
                         al[mt][0], al[mt][1], al[mt][2], al[mt][3], bh0, bh1);
#pragma unroll
                for (int mt = 0; mt < 5; mt++)
                    bmma(acc[mt][nt][0], acc[mt][nt][1], acc[mt][nt][2], acc[mt][nt][3],
                         ah[mt][0], ah[mt][1], ah[mt][2], ah[mt][3], bl0, bl1);
            }
        }
        __syncthreads();
    }
    float* outp = d_XGp + (size_t)blockIdx.y * NJ;
#pragma unroll
    for (int mt = 0; mt < 5; mt++) {
#pragma unroll
        for (int nt = 0; nt < 3; nt++) {
            int r0 = rowb + 16 * mt + g;
            int col = wid * 24 + nt * 8 + 2 * t4;
            float2 v0 = {acc[mt][nt][0], acc[mt][nt][1]};
            float2 v1 = {acc[mt][nt][2], acc[mt][nt][3]};
            *(float2*)&outp[r0 * Jj + col] = v0;
            *(float2*)&outp[(r0 + 8) * Jj + col] = v1;
        }
    }
}

__global__ void reduce_xg() {
    int i = blockIdx.x * blockDim.x + threadIdx.x;
    if (i >= NJ / 4) return;
    float4 s = ((const float4*)d_XGp)[i];
#pragma unroll
    for (int sp = 1; sp < SPLITK; sp++) {
        float4 v = ((const float4*)(d_XGp + (size_t)sp * NJ))[i];
        s.x += v.x; s.y += v.y; s.z += v.z; s.w += v.w;
    }
    ((float4*)d_XGs)[i] = s;
}

// ---------------- mma.sync LSTM: 128 rows/block, 16 warps, mt2/nt8 tiling ----------------
#define WTS 72
#define OFF_WIH_H 0u
#define OFF_WIH_L 36864u
#define OFF_WHH_H 73728u
#define OFF_WHH_L 110592u
#define OFF_GH 147456u
#define OFF_GL 165888u
#define OFF_HH 184320u
#define OFF_HL 202752u
#define OFF_BIAS 221184u       // 256 f
#define OFF_WG 222208u         // 128 f
#define OFF_BG 222720u         // 64 f
#define OFF_WO 222976u         // 64 f
#define LSTM_SMEM 223232u

// warp (wm, wq): rows wm*32..+31 (mt=2), cols wq*64..+63 (nt=8).
// A resident per kc (ah+al); B streamed in nt-pairs (HMMA same-acc distance 4).
__device__ __forceinline__ void mma_pass(float (*acc)[8][4],
        const __nv_bfloat16* Ah, const __nv_bfloat16* Al,
        const __nv_bfloat16* Bh, const __nv_bfloat16* Bl,
        int g, int t4, int wq) {
#pragma unroll
    for (int kc = 0; kc < 4; kc++) {
        int kk = kc * 16 + 2 * t4;
        uint32_t ah[2][4], al[2][4];
#pragma unroll
        for (int mt = 0; mt < 2; mt++) {
            const __nv_bfloat16* p0 = Ah + (16 * mt + g) * WTS + kk;
            const __nv_bfloat16* p1 = Ah + (16 * mt + 8 + g) * WTS + kk;
            ah[mt][0] = *(const uint32_t*)p0;
            ah[mt][1] = *(const uint32_t*)p1;
            ah[mt][2] = *(const uint32_t*)(p0 + 8);
            ah[mt][3] = *(const uint32_t*)(p1 + 8);
            const __nv_bfloat16* q0 = Al + (16 * mt + g) * WTS + kk;
            const __nv_bfloat16* q1 = Al + (16 * mt + 8 + g) * WTS + kk;
            al[mt][0] = *(const uint32_t*)q0;
            al[mt][1] = *(const uint32_t*)q1;
            al[mt][2] = *(const uint32_t*)(q0 + 8);
            al[mt][3] = *(const uint32_t*)(q1 + 8);
        }
#pragma unroll
        for (int np = 0; np < 4; np++) {          // nt pairs
            int n0 = wq * 64 + (2 * np) * 8 + g;
            int n1 = n0 + 8;
            const __nv_bfloat16* pb0 = Bh + n0 * WTS + kk;
            const __nv_bfloat16* pl0 = Bl + n0 * WTS + kk;
            const __nv_bfloat16* pb1 = Bh + n1 * WTS + kk;
            const __nv_bfloat16* pl1 = Bl + n1 * WTS + kk;
            uint32_t b0h0 = *(const uint32_t*)pb0, b0h1 = *(const uint32_t*)(pb0 + 8);
            uint32_t b0l0 = *(const uint32_t*)pl0, b0l1 = *(const uint32_t*)(pl0 + 8);
            uint32_t b1h0 = *(const uint32_t*)pb1, b1h1 = *(const uint32_t*)(pb1 + 8);
            uint32_t b1l0 = *(const uint32_t*)pl1, b1l1 = *(const uint32_t*)(pl1 + 8);
            float* a00 = acc[0][2 * np];
            float* a10 = acc[1][2 * np];
            float* a01 = acc[0][2 * np + 1];
            float* a11 = acc[1][2 * np + 1];
            // term 1: Ah@Bh
            bmma(a00[0], a00[1], a00[2], a00[3], ah[0][0], ah[0][1], ah[0][2], ah[0][3], b0h0, b0h1);
            bmma(a10[0], a10[1], a10[2], a10[3], ah[1][0], ah[1][1], ah[1][2], ah[1][3], b0h0, b0h1);
            bmma(a01[0], a01[1], a01[2], a01[3], ah[0][0], ah[0][1], ah[0][2], ah[0][3], b1h0, b1h1);
            bmma(a11[0], a11[1], a11[2], a11[3], ah[1][0], ah[1][1], ah[1][2], ah[1][3], b1h0, b1h1);
            // term 2: Al@Bh
            bmma(a00[0], a00[1], a00[2], a00[3], al[0][0], al[0][1], al[0][2], al[0][3], b0h0, b0h1);
            bmma(a10[0], a10[1], a10[2], a10[3], al[1][0], al[1][1], al[1][2], al[1][3], b0h0, b0h1);
            bmma(a01[0], a01[1], a01[2], a01[3], al[0][0], al[0][1], al[0][2], al[0][3], b1h0, b1h1);
            bmma(a11[0], a11[1], a11[2], a11[3], al[1][0], al[1][1], al[1][2], al[1][3], b1h0, b1h1);
            // term 3: Ah@Bl
            bmma(a00[0], a00[1], a00[2], a00[3], ah[0][0], ah[0][1], ah[0][2], ah[0][3], b0l0, b0l1);
            bmma(a10[0], a10[1], a10[2], a10[3], ah[1][0], ah[1][1], ah[1][2], ah[1][3], b0l0, b0l1);
            bmma(a01[0], a01[1], a01[2], a01[3], ah[0][0], ah[0][1], ah[0][2], ah[0][3], b1l0, b1l1);
            bmma(a11[0], a11[1], a11[2], a11[3], ah[1][0], ah[1][1], ah[1][2], ah[1][3], b1l0, b1l1);
        }
    }
}

__global__ __launch_bounds__(512, 1) void lstm_mma(
        const float* __restrict__ Wg,  const float* __restrict__ bg,
        const float* __restrict__ bih, const float* __restrict__ bhh,
        const float* __restrict__ Wout, const float* __restrict__ bout,
        float* __restrict__ out) {
    extern __shared__ __align__(16) char smc[];
    __nv_bfloat16* WIHh = (__nv_bfloat16*)(smc + OFF_WIH_H);
    __nv_bfloat16* WIHl = (__nv_bfloat16*)(smc + OFF_WIH_L);
    __nv_bfloat16* WHHh = (__nv_bfloat16*)(smc + OFF_WHH_H);
    __nv_bfloat16* WHHl = (__nv_bfloat16*)(smc + OFF_WHH_L);
    __nv_bfloat16* Gh = (__nv_bfloat16*)(smc + OFF_GH);
    __nv_bfloat16* Gl = (__nv_bfloat16*)(smc + OFF_GL);
    __nv_bfloat16* Hh = (__nv_bfloat16*)(smc + OFF_HH);
    __nv_bfloat16* Hl = (__nv_bfloat16*)(smc + OFF_HL);
    float* sbias = (float*)(smc + OFF_BIAS);
    float* sWg   = (float*)(smc + OFF_WG);
    float* sbg   = (float*)(smc + OFF_BG);
    float* sWo   = (float*)(smc + OFF_WO);
    float* outp  = (float*)(smc + OFF_GH);   // reused after final MMA (4*132 floats)

    int tid = threadIdx.x, wid = tid >> 5, lane = tid & 31;
    int g = lane >> 2, t4 = lane & 3;
    int wm = wid >> 2, wq = wid & 3;        // m-quarter (32 rows), n-slice (64 cols)
    int rowb = blockIdx.x * 128;

    {   // linear copy of pre-split weight image: 9216 uint4
        const uint4* src = (const uint4*)d_Wall;
        uint4* dst = (uint4*)smc;
#pragma unroll
        for (int q = 0; q < 18; q++) dst[tid + 512 * q] = src[tid + 512 * q];
    }
    if (tid < 256) {
        int n = tid;
        int gate = (n >> 3) & 3, h = (n >> 5) * 8 + (n & 7);
        int o = gate * 64 + h;
        sbias[n] = bih[o] + bhh[o];
    }
    if (tid < 128) sWg[tid] = Wg[tid];
    if (tid < 64) { sbg[tid] = bg[tid]; sWo[tid] = Wout[tid]; }

    // per-thread x source (row = tid>>2)
    int grow = tid >> 2, t4b = tid & 3;
    int R = rowb + grow;
    int bb = R / Nn, nn = R - bb * Nn;
    const float* xsrc = d_XGs + nn * Jj + bb * (Tt * 2);
    __syncthreads();

    float cst[2][8];                         // [mt][hg*4 + d]
#pragma unroll
    for (int mt = 0; mt < 2; mt++)
#pragma unroll
        for (int q = 0; q < 8; q++) cst[mt][q] = 0.f;

    const __nv_bfloat16* Ahm = Gh + wm * 32 * WTS;
    const __nv_bfloat16* Alm = Gl + wm * 32 * WTS;
    const __nv_bfloat16* Hhm = Hh + wm * 32 * WTS;
    const __nv_bfloat16* Hlm = Hl + wm * 32 * WTS;

    for (int t = 0; t < Tt; t++) {
        // ---- G tile build (relu GCN), row = tid>>2 ----
        {
            float2 xv = *(const float2*)&xsrc[2 * t];
#pragma unroll
            for (int j = 0; j < 8; j++) {
                int k = t4b * 2 + 8 * j;
                float z0 = fmaf(xv.x, sWg[2 * k],     fmaf(xv.y, sWg[2 * k + 1], sbg[k]));
                float z1 = fmaf(xv.x, sWg[2 * k + 2], fmaf(xv.y, sWg[2 * k + 3], sbg[k + 1]));
                z0 = fmaxf(z0, 0.f); z1 = fmaxf(z1, 0.f);
                __nv_bfloat16 h0, l0, h1, l1;
                split_bf(z0, h0, l0); split_bf(z1, h1, l1);
                *(uint32_t*)(Gh + grow * WTS + k) = pack2(h0, h1);
                *(uint32_t*)(Gl + grow * WTS + k) = pack2(l0, l1);
            }
        }
        __syncthreads();
        float acc[2][8][4];
#pragma unroll
        for (int mt = 0; mt < 2; mt++)
#pragma unroll
            for (int nt = 0; nt < 8; nt++)
#pragma unroll
                for (int q = 0; q < 4; q++) acc[mt][nt][q] = 0.f;
        mma_pass(acc, Ahm, Alm, WIHh, WIHl, g, t4, wq);
        if (t > 0) mma_pass(acc, Hhm, Hlm, WHHh, WHHl, g, t4, wq);
        // ---- cell update: nt = hg*4 + gate; hnew written in-place into i-slot ----
#pragma unroll
        for (int mt = 0; mt < 2; mt++) {
#pragma unroll
            for (int hg = 0; hg < 2; hg++) {
#pragma unroll
                for (int d = 0; d < 4; d++) {
                    int j = d & 1;
                    int nb = wq * 64 + hg * 32 + 2 * t4 + j;
                    float ig = acc[mt][hg * 4 + 0][d] + sbias[nb];
                    float fg = acc[mt][hg * 4 + 1][d] + sbias[nb + 8];
                    float gg = acc[mt][hg * 4 + 2][d] + sbias[nb + 16];
                    float og = acc[mt][hg * 4 + 3][d] + sbias[nb + 24];
                    float cn = sigf(fg) * cst[mt][hg * 4 + d] + sigf(ig) * tanhfast(gg);
                    cst[mt][hg * 4 + d] = cn;
                    acc[mt][hg * 4 + 0][d] = sigf(og) * tanhfast(cn);
                }
            }
        }
        __syncthreads();
        if (t < Tt - 1) {
            // store new H (bf16 hi/lo): h = (2wq+hg)*8 + 2t4 (+1)
#pragma unroll
            for (int mt = 0; mt < 2; mt++) {
#pragma unroll
                for (int s = 0; s < 2; s++) {
                    int row = wm * 32 + 16 * mt + 8 * s + g;
#pragma unroll
                    for (int hg = 0; hg < 2; hg++) {
                        int hidx = (2 * wq + hg) * 8 + 2 * t4;
                        float z0 = acc[mt][hg * 4][2 * s];
                        float z1 = acc[mt][hg * 4][2 * s + 1];
                        __nv_bfloat16 h0, l0, h1, l1;
                        split_bf(z0, h0, l0); split_bf(z1, h1, l1);
                        *(uint32_t*)(Hh + row * WTS + hidx) = pack2(h0, h1);
                        *(uint32_t*)(Hl + row * WTS + hidx) = pack2(l0, l1);
                    }
                }
            }
        } else {
            // output head partials: this warp covers h = wq*16 .. +15
#pragma unroll
            for (int mt = 0; mt < 2; mt++) {
#pragma unroll
                for (int s = 0; s < 2; s++) {
                    int row = wm * 32 + 16 * mt + 8 * s + g;
                    float c = 0.f;
#pragma unroll
                    for (int hg = 0; hg < 2; hg++) {
                        int hidx = (2 * wq + hg) * 8 + 2 * t4;
                        c = fmaf(acc[mt][hg * 4][2 * s],     sWo[hidx],
                            fmaf(acc[mt][hg * 4][2 * s + 1], sWo[hidx + 1], c));
                    }
                    c += __shfl_down_sync(0xffffffffu, c, 2, 4);
                    c += __shfl_down_sync(0xffffffffu, c, 1, 4);
                    if (t4 == 0) outp[wq * 132 + row] = c;
                }
            }
        }
    }
    __syncthreads();
    if (tid < 128) {
        float s = outp[tid] + outp[132 + tid] + outp[264 + tid] + outp[396 + tid];
        out[rowb + tid] = s + bout[0];
    }
}

// ---------------- launch ----------------
extern "C" void kernel_launch(void* const* d_in, const int* in_sizes, int n_in,
                              void* d_out, int out_size) {
    const float* x    = (const float*)d_in[0];
    const float* adj  = (const float*)d_in[1];
    const float* Wg   = (const float*)d_in[2];
    const float* bg   = (const float*)d_in[3];
    const float* Wih  = (const float*)d_in[4];
    const float* Whh  = (const float*)d_in[5];
    const float* bih  = (const float*)d_in[6];
    const float* bhh  = (const float*)d_in[7];
    const float* Wout = (const float*)d_in[8];
    const float* bout = (const float*)d_in[9];
    float* out = (float*)d_out;

    cudaFuncSetAttribute(lstm_mma, cudaFuncAttributeMaxDynamicSharedMemorySize, LSTM_SMEM);

    prep_w<<<64, 256>>>(Wih, Whh);
    pack_x<<<(Jj * 2000 + 255) / 256, 256>>>(x);
    dim3 ga(50, SPLITK);
    gemm_adj_mma<<<ga, 256>>>(adj);
    reduce_xg<<<(NJ / 4 + 255) / 256, 256>>>();
    lstm_mma<<<BNr / 128, 512, LSTM_SMEM>>>(Wg, bg, bih, bhh, Wout, bout, out);
}

// round 10
// speedup vs baseline: 5.1264x; 1.2898x over previous
#include <cuda_runtime.h>
#include <cuda_fp16.h>
#include <stdint.h>

#define Tt 12
#define Nn 4000
#define Jj 192          // B*T*C
#define BNr 32000       // B*N
#define NJ (Nn*Jj)
#define SPLITK 5
#define ADJ_SCALE 4096.0f
#define ADJ_INV (1.0f/4096.0f)

// ---------------- scratch ----------------
__device__ uint32_t d_XTh32[Jj * 2000];   // x^T hi: [j][m-pair] packed half2
__device__ float d_XGp[SPLITK * NJ];      // split-K partials of (4096*adj) @ x
__device__ float d_XGs[NJ];               // summed adj @ x (rescaled)
__device__ __align__(16) char d_Wall[73728];   // pre-split/permuted lstm weights (hi only)

// ---------------- helpers ----------------
__device__ __forceinline__ float sigf(float x) {
    return __fdividef(1.f, 1.f + __expf(-x));
}
__device__ __forceinline__ float tanhfast(float x) {
    return 1.f - 2.f * __fdividef(1.f, __expf(2.f * x) + 1.f);
}
__device__ __forceinline__ void split_h(float z, __half& h, __half& l) {
    h = __float2half(z);
    l = __float2half(z - __half2float(h));
}
__device__ __forceinline__ uint32_t pack2h(__half a, __half b) {
    __half2 v; v.x = a; v.y = b;
    return *(uint32_t*)&v;
}
__device__ __forceinline__ void hmma(float& d0, float& d1, float& d2, float& d3,
                                     uint32_t a0, uint32_t a1, uint32_t a2, uint32_t a3,
                                     uint32_t b0, uint32_t b1) {
    asm volatile("mma.sync.aligned.m16n8k16.row.col.f32.f16.f16.f32 "
        "{%0,%1,%2,%3}, {%4,%5,%6,%7}, {%8,%9}, {%0,%1,%2,%3};"
        : "+f"(d0), "+f"(d1), "+f"(d2), "+f"(d3)
        : "r"(a0), "r"(a1), "r"(a2), "r"(a3), "r"(b0), "r"(b1));
}

// ---------------- prep: weight permute into smem image (fp16 hi only) ----------------
__global__ void prep_w(const float* __restrict__ Wih, const float* __restrict__ Whh) {
    int idx = blockIdx.x * 256 + threadIdx.x;
    if (idx >= 16384) return;
    int o = idx >> 6, k = idx & 63;
    int gate = o >> 6, h = o & 63;
    int n = (h >> 3) * 32 + gate * 8 + (h & 7);
    *(__half*)(d_Wall +          (n * 72 + k) * 2) = __float2half(Wih[idx]);
    *(__half*)(d_Wall + 36864u + (n * 72 + k) * 2) = __float2half(Whh[idx]);
}

// ---------------- pack x: transpose + fp16 hi ----------------
__global__ void pack_x(const float* __restrict__ x) {
    int gid = blockIdx.x * blockDim.x + threadIdx.x;
    if (gid >= Jj * 2000) return;
    int j = gid / 2000, m2 = gid - j * 2000;
    int bt = j >> 1, c = j & 1;
    size_t base = (size_t)bt * Nn * 2 + c;
    float v0 = x[base + (size_t)(2 * m2) * 2];
    float v1 = x[base + (size_t)(2 * m2 + 1) * 2];
    d_XTh32[gid] = pack2h(__float2half(v0), __float2half(v1));
}

// ---------------- adj GEMM via fp16 mma, 2-term A-split, BM=80, 250 blocks ----------------
#define BTS 40
__global__ __launch_bounds__(256, 2) void gemm_adj_mma(const float* __restrict__ adj) {
    __shared__ __align__(16) __half Ah[80 * BTS], Al[80 * BTS];
    __shared__ __align__(16) __half Bh[192 * BTS];
    int tid = threadIdx.x, wid = tid >> 5, lane = tid & 31;
    int g = lane >> 2, t4 = lane & 3;
    int rowb = blockIdx.x * 80;
    int kb0 = blockIdx.y * 800;
    float acc[5][3][4];
#pragma unroll
    for (int mt = 0; mt < 5; mt++)
#pragma unroll
        for (int nt = 0; nt < 3; nt++)
#pragma unroll
            for (int q = 0; q < 4; q++) acc[mt][nt][q] = 0.f;

    for (int it = 0; it < 25; it++) {
        int kb = kb0 + it * 32;
#pragma unroll
        for (int q = 0; q < 5; q++) {            // A: 80 rows x 16 float2, scaled x4096, split
            int lin = tid + 256 * q;
            int r = lin >> 4, w = lin & 15;
            float2 v = *(const float2*)&adj[(size_t)(rowb + r) * Nn + kb + 2 * w];
            v.x *= ADJ_SCALE; v.y *= ADJ_SCALE;
            __half h0, l0, h1, l1;
            split_h(v.x, h0, l0); split_h(v.y, h1, l1);
            ((uint32_t*)Ah)[r * (BTS/2) + w] = pack2h(h0, h1);
            ((uint32_t*)Al)[r * (BTS/2) + w] = pack2h(l0, l1);
        }
        int kw = kb >> 1;
#pragma unroll
        for (int q = 0; q < 12; q++) {           // B: 192 rows x 16 words (hi only)
            int lin = tid + 256 * q;
            int j = lin >> 4, w = lin & 15;
            ((uint32_t*)Bh)[j * (BTS/2) + w] = d_XTh32[j * 2000 + kw + w];
        }
        __syncthreads();
#pragma unroll
        for (int kc = 0; kc < 2; kc++) {
            int kk = kc * 16 + 2 * t4;
            uint32_t ah[5][4], al[5][4];
#pragma unroll
            for (int mt = 0; mt < 5; mt++) {
                const __half* p0 = Ah + (16 * mt + g) * BTS + kk;
                const __half* p1 = Ah + (16 * mt + 8 + g) * BTS + kk;
                ah[mt][0] = *(const uint32_t*)p0;
                ah[mt][1] = *(const uint32_t*)p1;
                ah[mt][2] = *(const uint32_t*)(p0 + 8);
                ah[mt][3] = *(const uint32_t*)(p1 + 8);
                const __half* q0 = Al + (16 * mt + g) * BTS + kk;
                const __half* q1 = Al + (16 * mt + 8 + g) * BTS + kk;
                al[mt][0] = *(const uint32_t*)q0;
                al[mt][1] = *(const uint32_t*)q1;
                al[mt][2] = *(const uint32_t*)(q0 + 8);
                al[mt][3] = *(const uint32_t*)(q1 + 8);
            }
#pragma unroll
            for (int nt = 0; nt < 3; nt++) {
                int n = wid * 24 + nt * 8 + g;
                const __half* pb = Bh + n * BTS + kk;
                uint32_t bh0 = *(const uint32_t*)pb, bh1 = *(const uint32_t*)(pb + 8);
#pragma unroll
                for (int mt = 0; mt < 5; mt++)
                    hmma(acc[mt][nt][0], acc[mt][nt][1], acc[mt][nt][2], acc[mt][nt][3],
                         ah[mt][0], ah[mt][1], ah[mt][2], ah[mt][3], bh0, bh1);
#pragma unroll
                for (int mt = 0; mt < 5; mt++)
                    hmma(acc[mt][nt][0], acc[mt][nt][1], acc[mt][nt][2], acc[mt][nt][3],
                         al[mt][0], al[mt][1], al[mt][2], al[mt][3], bh0, bh1);
            }
        }
        __syncthreads();
    }
    float* outp = d_XGp + (size_t)blockIdx.y * NJ;
#pragma unroll
    for (int mt = 0; mt < 5; mt++) {
#pragma unroll
        for (int nt = 0; nt < 3; nt++) {
            int r0 = rowb + 16 * mt + g;
            int col = wid * 24 + nt * 8 + 2 * t4;
            float2 v0 = {acc[mt][nt][0], acc[mt][nt][1]};
            float2 v1 = {acc[mt][nt][2], acc[mt][nt][3]};
            *(float2*)&outp[r0 * Jj + col] = v0;
            *(float2*)&outp[(r0 + 8) * Jj + col] = v1;
        }
    }
}

__global__ void reduce_xg() {
    int i = blockIdx.x * blockDim.x + threadIdx.x;
    if (i >= NJ / 4) return;
    float4 s = ((const float4*)d_XGp)[i];
#pragma unroll
    for (int sp = 1; sp < SPLITK; sp++) {
        float4 v = ((const float4*)(d_XGp + (size_t)sp * NJ))[i];
        s.x += v.x; s.y += v.y; s.z += v.z; s.w += v.w;
    }
    s.x *= ADJ_INV; s.y *= ADJ_INV; s.z *= ADJ_INV; s.w *= ADJ_INV;
    ((float4*)d_XGs)[i] = s;
}

// ---------------- fp16 mma LSTM: 128 rows/block, 16 warps, mt2/nt8, 2-term ----------------
#define WTS 72
#define OFF_WIHH 0u
#define OFF_WHHH 36864u
#define OFF_GH 73728u          // 128*72*2 = 18432 each
#define OFF_GL 92160u
#define OFF_HH 110592u
#define OFF_HL 129024u
#define OFF_BIAS 147456u       // 256 f
#define OFF_WG 148480u         // 128 f
#define OFF_BG 148992u         // 64 f
#define OFF_WO 149248u         // 64 f
#define LSTM_SMEM 149504u

// warp (wm, wq): rows wm*32..+31 (mt=2), cols wq*64..+63 (nt=8).
// 2-term: Ah@Bh + Al@Bh; B hi only. A resident per kc; B streamed in nt-pairs.
__device__ __forceinline__ void mma_pass(float (*acc)[8][4],
        const __half* Ah, const __half* Al, const __half* Bh,
        int g, int t4, int wq) {
#pragma unroll
    for (int kc = 0; kc < 4; kc++) {
        int kk = kc * 16 + 2 * t4;
        uint32_t ah[2][4], al[2][4];
#pragma unroll
        for (int mt = 0; mt < 2; mt++) {
            const __half* p0 = Ah + (16 * mt + g) * WTS + kk;
            const __half* p1 = Ah + (16 * mt + 8 + g) * WTS + kk;
            ah[mt][0] = *(const uint32_t*)p0;
            ah[mt][1] = *(const uint32_t*)p1;
            ah[mt][2] = *(const uint32_t*)(p0 + 8);
            ah[mt][3] = *(const uint32_t*)(p1 + 8);
            const __half* q0 = Al + (16 * mt + g) * WTS + kk;
            const __half* q1 = Al + (16 * mt + 8 + g) * WTS + kk;
            al[mt][0] = *(const uint32_t*)q0;
            al[mt][1] = *(const uint32_t*)q1;
            al[mt][2] = *(const uint32_t*)(q0 + 8);
            al[mt][3] = *(const uint32_t*)(q1 + 8);
        }
#pragma unroll
        for (int np = 0; np < 4; np++) {          // nt pairs
            int n0 = wq * 64 + (2 * np) * 8 + g;
            int n1 = n0 + 8;
            const __half* pb0 = Bh + n0 * WTS + kk;
            const __half* pb1 = Bh + n1 * WTS + kk;
            uint32_t b0h0 = *(const uint32_t*)pb0, b0h1 = *(const uint32_t*)(pb0 + 8);
            uint32_t b1h0 = *(const uint32_t*)pb1, b1h1 = *(const uint32_t*)(pb1 + 8);
            float* a00 = acc[0][2 * np];
            float* a10 = acc[1][2 * np];
            float* a01 = acc[0][2 * np + 1];
            float* a11 = acc[1][2 * np + 1];
            // term 1: Ah@Bh
            hmma(a00[0], a00[1], a00[2], a00[3], ah[0][0], ah[0][1], ah[0][2], ah[0][3], b0h0, b0h1);
            hmma(a10[0], a10[1], a10[2], a10[3], ah[1][0], ah[1][1], ah[1][2], ah[1][3], b0h0, b0h1);
            hmma(a01[0], a01[1], a01[2], a01[3], ah[0][0], ah[0][1], ah[0][2], ah[0][3], b1h0, b1h1);
            hmma(a11[0], a11[1], a11[2], a11[3], ah[1][0], ah[1][1], ah[1][2], ah[1][3], b1h0, b1h1);
            // term 2: Al@Bh
            hmma(a00[0], a00[1], a00[2], a00[3], al[0][0], al[0][1], al[0][2], al[0][3], b0h0, b0h1);
            hmma(a10[0], a10[1], a10[2], a10[3], al[1][0], al[1][1], al[1][2], al[1][3], b0h0, b0h1);
            hmma(a01[0], a01[1], a01[2], a01[3], al[0][0], al[0][1], al[0][2], al[0][3], b1h0, b1h1);
            hmma(a11[0], a11[1], a11[2], a11[3], al[1][0], al[1][1], al[1][2], al[1][3], b1h0, b1h1);
        }
    }
}

__global__ __launch_bounds__(512, 1) void lstm_mma(
        const float* __restrict__ Wg,  const float* __restrict__ bg,
        const float* __restrict__ bih, const float* __restrict__ bhh,
        const float* __restrict__ Wout, const float* __restrict__ bout,
        float* __restrict__ out) {
    extern __shared__ __align__(16) char smc[];
    __half* WIHh = (__half*)(smc + OFF_WIHH);
    __half* WHHh = (__half*)(smc + OFF_WHHH);
    __half* Gh = (__half*)(smc + OFF_GH);
    __half* Gl = (__half*)(smc + OFF_GL);
    __half* Hh = (__half*)(smc + OFF_HH);
    __half* Hl = (__half*)(smc + OFF_HL);
    float* sbias = (float*)(smc + OFF_BIAS);
    float* sWg   = (float*)(smc + OFF_WG);
    float* sbg   = (float*)(smc + OFF_BG);
    float* sWo   = (float*)(smc + OFF_WO);
    float* outp  = (float*)(smc + OFF_GH);   // reused after final MMA (4*132 floats)

    int tid = threadIdx.x, wid = tid >> 5, lane = tid & 31;
    int g = lane >> 2, t4 = lane & 3;
    int wm = wid >> 2, wq = wid & 3;        // m-quarter (32 rows), n-slice (64 cols)
    int rowb = blockIdx.x * 128;

    {   // linear copy of pre-split weight image: 4608 uint4
        const uint4* src = (const uint4*)d_Wall;
        uint4* dst = (uint4*)smc;
#pragma unroll
        for (int q = 0; q < 9; q++) dst[tid + 512 * q] = src[tid + 512 * q];
    }
    if (tid < 256) {
        int n = tid;
        int gate = (n >> 3) & 3, h = (n >> 5) * 8 + (n & 7);
        int o = gate * 64 + h;
        sbias[n] = bih[o] + bhh[o];
    }
    if (tid < 128) sWg[tid] = Wg[tid];
    if (tid < 64) { sbg[tid] = bg[tid]; sWo[tid] = Wout[tid]; }

    // per-thread x source (row = tid>>2)
    int grow = tid >> 2, t4b = tid & 3;
    int R = rowb + grow;
    int bb = R / Nn, nn = R - bb * Nn;
    const float* xsrc = d_XGs + nn * Jj + bb * (Tt * 2);
    __syncthreads();

    float cst[2][8];                         // [mt][hg*4 + d]
#pragma unroll
    for (int mt = 0; mt < 2; mt++)
#pragma unroll
        for (int q = 0; q < 8; q++) cst[mt][q] = 0.f;

    const __half* Ahm = Gh + wm * 32 * WTS;
    const __half* Alm = Gl + wm * 32 * WTS;
    const __half* Hhm = Hh + wm * 32 * WTS;
    const __half* Hlm = Hl + wm * 32 * WTS;

    for (int t = 0; t < Tt; t++) {
        // ---- G tile build (relu GCN), row = tid>>2 ----
        {
            float2 xv = *(const float2*)&xsrc[2 * t];
#pragma unroll
            for (int j = 0; j < 8; j++) {
                int k = t4b * 2 + 8 * j;
                float z0 = fmaf(xv.x, sWg[2 * k],     fmaf(xv.y, sWg[2 * k + 1], sbg[k]));
                float z1 = fmaf(xv.x, sWg[2 * k + 2], fmaf(xv.y, sWg[2 * k + 3], sbg[k + 1]));
                z0 = fmaxf(z0, 0.f); z1 = fmaxf(z1, 0.f);
                __half h0, l0, h1, l1;
                split_h(z0, h0, l0); split_h(z1, h1, l1);
                *(uint32_t*)(Gh + grow * WTS + k) = pack2h(h0, h1);
                *(uint32_t*)(Gl + grow * WTS + k) = pack2h(l0, l1);
            }
        }
        __syncthreads();
        float acc[2][8][4];
#pragma unroll
        for (int mt = 0; mt < 2; mt++)
#pragma unroll
            for (int nt = 0; nt < 8; nt++)
#pragma unroll
                for (int q = 0; q < 4; q++) acc[mt][nt][q] = 0.f;
        mma_pass(acc, Ahm, Alm, WIHh, g, t4, wq);
        if (t > 0) mma_pass(acc, Hhm, Hlm, WHHh, g, t4, wq);
        // ---- cell update: nt = hg*4 + gate; hnew in-place into i-slot ----
#pragma unroll
        for (int mt = 0; mt < 2; mt++) {
#pragma unroll
            for (int hg = 0; hg < 2; hg++) {
#pragma unroll
                for (int d = 0; d < 4; d++) {
                    int j = d & 1;
                    int nb = wq * 64 + hg * 32 + 2 * t4 + j;
                    float ig = acc[mt][hg * 4 + 0][d] + sbias[nb];
                    float fg = acc[mt][hg * 4 + 1][d] + sbias[nb + 8];
                    float gg = acc[mt][hg * 4 + 2][d] + sbias[nb + 16];
                    float og = acc[mt][hg * 4 + 3][d] + sbias[nb + 24];
                    float cn = sigf(fg) * cst[mt][hg * 4 + d] + sigf(ig) * tanhfast(gg);
                    cst[mt][hg * 4 + d] = cn;
                    acc[mt][hg * 4 + 0][d] = sigf(og) * tanhfast(cn);
                }
            }
        }
        __syncthreads();
        if (t < Tt - 1) {
            // store new H (fp16 hi/lo): h = (2wq+hg)*8 + 2t4 (+1)
#pragma unroll
            for (int mt = 0; mt < 2; mt++) {
#pragma unroll
                for (int s = 0; s < 2; s++) {
                    int row = wm * 32 + 16 * mt + 8 * s + g;
#pragma unroll
                    for (int hg = 0; hg < 2; hg++) {
                        int hidx = (2 * wq + hg) * 8 + 2 * t4;
                        float z0 = acc[mt][hg * 4][2 * s];
                        float z1 = acc[mt][hg * 4][2 * s + 1];
                        __half h0, l0, h1, l1;
                        split_h(z0, h0, l0); split_h(z1, h1, l1);
                        *(uint32_t*)(Hh + row * WTS + hidx) = pack2h(h0, h1);
                        *(uint32_t*)(Hl + row * WTS + hidx) = pack2h(l0, l1);
                    }
                }
            }
        } else {
            // output head partials: this warp covers h = wq*16 .. +15
#pragma unroll
            for (int mt = 0; mt < 2; mt++) {
#pragma unroll
                for (int s = 0; s < 2; s++) {
                    int row = wm * 32 + 16 * mt + 8 * s + g;
                    float c = 0.f;
#pragma unroll
                    for (int hg = 0; hg < 2; hg++) {
                        int hidx = (2 * wq + hg) * 8 + 2 * t4;
                        c = fmaf(acc[mt][hg * 4][2 * s],     sWo[hidx],
                            fmaf(acc[mt][hg * 4][2 * s + 1], sWo[hidx + 1], c));
                    }
                    c += __shfl_down_sync(0xffffffffu, c, 2, 4);
                    c += __shfl_down_sync(0xffffffffu, c, 1, 4);
                    if (t4 == 0) outp[wq * 132 + row] = c;
                }
            }
        }
    }
    __syncthreads();
    if (tid < 128) {
        float s = outp[tid] + outp[132 + tid] + outp[264 + tid] + outp[396 + tid];
        out[rowb + tid] = s + bout[0];
    }
}

// ---------------- launch ----------------
extern "C" void kernel_launch(void* const* d_in, const int* in_sizes, int n_in,
                              void* d_out, int out_size) {
    const float* x    = (const float*)d_in[0];
    const float* adj  = (const float*)d_in[1];
    const float* Wg   = (const float*)d_in[2];
    const float* bg   = (const float*)d_in[3];
    const float* Wih  = (const float*)d_in[4];
    const float* Whh  = (const float*)d_in[5];
    const float* bih  = (const float*)d_in[6];
    const float* bhh  = (const float*)d_in[7];
    const float* Wout = (const float*)d_in[8];
    const float* bout = (const float*)d_in[9];
    float* out = (float*)d_out;

    cudaFuncSetAttribute(lstm_mma, cudaFuncAttributeMaxDynamicSharedMemorySize, LSTM_SMEM);

    prep_w<<<64, 256>>>(Wih, Whh);
    pack_x<<<(Jj * 2000 + 255) / 256, 256>>>(x);
    dim3 ga(50, SPLITK);
    gemm_adj_mma<<<ga, 256>>>(adj);
    reduce_xg<<<(NJ / 4 + 255) / 256, 256>>>();
    lstm_mma<<<BNr / 128, 512, LSTM_SMEM>>>(Wg, bg, bih, bhh, Wout, bout, out);
}

// round 11
// speedup vs baseline: 5.6721x; 1.1064x over previous
#include <cuda_runtime.h>
#include <cuda_fp16.h>
#include <stdint.h>

#define Tt 12
#define Nn 4000
#define Jj 192          // B*T*C
#define BNr 32000       // B*N
#define NJ (Nn*Jj)
#define SPLITK 5
#define ADJ_SCALE 4096.0f
#define ADJ_INV (1.0f/4096.0f)

// ---------------- scratch ----------------
__device__ uint32_t d_XTh32[Jj * 2000];   // x^T hi: [j][m-pair] packed half2
__device__ float d_XGp[SPLITK * NJ];      // split-K partials of (4096*adj) @ x
__device__ __align__(16) char d_Wall[73728];   // pre-permuted lstm weights (fp16 hi)

// ---------------- helpers ----------------
__device__ __forceinline__ float tanha(float x) {
    float y;
    asm("tanh.approx.f32 %0, %1;" : "=f"(y) : "f"(x));
    return y;
}
__device__ __forceinline__ float siga(float x) {          // sigmoid via MUFU.TANH
    return fmaf(0.5f, tanha(0.5f * x), 0.5f);
}
__device__ __forceinline__ void split_h(float z, __half& h, __half& l) {
    h = __float2half(z);
    l = __float2half(z - __half2float(h));
}
__device__ __forceinline__ uint32_t pack2h(__half a, __half b) {
    __half2 v; v.x = a; v.y = b;
    return *(uint32_t*)&v;
}
__device__ __forceinline__ void hmma(float& d0, float& d1, float& d2, float& d3,
                                     uint32_t a0, uint32_t a1, uint32_t a2, uint32_t a3,
                                     uint32_t b0, uint32_t b1) {
    asm volatile("mma.sync.aligned.m16n8k16.row.col.f32.f16.f16.f32 "
        "{%0,%1,%2,%3}, {%4,%5,%6,%7}, {%8,%9}, {%0,%1,%2,%3};"
        : "+f"(d0), "+f"(d1), "+f"(d2), "+f"(d3)
        : "r"(a0), "r"(a1), "r"(a2), "r"(a3), "r"(b0), "r"(b1));
}

// ---------------- prep: weight permute (fp16) + x transpose/pack, one launch ----------------
__global__ void prep_all(const float* __restrict__ x,
                         const float* __restrict__ Wih, const float* __restrict__ Whh) {
    int gid = blockIdx.x * 256 + threadIdx.x;
    if (gid < 16384) {
        int o = gid >> 6, k = gid & 63;
        int gate = o >> 6, h = o & 63;
        int n = (h >> 3) * 32 + gate * 8 + (h & 7);
        *(__half*)(d_Wall +          (n * 72 + k) * 2) = __float2half(Wih[gid]);
        *(__half*)(d_Wall + 36864u + (n * 72 + k) * 2) = __float2half(Whh[gid]);
    }
    if (gid < Jj * 2000) {
        int j = gid / 2000, m2 = gid - j * 2000;
        int bt = j >> 1, c = j & 1;
        size_t base = (size_t)bt * Nn * 2 + c;
        float v0 = x[base + (size_t)(2 * m2) * 2];
        float v1 = x[base + (size_t)(2 * m2 + 1) * 2];
        d_XTh32[gid] = pack2h(__float2half(v0), __float2half(v1));
    }
}

// ---------------- adj GEMM via fp16 mma, 2-term A-split, BM=80, 250 blocks ----------------
#define BTS 40
__global__ __launch_bounds__(256, 2) void gemm_adj_mma(const float* __restrict__ adj) {
    __shared__ __align__(16) __half Ah[80 * BTS], Al[80 * BTS];
    __shared__ __align__(16) __half Bh[192 * BTS];
    int tid = threadIdx.x, wid = tid >> 5, lane = tid & 31;
    int g = lane >> 2, t4 = lane & 3;
    int rowb = blockIdx.x * 80;
    int kb0 = blockIdx.y * 800;
    float acc[5][3][4];
#pragma unroll
    for (int mt = 0; mt < 5; mt++)
#pragma unroll
        for (int nt = 0; nt < 3; nt++)
#pragma unroll
            for (int q = 0; q < 4; q++) acc[mt][nt][q] = 0.f;

    for (int it = 0; it < 25; it++) {
        int kb = kb0 + it * 32;
#pragma unroll
        for (int q = 0; q < 5; q++) {            // A: 80 rows x 16 float2, scaled x4096, split
            int lin = tid + 256 * q;
            int r = lin >> 4, w = lin & 15;
            float2 v = *(const float2*)&adj[(size_t)(rowb + r) * Nn + kb + 2 * w];
            v.x *= ADJ_SCALE; v.y *= ADJ_SCALE;
            __half h0, l0, h1, l1;
            split_h(v.x, h0, l0); split_h(v.y, h1, l1);
            ((uint32_t*)Ah)[r * (BTS/2) + w] = pack2h(h0, h1);
            ((uint32_t*)Al)[r * (BTS/2) + w] = pack2h(l0, l1);
        }
        int kw = kb >> 1;
#pragma unroll
        for (int q = 0; q < 12; q++) {           // B: 192 rows x 16 words (hi only)
            int lin = tid + 256 * q;
            int j = lin >> 4, w = lin & 15;
            ((uint32_t*)Bh)[j * (BTS/2) + w] = d_XTh32[j * 2000 + kw + w];
        }
        __syncthreads();
#pragma unroll
        for (int kc = 0; kc < 2; kc++) {
            int kk = kc * 16 + 2 * t4;
            uint32_t ah[5][4], al[5][4];
#pragma unroll
            for (int mt = 0; mt < 5; mt++) {
                const __half* p0 = Ah + (16 * mt + g) * BTS + kk;
                const __half* p1 = Ah + (16 * mt + 8 + g) * BTS + kk;
                ah[mt][0] = *(const uint32_t*)p0;
                ah[mt][1] = *(const uint32_t*)p1;
                ah[mt][2] = *(const uint32_t*)(p0 + 8);
                ah[mt][3] = *(const uint32_t*)(p1 + 8);
                const __half* q0 = Al + (16 * mt + g) * BTS + kk;
                const __half* q1 = Al + (16 * mt + 8 + g) * BTS + kk;
                al[mt][0] = *(const uint32_t*)q0;
                al[mt][1] = *(const uint32_t*)q1;
                al[mt][2] = *(const uint32_t*)(q0 + 8);
                al[mt][3] = *(const uint32_t*)(q1 + 8);
            }
#pragma unroll
            for (int nt = 0; nt < 3; nt++) {
                int n = wid * 24 + nt * 8 + g;
                const __half* pb = Bh + n * BTS + kk;
                uint32_t bh0 = *(const uint32_t*)pb, bh1 = *(const uint32_t*)(pb + 8);
#pragma unroll
                for (int mt = 0; mt < 5; mt++)
                    hmma(acc[mt][nt][0], acc[mt][nt][1], acc[mt][nt][2], acc[mt][nt][3],
                         ah[mt][0], ah[mt][1], ah[mt][2], ah[mt][3], bh0, bh1);
#pragma unroll
                for (int mt = 0; mt < 5; mt++)
                    hmma(acc[mt][nt][0], acc[mt][nt][1], acc[mt][nt][2], acc[mt][nt][3],
                         al[mt][0], al[mt][1], al[mt][2], al[mt][3], bh0, bh1);
            }
        }
        __syncthreads();
    }
    float* outp = d_XGp + (size_t)blockIdx.y * NJ;
#pragma unroll
    for (int mt = 0; mt < 5; mt++) {
#pragma unroll
        for (int nt = 0; nt < 3; nt++) {
            int r0 = rowb + 16 * mt + g;
            int col = wid * 24 + nt * 8 + 2 * t4;
            float2 v0 = {acc[mt][nt][0], acc[mt][nt][1]};
            float2 v1 = {acc[mt][nt][2], acc[mt][nt][3]};
            *(float2*)&outp[r0 * Jj + col] = v0;
            *(float2*)&outp[(r0 + 8) * Jj + col] = v1;
        }
    }
}

// ---------------- fp16 mma LSTM: 128 rows/block, 16 warps, mt2/nt8, 2-term ----------------
#define WTS 72
#define OFF_WIHH 0u
#define OFF_WHHH 36864u
#define OFF_GH 73728u          // 128*72*2 = 18432 each
#define OFF_GL 92160u
#define OFF_HH 110592u
#define OFF_HL 129024u
#define OFF_BIAS 147456u       // 256 f
#define OFF_WG 148480u         // 128 f
#define OFF_BG 148992u         // 64 f
#define OFF_WO 149248u         // 64 f
#define OFF_SXA 149504u        // 128*24 f = 12288 B (fused split-K reduce)
#define LSTM_SMEM 161792u

// warp (wm, wq): rows wm*32..+31 (mt=2), cols wq*64..+63 (nt=8). 2-term: Ah@Bh + Al@Bh.
__device__ __forceinline__ void mma_pass(float (*acc)[8][4],
        const __half* Ah, const __half* Al, const __half* Bh,
        int g, int t4, int wq) {
#pragma unroll
    for (int kc = 0; kc < 4; kc++) {
        int kk = kc * 16 + 2 * t4;
        uint32_t ah[2][4], al[2][4];
#pragma unroll
        for (int mt = 0; mt < 2; mt++) {
            const __half* p0 = Ah + (16 * mt + g) * WTS + kk;
            const __half* p1 = Ah + (16 * mt + 8 + g) * WTS + kk;
            ah[mt][0] = *(const uint32_t*)p0;
            ah[mt][1] = *(const uint32_t*)p1;
            ah[mt][2] = *(const uint32_t*)(p0 + 8);
            ah[mt][3] = *(const uint32_t*)(p1 + 8);
            const __half* q0 = Al + (16 * mt + g) * WTS + kk;
            const __half* q1 = Al + (16 * mt + 8 + g) * WTS + kk;
            al[mt][0] = *(const uint32_t*)q0;
            al[mt][1] = *(const uint32_t*)q1;
            al[mt][2] = *(const uint32_t*)(q0 + 8);
            al[mt][3] = *(const uint32_t*)(q1 + 8);
        }
#pragma unroll
        for (int np = 0; np < 4; np++) {          // nt pairs
            int n0 = wq * 64 + (2 * np) * 8 + g;
            int n1 = n0 + 8;
            const __half* pb0 = Bh + n0 * WTS + kk;
            const __half* pb1 = Bh + n1 * WTS + kk;
            uint32_t b0h0 = *(const uint32_t*)pb0, b0h1 = *(const uint32_t*)(pb0 + 8);
            uint32_t b1h0 = *(const uint32_t*)pb1, b1h1 = *(const uint32_t*)(pb1 + 8);
            float* a00 = acc[0][2 * np];
            float* a10 = acc[1][2 * np];
            float* a01 = acc[0][2 * np + 1];
            float* a11 = acc[1][2 * np + 1];
            hmma(a00[0], a00[1], a00[2], a00[3], ah[0][0], ah[0][1], ah[0][2], ah[0][3], b0h0, b0h1);
            hmma(a10[0], a10[1], a10[2], a10[3], ah[1][0], ah[1][1], ah[1][2], ah[1][3], b0h0, b0h1);
            hmma(a01[0], a01[1], a01[2], a01[3], ah[0][0], ah[0][1], ah[0][2], ah[0][3], b1h0, b1h1);
            hmma(a11[0], a11[1], a11[2], a11[3], ah[1][0], ah[1][1], ah[1][2], ah[1][3], b1h0, b1h1);
            hmma(a00[0], a00[1], a00[2], a00[3], al[0][0], al[0][1], al[0][2], al[0][3], b0h0, b0h1);
            hmma(a10[0], a10[1], a10[2], a10[3], al[1][0], al[1][1], al[1][2], al[1][3], b0h0, b0h1);
            hmma(a01[0], a01[1], a01[2], a01[3], al[0][0], al[0][1], al[0][2], al[0][3], b1h0, b1h1);
            hmma(a11[0], a11[1], a11[2], a11[3], al[1][0], al[1][1], al[1][2], al[1][3], b1h0, b1h1);
        }
    }
}

__global__ __launch_bounds__(512, 1) void lstm_mma(
        const float* __restrict__ Wg,  const float* __restrict__ bg,
        const float* __restrict__ bih, const float* __restrict__ bhh,
        const float* __restrict__ Wout, const float* __restrict__ bout,
        float* __restrict__ out) {
    extern __shared__ __align__(16) char smc[];
    __half* WIHh = (__half*)(smc + OFF_WIHH);
    __half* WHHh = (__half*)(smc + OFF_WHHH);
    __half* Gh = (__half*)(smc + OFF_GH);
    __half* Gl = (__half*)(smc + OFF_GL);
    __half* Hh = (__half*)(smc + OFF_HH);
    __half* Hl = (__half*)(smc + OFF_HL);
    float* sbias = (float*)(smc + OFF_BIAS);
    float* sWg   = (float*)(smc + OFF_WG);
    float* sbg   = (float*)(smc + OFF_BG);
    float* sWo   = (float*)(smc + OFF_WO);
    float* sxa   = (float*)(smc + OFF_SXA);
    float* outp  = (float*)(smc + OFF_GH);   // reused after final MMA (4*132 floats)

    int tid = threadIdx.x, wid = tid >> 5, lane = tid & 31;
    int g = lane >> 2, t4 = lane & 3;
    int wm = wid >> 2, wq = wid & 3;        // m-quarter (32 rows), n-slice (64 cols)
    int rowb = blockIdx.x * 128;

    {   // linear copy of pre-permuted weight image: 4608 uint4
        const uint4* src = (const uint4*)d_Wall;
        uint4* dst = (uint4*)smc;
#pragma unroll
        for (int q = 0; q < 9; q++) dst[tid + 512 * q] = src[tid + 512 * q];
    }
    if (tid < 256) {
        int n = tid;
        int gate = (n >> 3) & 3, h = (n >> 5) * 8 + (n & 7);
        int o = gate * 64 + h;
        sbias[n] = bih[o] + bhh[o];
    }
    if (tid < 128) sWg[tid] = Wg[tid];
    if (tid < 64) { sbg[tid] = bg[tid]; sWo[tid] = Wout[tid]; }
    // fused split-K reduce: sum 5 partials for this block's 128 rows x 24 cols
    for (int v = tid; v < 128 * 24; v += 512) {
        int row = v / 24, j = v - row * 24;
        int R = rowb + row;
        int b = R / Nn, n = R - b * Nn;
        size_t idx = (size_t)n * Jj + b * 24 + j;
        float s = 0.f;
#pragma unroll
        for (int sp = 0; sp < SPLITK; sp++) s += d_XGp[(size_t)sp * NJ + idx];
        sxa[v] = s * ADJ_INV;
    }
    __syncthreads();

    int grow = tid >> 2, t4b = tid & 3;      // G-build row ownership
    float cst[2][8];                         // [mt][hg*4 + d]
#pragma unroll
    for (int mt = 0; mt < 2; mt++)
#pragma unroll
        for (int q = 0; q < 8; q++) cst[mt][q] = 0.f;

    const __half* Ahm = Gh + wm * 32 * WTS;
    const __half* Alm = Gl + wm * 32 * WTS;
    const __half* Hhm = Hh + wm * 32 * WTS;
    const __half* Hlm = Hl + wm * 32 * WTS;

    for (int t = 0; t < Tt; t++) {
        // ---- G tile build (relu GCN), row = tid>>2 ----
        {
            float xv0 = sxa[grow * 24 + 2 * t];
            float xv1 = sxa[grow * 24 + 2 * t + 1];
#pragma unroll
            for (int j = 0; j < 8; j++) {
                int k = t4b * 2 + 8 * j;
                float z0 = fmaf(xv0, sWg[2 * k],     fmaf(xv1, sWg[2 * k + 1], sbg[k]));
                float z1 = fmaf(xv0, sWg[2 * k + 2], fmaf(xv1, sWg[2 * k + 3], sbg[k + 1]));
                z0 = fmaxf(z0, 0.f); z1 = fmaxf(z1, 0.f);
                __half h0, l0, h1, l1;
                split_h(z0, h0, l0); split_h(z1, h1, l1);
                *(uint32_t*)(Gh + grow * WTS + k) = pack2h(h0, h1);
                *(uint32_t*)(Gl + grow * WTS + k) = pack2h(l0, l1);
            }
        }
        __syncthreads();
        float acc[2][8][4];
#pragma unroll
        for (int mt = 0; mt < 2; mt++)
#pragma unroll
            for (int nt = 0; nt < 8; nt++)
#pragma unroll
                for (int q = 0; q < 4; q++) acc[mt][nt][q] = 0.f;
        mma_pass(acc, Ahm, Alm, WIHh, g, t4, wq);
        if (t > 0) mma_pass(acc, Hhm, Hlm, WHHh, g, t4, wq);
        // ---- cell update (MUFU.TANH x5 per cell) ----
#pragma unroll
        for (int mt = 0; mt < 2; mt++) {
#pragma unroll
            for (int hg = 0; hg < 2; hg++) {
#pragma unroll
                for (int d = 0; d < 4; d++) {
                    int j = d & 1;
                    int nb = wq * 64 + hg * 32 + 2 * t4 + j;
                    float ig = acc[mt][hg * 4 + 0][d] + sbias[nb];
                    float fg = acc[mt][hg * 4 + 1][d] + sbias[nb + 8];
                    float gg = acc[mt][hg * 4 + 2][d] + sbias[nb + 16];
                    float og = acc[mt][hg * 4 + 3][d] + sbias[nb + 24];
                    float cn = siga(fg) * cst[mt][hg * 4 + d] + siga(ig) * tanha(gg);
                    cst[mt][hg * 4 + d] = cn;
                    acc[mt][hg * 4 + 0][d] = siga(og) * tanha(cn);
                }
            }
        }
        __syncthreads();
        if (t < Tt - 1) {
            // store new H (fp16 hi/lo): h = (2wq+hg)*8 + 2t4 (+1)
#pragma unroll
            for (int mt = 0; mt < 2; mt++) {
#pragma unroll
                for (int s = 0; s < 2; s++) {
                    int row = wm * 32 + 16 * mt + 8 * s + g;
#pragma unroll
                    for (int hg = 0; hg < 2; hg++) {
                        int hidx = (2 * wq + hg) * 8 + 2 * t4;
                        float z0 = acc[mt][hg * 4][2 * s];
                        float z1 = acc[mt][hg * 4][2 * s + 1];
                        __half h0, l0, h1, l1;
                        split_h(z0, h0, l0); split_h(z1, h1, l1);
                        *(uint32_t*)(Hh + row * WTS + hidx) = pack2h(h0, h1);
                        *(uint32_t*)(Hl + row * WTS + hidx) = pack2h(l0, l1);
                    }
                }
            }
        } else {
            // output head partials: this warp covers h = wq*16 .. +15
#pragma unroll
            for (int mt = 0; mt < 2; mt++) {
#pragma unroll
                for (int s = 0; s < 2; s++) {
                    int row = wm * 32 + 16 * mt + 8 * s + g;
                    float c = 0.f;
#pragma unroll
                    for (int hg = 0; hg < 2; hg++) {
                        int hidx = (2 * wq + hg) * 8 + 2 * t4;
                        c = fmaf(acc[mt][hg * 4][2 * s],     sWo[hidx],
                            fmaf(acc[mt][hg * 4][2 * s + 1], sWo[hidx + 1], c));
                    }
                    c += __shfl_down_sync(0xffffffffu, c, 2, 4);
                    c += __shfl_down_sync(0xffffffffu, c, 1, 4);
                    if (t4 == 0) outp[wq * 132 + row] = c;
                }
            }
        }
    }
    __syncthreads();
    if (tid < 128) {
        float s = outp[tid] + outp[132 + tid] + outp[264 + tid] + outp[396 + tid];
        out[rowb + tid] = s + bout[0];
    }
}

// ---------------- launch ----------------
extern "C" void kernel_launch(void* const* d_in, const int* in_sizes, int n_in,
                              void* d_out, int out_size) {
    const float* x    = (const float*)d_in[0];
    const float* adj  = (const float*)d_in[1];
    const float* Wg   = (const float*)d_in[2];
    const float* bg   = (const float*)d_in[3];
    const float* Wih  = (const float*)d_in[4];
    const float* Whh  = (const float*)d_in[5];
    const float* bih  = (const float*)d_in[6];
    const float* bhh  = (const float*)d_in[7];
    const float* Wout = (const float*)d_in[8];
    const float* bout = (const float*)d_in[9];
    float* out = (float*)d_out;

    cudaFuncSetAttribute(lstm_mma, cudaFuncAttributeMaxDynamicSharedMemorySize, LSTM_SMEM);

    prep_all<<<(Jj * 2000 + 255) / 256, 256>>>(x, Wih, Whh);
    dim3 ga(50, SPLITK);
    gemm_adj_mma<<<ga, 256>>>(adj);
    lstm_mma<<<BNr / 128, 512, LSTM_SMEM>>>(Wg, bg, bih, bhh, Wout, bout, out);
}

// round 12
// speedup vs baseline: 6.6520x; 1.1728x over previous
#include <cuda_runtime.h>
#include <cuda_fp16.h>
#include <stdint.h>

#define Tt 12
#define Nn 4000
#define Jj 192          // B*T*C
#define BNr 32000       // B*N
#define NJ (Nn*Jj)
#define SPLITK 5
#define ADJ_SCALE 4096.0f
#define ADJ_INV (1.0f/4096.0f)

// ---------------- scratch ----------------
__device__ uint32_t d_XTh32[Jj * 2000];   // x^T hi: [j][m-pair] packed half2
__device__ float d_XGp[SPLITK * NJ];      // split-K partials of (4096*adj) @ x
__device__ __align__(16) char d_Wall[73728];   // pre-permuted lstm weights (fp16 hi)

// ---------------- helpers ----------------
__device__ __forceinline__ float tanha(float x) {
    float y;
    asm("tanh.approx.f32 %0, %1;" : "=f"(y) : "f"(x));
    return y;
}
__device__ __forceinline__ float siga(float x) {
    return fmaf(0.5f, tanha(0.5f * x), 0.5f);
}
__device__ __forceinline__ void split_h(float z, __half& h, __half& l) {
    h = __float2half(z);
    l = __float2half(z - __half2float(h));
}
__device__ __forceinline__ uint32_t pack2h(__half a, __half b) {
    __half2 v; v.x = a; v.y = b;
    return *(uint32_t*)&v;
}
__device__ __forceinline__ void hmma(float& d0, float& d1, float& d2, float& d3,
                                     uint32_t a0, uint32_t a1, uint32_t a2, uint32_t a3,
                                     uint32_t b0, uint32_t b1) {
    asm volatile("mma.sync.aligned.m16n8k16.row.col.f32.f16.f16.f32 "
        "{%0,%1,%2,%3}, {%4,%5,%6,%7}, {%8,%9}, {%0,%1,%2,%3};"
        : "+f"(d0), "+f"(d1), "+f"(d2), "+f"(d3)
        : "r"(a0), "r"(a1), "r"(a2), "r"(a3), "r"(b0), "r"(b1));
}

// ---------------- prep: weight permute (fp16) + x transpose/pack ----------------
__global__ void prep_all(const float* __restrict__ x,
                         const float* __restrict__ Wih, const float* __restrict__ Whh) {
    int gid = blockIdx.x * 256 + threadIdx.x;
    if (gid < 16384) {
        int o = gid >> 6, k = gid & 63;
        int gate = o >> 6, h = o & 63;
        int n = (h >> 3) * 32 + gate * 8 + (h & 7);
        *(__half*)(d_Wall +          (n * 72 + k) * 2) = __float2half(Wih[gid]);
        *(__half*)(d_Wall + 36864u + (n * 72 + k) * 2) = __float2half(Whh[gid]);
    }
    if (gid < Jj * 2000) {
        int j = gid / 2000, m2 = gid - j * 2000;
        int bt = j >> 1, c = j & 1;
        size_t base = (size_t)bt * Nn * 2 + c;
        float v0 = x[base + (size_t)(2 * m2) * 2];
        float v1 = x[base + (size_t)(2 * m2 + 1) * 2];
        d_XTh32[gid] = pack2h(__float2half(v0), __float2half(v1));
    }
}

// ---------------- adj GEMM via fp16 mma, 1-term, BM=80, 250 blocks ----------------
#define BTS 40
__global__ __launch_bounds__(256, 2) void gemm_adj_mma(const float* __restrict__ adj) {
    __shared__ __align__(16) __half Ah[80 * BTS];
    __shared__ __align__(16) __half Bh[192 * BTS];
    int tid = threadIdx.x, wid = tid >> 5, lane = tid & 31;
    int g = lane >> 2, t4 = lane & 3;
    int rowb = blockIdx.x * 80;
    int kb0 = blockIdx.y * 800;
    float acc[5][3][4];
#pragma unroll
    for (int mt = 0; mt < 5; mt++)
#pragma unroll
        for (int nt = 0; nt < 3; nt++)
#pragma unroll
            for (int q = 0; q < 4; q++) acc[mt][nt][q] = 0.f;

    for (int it = 0; it < 25; it++) {
        int kb = kb0 + it * 32;
#pragma unroll
        for (int q = 0; q < 5; q++) {            // A: 80 rows x 16 float2, scaled x4096
            int lin = tid + 256 * q;
            int r = lin >> 4, w = lin & 15;
            float2 v = *(const float2*)&adj[(size_t)(rowb + r) * Nn + kb + 2 * w];
            ((uint32_t*)Ah)[r * (BTS/2) + w] =
                pack2h(__float2half(v.x * ADJ_SCALE), __float2half(v.y * ADJ_SCALE));
        }
        int kw = kb >> 1;
#pragma unroll
        for (int q = 0; q < 12; q++) {           // B: 192 rows x 16 words
            int lin = tid + 256 * q;
            int j = lin >> 4, w = lin & 15;
            ((uint32_t*)Bh)[j * (BTS/2) + w] = d_XTh32[j * 2000 + kw + w];
        }
        __syncthreads();
#pragma unroll
        for (int kc = 0; kc < 2; kc++) {
            int kk = kc * 16 + 2 * t4;
            uint32_t ah[5][4];
#pragma unroll
            for (int mt = 0; mt < 5; mt++) {
                const __half* p0 = Ah + (16 * mt + g) * BTS + kk;
                const __half* p1 = Ah + (16 * mt + 8 + g) * BTS + kk;
                ah[mt][0] = *(const uint32_t*)p0;
                ah[mt][1] = *(const uint32_t*)p1;
                ah[mt][2] = *(const uint32_t*)(p0 + 8);
                ah[mt][3] = *(const uint32_t*)(p1 + 8);
            }
#pragma unroll
            for (int nt = 0; nt < 3; nt++) {
                int n = wid * 24 + nt * 8 + g;
                const __half* pb = Bh + n * BTS + kk;
                uint32_t bh0 = *(const uint32_t*)pb, bh1 = *(const uint32_t*)(pb + 8);
#pragma unroll
                for (int mt = 0; mt < 5; mt++)
                    hmma(acc[mt][nt][0], acc[mt][nt][1], acc[mt][nt][2], acc[mt][nt][3],
                         ah[mt][0], ah[mt][1], ah[mt][2], ah[mt][3], bh0, bh1);
            }
        }
        __syncthreads();
    }
    float* outp = d_XGp + (size_t)blockIdx.y * NJ;
#pragma unroll
    for (int mt = 0; mt < 5; mt++) {
#pragma unroll
        for (int nt = 0; nt < 3; nt++) {
            int r0 = rowb + 16 * mt + g;
            int col = wid * 24 + nt * 8 + 2 * t4;
            float2 v0 = {acc[mt][nt][0], acc[mt][nt][1]};
            float2 v1 = {acc[mt][nt][2], acc[mt][nt][3]};
            *(float2*)&outp[r0 * Jj + col] = v0;
            *(float2*)&outp[(r0 + 8) * Jj + col] = v1;
        }
    }
}

// ---------------- fp16 mma LSTM: 128 rows/block, 16 warps, mt2/nt8 ----------------
// input-proj: 1-term (G hi); recurrent: 2-term (H hi/lo)
#define WTS 72
#define OFF_WIHH 0u
#define OFF_WHHH 36864u
#define OFF_GH 73728u          // 128*72*2 = 18432
#define OFF_HH 92160u
#define OFF_HL 110592u
#define OFF_BIAS 129024u       // 256 f
#define OFF_WG 130048u         // 128 f
#define OFF_BG 130560u         // 64 f
#define OFF_WO 130816u         // 64 f
#define OFF_SXA 131072u        // 128*24 f
#define LSTM_SMEM 143360u

// 1-term pass: acc += A@B (A hi only)
__device__ __forceinline__ void mma_pass1(float (*acc)[8][4],
        const __half* Ah, const __half* Bh, int g, int t4, int wq) {
#pragma unroll
    for (int kc = 0; kc < 4; kc++) {
        int kk = kc * 16 + 2 * t4;
        uint32_t ah[2][4];
#pragma unroll
        for (int mt = 0; mt < 2; mt++) {
            const __half* p0 = Ah + (16 * mt + g) * WTS + kk;
            const __half* p1 = Ah + (16 * mt + 8 + g) * WTS + kk;
            ah[mt][0] = *(const uint32_t*)p0;
            ah[mt][1] = *(const uint32_t*)p1;
            ah[mt][2] = *(const uint32_t*)(p0 + 8);
            ah[mt][3] = *(const uint32_t*)(p1 + 8);
        }
#pragma unroll
        for (int np = 0; np < 4; np++) {
            int n0 = wq * 64 + (2 * np) * 8 + g;
            int n1 = n0 + 8;
            const __half* pb0 = Bh + n0 * WTS + kk;
            const __half* pb1 = Bh + n1 * WTS + kk;
            uint32_t b0h0 = *(const uint32_t*)pb0, b0h1 = *(const uint32_t*)(pb0 + 8);
            uint32_t b1h0 = *(const uint32_t*)pb1, b1h1 = *(const uint32_t*)(pb1 + 8);
            float* a00 = acc[0][2 * np];
            float* a10 = acc[1][2 * np];
            float* a01 = acc[0][2 * np + 1];
            float* a11 = acc[1][2 * np + 1];
            hmma(a00[0], a00[1], a00[2], a00[3], ah[0][0], ah[0][1], ah[0][2], ah[0][3], b0h0, b0h1);
            hmma(a10[0], a10[1], a10[2], a10[3], ah[1][0], ah[1][1], ah[1][2], ah[1][3], b0h0, b0h1);
            hmma(a01[0], a01[1], a01[2], a01[3], ah[0][0], ah[0][1], ah[0][2], ah[0][3], b1h0, b1h1);
            hmma(a11[0], a11[1], a11[2], a11[3], ah[1][0], ah[1][1], ah[1][2], ah[1][3], b1h0, b1h1);
        }
    }
}

// 2-term pass: acc += Ah@B + Al@B
__device__ __forceinline__ void mma_pass2(float (*acc)[8][4],
        const __half* Ah, const __half* Al, const __half* Bh,
        int g, int t4, int wq) {
#pragma unroll
    for (int kc = 0; kc < 4; kc++) {
        int kk = kc * 16 + 2 * t4;
        uint32_t ah[2][4], al[2][4];
#pragma unroll
        for (int mt = 0; mt < 2; mt++) {
            const __half* p0 = Ah + (16 * mt + g) * WTS + kk;
            const __half* p1 = Ah + (16 * mt + 8 + g) * WTS + kk;
            ah[mt][0] = *(const uint32_t*)p0;
            ah[mt][1] = *(const uint32_t*)p1;
            ah[mt][2] = *(const uint32_t*)(p0 + 8);
            ah[mt][3] = *(const uint32_t*)(p1 + 8);
            const __half* q0 = Al + (16 * mt + g) * WTS + kk;
            const __half* q1 = Al + (16 * mt + 8 + g) * WTS + kk;
            al[mt][0] = *(const uint32_t*)q0;
            al[mt][1] = *(const uint32_t*)q1;
            al[mt][2] = *(const uint32_t*)(q0 + 8);
            al[mt][3] = *(const uint32_t*)(q1 + 8);
        }
#pragma unroll
        for (int np = 0; np < 4; np++) {
            int n0 = wq * 64 + (2 * np) * 8 + g;
            int n1 = n0 + 8;
            const __half* pb0 = Bh + n0 * WTS + kk;
            const __half* pb1 = Bh + n1 * WTS + kk;
            uint32_t b0h0 = *(const uint32_t*)pb0, b0h1 = *(const uint32_t*)(pb0 + 8);
            uint32_t b1h0 = *(const uint32_t*)pb1, b1h1 = *(const uint32_t*)(pb1 + 8);
            float* a00 = acc[0][2 * np];
            float* a10 = acc[1][2 * np];
            float* a01 = acc[0][2 * np + 1];
            float* a11 = acc[1][2 * np + 1];
            hmma(a00[0], a00[1], a00[2], a00[3], ah[0][0], ah[0][1], ah[0][2], ah[0][3], b0h0, b0h1);
            hmma(a10[0], a10[1], a10[2], a10[3], ah[1][0], ah[1][1], ah[1][2], ah[1][3], b0h0, b0h1);
            hmma(a01[0], a01[1], a01[2], a01[3], ah[0][0], ah[0][1], ah[0][2], ah[0][3], b1h0, b1h1);
            hmma(a11[0], a11[1], a11[2], a11[3], ah[1][0], ah[1][1], ah[1][2], ah[1][3], b1h0, b1h1);
            hmma(a00[0], a00[1], a00[2], a00[3], al[0][0], al[0][1], al[0][2], al[0][3], b0h0, b0h1);
            hmma(a10[0], a10[1], a10[2], a10[3], al[1][0], al[1][1], al[1][2], al[1][3], b0h0, b0h1);
            hmma(a01[0], a01[1], a01[2], a01[3], al[0][0], al[0][1], al[0][2], al[0][3], b1h0, b1h1);
            hmma(a11[0], a11[1], a11[2], a11[3], al[1][0], al[1][1], al[1][2], al[1][3], b1h0, b1h1);
        }
    }
}

__global__ __launch_bounds__(512, 1) void lstm_mma(
        const float* __restrict__ Wg,  const float* __restrict__ bg,
        const float* __restrict__ bih, const float* __restrict__ bhh,
        const float* __restrict__ Wout, const float* __restrict__ bout,
        float* __restrict__ out) {
    extern __shared__ __align__(16) char smc[];
    __half* WIHh = (__half*)(smc + OFF_WIHH);
    __half* WHHh = (__half*)(smc + OFF_WHHH);
    __half* Gh = (__half*)(smc + OFF_GH);
    __half* Hh = (__half*)(smc + OFF_HH);
    __half* Hl = (__half*)(smc + OFF_HL);
    float* sbias = (float*)(smc + OFF_BIAS);
    float* sWg   = (float*)(smc + OFF_WG);
    float* sbg   = (float*)(smc + OFF_BG);
    float* sWo   = (float*)(smc + OFF_WO);
    float* sxa   = (float*)(smc + OFF_SXA);
    float* outp  = (float*)(smc + OFF_GH);   // reused after final MMA

    int tid = threadIdx.x, wid = tid >> 5, lane = tid & 31;
    int g = lane >> 2, t4 = lane & 3;
    int wm = wid >> 2, wq = wid & 3;
    int rowb = blockIdx.x * 128;

    {   // linear copy of pre-permuted weight image: 4608 uint4
        const uint4* src = (const uint4*)d_Wall;
        uint4* dst = (uint4*)smc;
#pragma unroll
        for (int q = 0; q < 9; q++) dst[tid + 512 * q] = src[tid + 512 * q];
    }
    if (tid < 256) {
        int n = tid;
        int gate = (n >> 3) & 3, h = (n >> 5) * 8 + (n & 7);
        int o = gate * 64 + h;
        sbias[n] = bih[o] + bhh[o];
    }
    if (tid < 128) sWg[tid] = Wg[tid];
    if (tid < 64) { sbg[tid] = bg[tid]; sWo[tid] = Wout[tid]; }
    // fused split-K reduce: this block's 128 rows x 24 cols
    for (int v = tid; v < 128 * 24; v += 512) {
        int row = v / 24, j = v - row * 24;
        int R = rowb + row;
        int b = R / Nn, n = R - b * Nn;
        size_t idx = (size_t)n * Jj + b * 24 + j;
        float s = 0.f;
#pragma unroll
        for (int sp = 0; sp < SPLITK; sp++) s += d_XGp[(size_t)sp * NJ + idx];
        sxa[v] = s * ADJ_INV;
    }
    __syncthreads();

    int grow = tid >> 2, t4b = tid & 3;
    float cst[2][8];
#pragma unroll
    for (int mt = 0; mt < 2; mt++)
#pragma unroll
        for (int q = 0; q < 8; q++) cst[mt][q] = 0.f;

    const __half* Ahm = Gh + wm * 32 * WTS;
    const __half* Hhm = Hh + wm * 32 * WTS;
    const __half* Hlm = Hl + wm * 32 * WTS;

    for (int t = 0; t < Tt; t++) {
        // ---- G tile build (relu GCN, fp16 hi only) ----
        {
            float xv0 = sxa[grow * 24 + 2 * t];
            float xv1 = sxa[grow * 24 + 2 * t + 1];
#pragma unroll
            for (int j = 0; j < 8; j++) {
                int k = t4b * 2 + 8 * j;
                float z0 = fmaf(xv0, sWg[2 * k],     fmaf(xv1, sWg[2 * k + 1], sbg[k]));
                float z1 = fmaf(xv0, sWg[2 * k + 2], fmaf(xv1, sWg[2 * k + 3], sbg[k + 1]));
                z0 = fmaxf(z0, 0.f); z1 = fmaxf(z1, 0.f);
                *(uint32_t*)(Gh + grow * WTS + k) =
                    pack2h(__float2half(z0), __float2half(z1));
            }
        }
        __syncthreads();
        float acc[2][8][4];
#pragma unroll
        for (int mt = 0; mt < 2; mt++)
#pragma unroll
            for (int nt = 0; nt < 8; nt++)
#pragma unroll
                for (int q = 0; q < 4; q++) acc[mt][nt][q] = 0.f;
        mma_pass1(acc, Ahm, WIHh, g, t4, wq);
        if (t > 0) mma_pass2(acc, Hhm, Hlm, WHHh, g, t4, wq);
        // ---- cell update ----
#pragma unroll
        for (int mt = 0; mt < 2; mt++) {
#pragma unroll
            for (int hg = 0; hg < 2; hg++) {
#pragma unroll
                for (int d = 0; d < 4; d++) {
                    int j = d & 1;
                    int nb = wq * 64 + hg * 32 + 2 * t4 + j;
                    float ig = acc[mt][hg * 4 + 0][d] + sbias[nb];
                    float fg = acc[mt][hg * 4 + 1][d] + sbias[nb + 8];
                    float gg = acc[mt][hg * 4 + 2][d] + sbias[nb + 16];
                    float og = acc[mt][hg * 4 + 3][d] + sbias[nb + 24];
                    float cn = siga(fg) * cst[mt][hg * 4 + d] + siga(ig) * tanha(gg);
                    cst[mt][hg * 4 + d] = cn;
                    acc[mt][hg * 4 + 0][d] = siga(og) * tanha(cn);
                }
            }
        }
        __syncthreads();
        if (t < Tt - 1) {
#pragma unroll
            for (int mt = 0; mt < 2; mt++) {
#pragma unroll
                for (int s = 0; s < 2; s++) {
                    int row = wm * 32 + 16 * mt + 8 * s + g;
#pragma unroll
                    for (int hg = 0; hg < 2; hg++) {
                        int hidx = (2 * wq + hg) * 8 + 2 * t4;
                        float z0 = acc[mt][hg * 4][2 * s];
                        float z1 = acc[mt][hg * 4][2 * s + 1];
                        __half h0, l0, h1, l1;
                        split_h(z0, h0, l0); split_h(z1, h1, l1);
                        *(uint32_t*)(Hh + row * WTS + hidx) = pack2h(h0, h1);
                        *(uint32_t*)(Hl + row * WTS + hidx) = pack2h(l0, l1);
                    }
                }
            }
        } else {
#pragma unroll
            for (int mt = 0; mt < 2; mt++) {
#pragma unroll
                for (int s = 0; s < 2; s++) {
                    int row = wm * 32 + 16 * mt + 8 * s + g;
                    float c = 0.f;
#pragma unroll
                    for (int hg = 0; hg < 2; hg++) {
                        int hidx = (2 * wq + hg) * 8 + 2 * t4;
                        c = fmaf(acc[mt][hg * 4][2 * s],     sWo[hidx],
                            fmaf(acc[mt][hg * 4][2 * s + 1], sWo[hidx + 1], c));
                    }
                    c += __shfl_down_sync(0xffffffffu, c, 2, 4);
                    c += __shfl_down_sync(0xffffffffu, c, 1, 4);
                    if (t4 == 0) outp[wq * 132 + row] = c;
                }
            }
        }
    }
    __syncthreads();
    if (tid < 128) {
        float s = outp[tid] + outp[132 + tid] + outp[264 + tid] + outp[396 + tid];
        out[rowb + tid] = s + bout[0];
    }
}

// ---------------- launch ----------------
extern "C" void kernel_launch(void* const* d_in, const int* in_sizes, int n_in,
                              void* d_out, int out_size) {
    const float* x    = (const float*)d_in[0];
    const float* adj  = (const float*)d_in[1];
    const float* Wg   = (const float*)d_in[2];
    const float* bg   = (const float*)d_in[3];
    const float* Wih  = (const float*)d_in[4];
    const float* Whh  = (const float*)d_in[5];
    const float* bih  = (const float*)d_in[6];
    const float* bhh  = (const float*)d_in[7];
    const float* Wout = (const float*)d_in[8];
    const float* bout = (const float*)d_in[9];
    float* out = (float*)d_out;

    cudaFuncSetAttribute(lstm_mma, cudaFuncAttributeMaxDynamicSharedMemorySize, LSTM_SMEM);

    prep_all<<<(Jj * 2000 + 255) / 256, 256>>>(x, Wih, Whh);
    dim3 ga(50, SPLITK);
    gemm_adj_mma<<<ga, 256>>>(adj);
    lstm_mma<<<BNr / 128, 512, LSTM_SMEM>>>(Wg, bg, bih, bhh, Wout, bout, out);
}

// round 13
// speedup vs baseline: 7.8148x; 1.1748x over previous
#include <cuda_runtime.h>
#include <cuda_fp16.h>
#include <stdint.h>

#define Tt 12
#define Nn 4000
#define Jj 192          // B*T*C
#define BNr 32000       // B*N
#define NJ (Nn*Jj)
#define SPLITK 5
#define ADJ_SCALE 4096.0f
#define ADJ_INV (1.0f/4096.0f)

// ---------------- scratch ----------------
__device__ uint32_t d_XTh32[Jj * 2000];   // x^T hi: [j][m-pair] packed half2
__device__ float d_XGp[SPLITK * NJ];      // split-K partials of (4096*adj) @ x
__device__ __align__(16) char d_Wall[73728];   // pre-permuted lstm weights (fp16)

// ---------------- helpers ----------------
__device__ __forceinline__ float tanha(float x) {
    float y;
    asm("tanh.approx.f32 %0, %1;" : "=f"(y) : "f"(x));
    return y;
}
__device__ __forceinline__ float siga(float x) {
    return fmaf(0.5f, tanha(0.5f * x), 0.5f);
}
__device__ __forceinline__ uint32_t pack2h(__half a, __half b) {
    __half2 v; v.x = a; v.y = b;
    return *(uint32_t*)&v;
}
__device__ __forceinline__ void hmma(float& d0, float& d1, float& d2, float& d3,
                                     uint32_t a0, uint32_t a1, uint32_t a2, uint32_t a3,
                                     uint32_t b0, uint32_t b1) {
    asm volatile("mma.sync.aligned.m16n8k16.row.col.f32.f16.f16.f32 "
        "{%0,%1,%2,%3}, {%4,%5,%6,%7}, {%8,%9}, {%0,%1,%2,%3};"
        : "+f"(d0), "+f"(d1), "+f"(d2), "+f"(d3)
        : "r"(a0), "r"(a1), "r"(a2), "r"(a3), "r"(b0), "r"(b1));
}

// ---------------- prep: weight permute (fp16) + x transpose/pack ----------------
__global__ void prep_all(const float* __restrict__ x,
                         const float* __restrict__ Wih, const float* __restrict__ Whh) {
    int gid = blockIdx.x * 256 + threadIdx.x;
    if (gid < 16384) {
        int o = gid >> 6, k = gid & 63;
        int gate = o >> 6, h = o & 63;
        int n = (h >> 3) * 32 + gate * 8 + (h & 7);
        *(__half*)(d_Wall +          (n * 72 + k) * 2) = __float2half(Wih[gid]);
        *(__half*)(d_Wall + 36864u + (n * 72 + k) * 2) = __float2half(Whh[gid]);
    }
    if (gid < Jj * 2000) {
        int j = gid / 2000, m2 = gid - j * 2000;
        int bt = j >> 1, c = j & 1;
        size_t base = (size_t)bt * Nn * 2 + c;
        float v0 = x[base + (size_t)(2 * m2) * 2];
        float v1 = x[base + (size_t)(2 * m2 + 1) * 2];
        d_XTh32[gid] = pack2h(__float2half(v0), __float2half(v1));
    }
}

// ---------------- adj GEMM via fp16 mma, 1-term, BM=80, 250 blocks ----------------
#define BTS 40
__global__ __launch_bounds__(256, 2) void gemm_adj_mma(const float* __restrict__ adj) {
    __shared__ __align__(16) __half Ah[80 * BTS];
    __shared__ __align__(16) __half Bh[192 * BTS];
    int tid = threadIdx.x, wid = tid >> 5, lane = tid & 31;
    int g = lane >> 2, t4 = lane & 3;
    int rowb = blockIdx.x * 80;
    int kb0 = blockIdx.y * 800;
    float acc[5][3][4];
#pragma unroll
    for (int mt = 0; mt < 5; mt++)
#pragma unroll
        for (int nt = 0; nt < 3; nt++)
#pragma unroll
            for (int q = 0; q < 4; q++) acc[mt][nt][q] = 0.f;

    for (int it = 0; it < 25; it++) {
        int kb = kb0 + it * 32;
#pragma unroll
        for (int q = 0; q < 5; q++) {            // A: 80 rows x 16 float2, scaled x4096
            int lin = tid + 256 * q;
            int r = lin >> 4, w = lin & 15;
            float2 v = *(const float2*)&adj[(size_t)(rowb + r) * Nn + kb + 2 * w];
            ((uint32_t*)Ah)[r * (BTS/2) + w] =
                pack2h(__float2half(v.x * ADJ_SCALE), __float2half(v.y * ADJ_SCALE));
        }
        int kw = kb >> 1;
#pragma unroll
        for (int q = 0; q < 12; q++) {           // B: 192 rows x 16 words
            int lin = tid + 256 * q;
            int j = lin >> 4, w = lin & 15;
            ((uint32_t*)Bh)[j * (BTS/2) + w] = d_XTh32[j * 2000 + kw + w];
        }
        __syncthreads();
#pragma unroll
        for (int kc = 0; kc < 2; kc++) {
            int kk = kc * 16 + 2 * t4;
            uint32_t ah[5][4];
#pragma unroll
            for (int mt = 0; mt < 5; mt++) {
                const __half* p0 = Ah + (16 * mt + g) * BTS + kk;
                const __half* p1 = Ah + (16 * mt + 8 + g) * BTS + kk;
                ah[mt][0] = *(const uint32_t*)p0;
                ah[mt][1] = *(const uint32_t*)p1;
                ah[mt][2] = *(const uint32_t*)(p0 + 8);
                ah[mt][3] = *(const uint32_t*)(p1 + 8);
            }
#pragma unroll
            for (int nt = 0; nt < 3; nt++) {
                int n = wid * 24 + nt * 8 + g;
                const __half* pb = Bh + n * BTS + kk;
                uint32_t bh0 = *(const uint32_t*)pb, bh1 = *(const uint32_t*)(pb + 8);
#pragma unroll
                for (int mt = 0; mt < 5; mt++)
                    hmma(acc[mt][nt][0], acc[mt][nt][1], acc[mt][nt][2], acc[mt][nt][3],
                         ah[mt][0], ah[mt][1], ah[mt][2], ah[mt][3], bh0, bh1);
            }
        }
        __syncthreads();
    }
    float* outp = d_XGp + (size_t)blockIdx.y * NJ;
#pragma unroll
    for (int mt = 0; mt < 5; mt++) {
#pragma unroll
        for (int nt = 0; nt < 3; nt++) {
            int r0 = rowb + 16 * mt + g;
            int col = wid * 24 + nt * 8 + 2 * t4;
            float2 v0 = {acc[mt][nt][0], acc[mt][nt][1]};
            float2 v1 = {acc[mt][nt][2], acc[mt][nt][3]};
            *(float2*)&outp[r0 * Jj + col] = v0;
            *(float2*)&outp[(r0 + 8) * Jj + col] = v1;
        }
    }
}

// ---------------- fp16 mma LSTM: 128 rows/block, 16 warps, 1-term everywhere ----------------
#define WTS 72
#define OFF_WIHH 0u
#define OFF_WHHH 36864u
#define OFF_GH 73728u          // 128*72*2 = 18432
#define OFF_HH 92160u
#define OFF_BIAS 110592u       // 256 f
#define OFF_WG 111616u         // 128 f
#define OFF_BG 112128u         // 64 f
#define OFF_WO 112384u         // 64 f
#define OFF_SXA 112640u        // 128*24 f = 12288 B
#define LSTM_SMEM 124928u

// 1-term pass: acc += A@B
__device__ __forceinline__ void mma_pass1(float (*acc)[8][4],
        const __half* Ah, const __half* Bh, int g, int t4, int wq) {
#pragma unroll
    for (int kc = 0; kc < 4; kc++) {
        int kk = kc * 16 + 2 * t4;
        uint32_t ah[2][4];
#pragma unroll
        for (int mt = 0; mt < 2; mt++) {
            const __half* p0 = Ah + (16 * mt + g) * WTS + kk;
            const __half* p1 = Ah + (16 * mt + 8 + g) * WTS + kk;
            ah[mt][0] = *(const uint32_t*)p0;
            ah[mt][1] = *(const uint32_t*)p1;
            ah[mt][2] = *(const uint32_t*)(p0 + 8);
            ah[mt][3] = *(const uint32_t*)(p1 + 8);
        }
#pragma unroll
        for (int np = 0; np < 4; np++) {
            int n0 = wq * 64 + (2 * np) * 8 + g;
            int n1 = n0 + 8;
            const __half* pb0 = Bh + n0 * WTS + kk;
            const __half* pb1 = Bh + n1 * WTS + kk;
            uint32_t b0h0 = *(const uint32_t*)pb0, b0h1 = *(const uint32_t*)(pb0 + 8);
            uint32_t b1h0 = *(const uint32_t*)pb1, b1h1 = *(const uint32_t*)(pb1 + 8);
            float* a00 = acc[0][2 * np];
            float* a10 = acc[1][2 * np];
            float* a01 = acc[0][2 * np + 1];
            float* a11 = acc[1][2 * np + 1];
            hmma(a00[0], a00[1], a00[2], a00[3], ah[0][0], ah[0][1], ah[0][2], ah[0][3], b0h0, b0h1);
            hmma(a10[0], a10[1], a10[2], a10[3], ah[1][0], ah[1][1], ah[1][2], ah[1][3], b0h0, b0h1);
            hmma(a01[0], a01[1], a01[2], a01[3], ah[0][0], ah[0][1], ah[0][2], ah[0][3], b1h0, b1h1);
            hmma(a11[0], a11[1], a11[2], a11[3], ah[1][0], ah[1][1], ah[1][2], ah[1][3], b1h0, b1h1);
        }
    }
}

__global__ __launch_bounds__(512, 1) void lstm_mma(
        const float* __restrict__ Wg,  const float* __restrict__ bg,
        const float* __restrict__ bih, const float* __restrict__ bhh,
        const float* __restrict__ Wout, const float* __restrict__ bout,
        float* __restrict__ out) {
    extern __shared__ __align__(16) char smc[];
    __half* WIHh = (__half*)(smc + OFF_WIHH);
    __half* WHHh = (__half*)(smc + OFF_WHHH);
    __half* Gh = (__half*)(smc + OFF_GH);
    __half* Hh = (__half*)(smc + OFF_HH);
    float* sbias = (float*)(smc + OFF_BIAS);
    float* sWg   = (float*)(smc + OFF_WG);
    float* sbg   = (float*)(smc + OFF_BG);
    float* sWo   = (float*)(smc + OFF_WO);
    float* sxa   = (float*)(smc + OFF_SXA);
    float* outp  = (float*)(smc + OFF_GH);   // reused after final MMA

    int tid = threadIdx.x, wid = tid >> 5, lane = tid & 31;
    int g = lane >> 2, t4 = lane & 3;
    int wm = wid >> 2, wq = wid & 3;
    int rowb = blockIdx.x * 128;

    {   // linear copy of pre-permuted weight image: 4608 uint4
        const uint4* src = (const uint4*)d_Wall;
        uint4* dst = (uint4*)smc;
#pragma unroll
        for (int q = 0; q < 9; q++) dst[tid + 512 * q] = src[tid + 512 * q];
    }
    if (tid < 256) {
        int n = tid;
        int gate = (n >> 3) & 3, h = (n >> 5) * 8 + (n & 7);
        int o = gate * 64 + h;
        sbias[n] = bih[o] + bhh[o];
    }
    if (tid < 128) sWg[tid] = Wg[tid];
    if (tid < 64) { sbg[tid] = bg[tid]; sWo[tid] = Wout[tid]; }
    // fused split-K reduce: this block's 128 rows x 24 cols
    for (int v = tid; v < 128 * 24; v += 512) {
        int row = v / 24, j = v - row * 24;
        int R = rowb + row;
        int b = R / Nn, n = R - b * Nn;
        size_t idx = (size_t)n * Jj + b * 24 + j;
        float s = 0.f;
#pragma unroll
        for (int sp = 0; sp < SPLITK; sp++) s += d_XGp[(size_t)sp * NJ + idx];
        sxa[v] = s * ADJ_INV;
    }
    __syncthreads();

    int grow = tid >> 2, t4b = tid & 3;
    float cst[2][8];
#pragma unroll
    for (int mt = 0; mt < 2; mt++)
#pragma unroll
        for (int q = 0; q < 8; q++) cst[mt][q] = 0.f;

    const __half* Ahm = Gh + wm * 32 * WTS;
    const __half* Hhm = Hh + wm * 32 * WTS;

    for (int t = 0; t < Tt; t++) {
        // ---- G tile build (relu GCN, fp16) ----
        {
            float xv0 = sxa[grow * 24 + 2 * t];
            float xv1 = sxa[grow * 24 + 2 * t + 1];
#pragma unroll
            for (int j = 0; j < 8; j++) {
                int k = t4b * 2 + 8 * j;
                float z0 = fmaf(xv0, sWg[2 * k],     fmaf(xv1, sWg[2 * k + 1], sbg[k]));
                float z1 = fmaf(xv0, sWg[2 * k + 2], fmaf(xv1, sWg[2 * k + 3], sbg[k + 1]));
                z0 = fmaxf(z0, 0.f); z1 = fmaxf(z1, 0.f);
                *(uint32_t*)(Gh + grow * WTS + k) =
                    pack2h(__float2half(z0), __float2half(z1));
            }
        }
        __syncthreads();
        float acc[2][8][4];
#pragma unroll
        for (int mt = 0; mt < 2; mt++)
#pragma unroll
            for (int nt = 0; nt < 8; nt++)
#pragma unroll
                for (int q = 0; q < 4; q++) acc[mt][nt][q] = 0.f;
        mma_pass1(acc, Ahm, WIHh, g, t4, wq);
        if (t > 0) mma_pass1(acc, Hhm, WHHh, g, t4, wq);
        // ---- cell update ----
#pragma unroll
        for (int mt = 0; mt < 2; mt++) {
#pragma unroll
            for (int hg = 0; hg < 2; hg++) {
#pragma unroll
                for (int d = 0; d < 4; d++) {
                    int j = d & 1;
                    int nb = wq * 64 + hg * 32 + 2 * t4 + j;
                    float ig = acc[mt][hg * 4 + 0][d] + sbias[nb];
                    float fg = acc[mt][hg * 4 + 1][d] + sbias[nb + 8];
                    float gg = acc[mt][hg * 4 + 2][d] + sbias[nb + 16];
                    float og = acc[mt][hg * 4 + 3][d] + sbias[nb + 24];
                    float cn = siga(fg) * cst[mt][hg * 4 + d] + siga(ig) * tanha(gg);
                    cst[mt][hg * 4 + d] = cn;
                    acc[mt][hg * 4 + 0][d] = siga(og) * tanha(cn);
                }
            }
        }
        __syncthreads();
        if (t < Tt - 1) {
            // store new H (fp16): h = (2wq+hg)*8 + 2*t4 (+1)
#pragma unroll
            for (int mt = 0; mt < 2; mt++) {
#pragma unroll
                for (int s = 0; s < 2; s++) {
                    int row = wm * 32 + 16 * mt + 8 * s + g;
#pragma unroll
                    for (int hg = 0; hg < 2; hg++) {
                        int hidx = (2 * wq + hg) * 8 + 2 * t4;
                        *(uint32_t*)(Hh + row * WTS + hidx) =
                            pack2h(__float2half(acc[mt][hg * 4][2 * s]),
                                   __float2half(acc[mt][hg * 4][2 * s + 1]));
                    }
                }
            }
        } else {
            // output head partials: this warp covers h = wq*16 .. +15
#pragma unroll
            for (int mt = 0; mt < 2; mt++) {
#pragma unroll
                for (int s = 0; s < 2; s++) {
                    int row = wm * 32 + 16 * mt + 8 * s + g;
                    float c = 0.f;
#pragma unroll
                    for (int hg = 0; hg < 2; hg++) {
                        int hidx = (2 * wq + hg) * 8 + 2 * t4;
                        c = fmaf(acc[mt][hg * 4][2 * s],     sWo[hidx],
                            fmaf(acc[mt][hg * 4][2 * s + 1], sWo[hidx + 1], c));
                    }
                    c += __shfl_down_sync(0xffffffffu, c, 2, 4);
                    c += __shfl_down_sync(0xffffffffu, c, 1, 4);
                    if (t4 == 0) outp[wq * 132 + row] = c;
                }
            }
        }
    }
    __syncthreads();
    if (tid < 128) {
        float s = outp[tid] + outp[132 + tid] + outp[264 + tid] + outp[396 + tid];
        out[rowb + tid] = s + bout[0];
    }
}

// ---------------- launch ----------------
extern "C" void kernel_launch(void* const* d_in, const int* in_sizes, int n_in,
                              void* d_out, int out_size) {
    const float* x    = (const float*)d_in[0];
    const float* adj  = (const float*)d_in[1];
    const float* Wg   = (const float*)d_in[2];
    const float* bg   = (const float*)d_in[3];
    const float* Wih  = (const float*)d_in[4];
    const float* Whh  = (const float*)d_in[5];
    const float* bih  = (const float*)d_in[6];
    const float* bhh  = (const float*)d_in[7];
    const float* Wout = (const float*)d_in[8];
    const float* bout = (const float*)d_in[9];
    float* out = (float*)d_out;

    cudaFuncSetAttribute(lstm_mma, cudaFuncAttributeMaxDynamicSharedMemorySize, LSTM_SMEM);

    prep_all<<<(Jj * 2000 + 255) / 256, 256>>>(x, Wih, Whh);
    dim3 ga(50, SPLITK);
    gemm_adj_mma<<<ga, 256>>>(adj);
    lstm_mma<<<BNr / 128, 512, LSTM_SMEM>>>(Wg, bg, bih, bhh, Wout, bout, out);
}

// round 14
// speedup vs baseline: 8.6134x; 1.1022x over previous
#include <cuda_runtime.h>
#include <cuda_fp16.h>
#include <stdint.h>

#define Tt 12
#define Nn 4000
#define Jj 192          // B*T*C
#define BNr 32000       // B*N
#define NJ (Nn*Jj)
#define SPLITK 5
#define ADJ_SCALE 4096.0f
#define ADJ_INV (1.0f/4096.0f)

// ---------------- scratch ----------------
__device__ uint32_t d_XTh32[Jj * 2000];   // x^T: [j][m-pair] packed half2
__device__ float d_XGp[SPLITK * NJ];      // split-K partials of (4096*adj) @ x
__device__ __align__(16) char d_Wall[73728];   // pre-permuted lstm weights (fp16)

// ---------------- helpers ----------------
__device__ __forceinline__ float tanha(float x) {
    float y;
    asm("tanh.approx.f32 %0, %1;" : "=f"(y) : "f"(x));
    return y;
}
__device__ __forceinline__ float siga(float x) {
    return fmaf(0.5f, tanha(0.5f * x), 0.5f);
}
__device__ __forceinline__ uint32_t pack2h(__half a, __half b) {
    __half2 v; v.x = a; v.y = b;
    return *(uint32_t*)&v;
}
__device__ __forceinline__ void hmma(float& d0, float& d1, float& d2, float& d3,
                                     uint32_t a0, uint32_t a1, uint32_t a2, uint32_t a3,
                                     uint32_t b0, uint32_t b1) {
    asm volatile("mma.sync.aligned.m16n8k16.row.col.f32.f16.f16.f32 "
        "{%0,%1,%2,%3}, {%4,%5,%6,%7}, {%8,%9}, {%0,%1,%2,%3};"
        : "+f"(d0), "+f"(d1), "+f"(d2), "+f"(d3)
        : "r"(a0), "r"(a1), "r"(a2), "r"(a3), "r"(b0), "r"(b1));
}

// ---------------- prep: weight permute (fp16) + x transpose/pack ----------------
__global__ void prep_all(const float* __restrict__ x,
                         const float* __restrict__ Wih, const float* __restrict__ Whh) {
    int gid = blockIdx.x * 256 + threadIdx.x;
    if (gid < 16384) {
        int o = gid >> 6, k = gid & 63;
        int gate = o >> 6, h = o & 63;
        int n = (h >> 3) * 32 + gate * 8 + (h & 7);
        *(__half*)(d_Wall +          (n * 72 + k) * 2) = __float2half(Wih[gid]);
        *(__half*)(d_Wall + 36864u + (n * 72 + k) * 2) = __float2half(Whh[gid]);
    }
    if (gid < Jj * 2000) {
        int j = gid / 2000, m2 = gid - j * 2000;
        int bt = j >> 1, c = j & 1;
        size_t base = (size_t)bt * Nn * 2 + c;
        float v0 = x[base + (size_t)(2 * m2) * 2];
        float v1 = x[base + (size_t)(2 * m2 + 1) * 2];
        d_XTh32[gid] = pack2h(__float2half(v0), __float2half(v1));
    }
}

// ---------------- adj GEMM via fp16 mma, 1-term, BM=80, 250 blocks ----------------
#define BTS 40
__global__ __launch_bounds__(256, 2) void gemm_adj_mma(const float* __restrict__ adj) {
    __shared__ __align__(16) __half Ah[80 * BTS];
    __shared__ __align__(16) __half Bh[192 * BTS];
    int tid = threadIdx.x, wid = tid >> 5, lane = tid & 31;
    int g = lane >> 2, t4 = lane & 3;
    int rowb = blockIdx.x * 80;
    int kb0 = blockIdx.y * 800;
    float acc[5][3][4];
#pragma unroll
    for (int mt = 0; mt < 5; mt++)
#pragma unroll
        for (int nt = 0; nt < 3; nt++)
#pragma unroll
            for (int q = 0; q < 4; q++) acc[mt][nt][q] = 0.f;

    for (int it = 0; it < 25; it++) {
        int kb = kb0 + it * 32;
#pragma unroll
        for (int q = 0; q < 5; q++) {            // A: 80 rows x 16 float2, scaled x4096
            int lin = tid + 256 * q;
            int r = lin >> 4, w = lin & 15;
            float2 v = *(const float2*)&adj[(size_t)(rowb + r) * Nn + kb + 2 * w];
            ((uint32_t*)Ah)[r * (BTS/2) + w] =
                pack2h(__float2half(v.x * ADJ_SCALE), __float2half(v.y * ADJ_SCALE));
        }
        int kw = kb >> 1;
#pragma unroll
        for (int q = 0; q < 12; q++) {           // B: 192 rows x 16 words
            int lin = tid + 256 * q;
            int j = lin >> 4, w = lin & 15;
            ((uint32_t*)Bh)[j * (BTS/2) + w] = d_XTh32[j * 2000 + kw + w];
        }
        __syncthreads();
#pragma unroll
        for (int kc = 0; kc < 2; kc++) {
            int kk = kc * 16 + 2 * t4;
            uint32_t ah[5][4];
#pragma unroll
            for (int mt = 0; mt < 5; mt++) {
                const __half* p0 = Ah + (16 * mt + g) * BTS + kk;
                const __half* p1 = Ah + (16 * mt + 8 + g) * BTS + kk;
                ah[mt][0] = *(const uint32_t*)p0;
                ah[mt][1] = *(const uint32_t*)p1;
                ah[mt][2] = *(const uint32_t*)(p0 + 8);
                ah[mt][3] = *(const uint32_t*)(p1 + 8);
            }
#pragma unroll
            for (int nt = 0; nt < 3; nt++) {
                int n = wid * 24 + nt * 8 + g;
                const __half* pb = Bh + n * BTS + kk;
                uint32_t bh0 = *(const uint32_t*)pb, bh1 = *(const uint32_t*)(pb + 8);
#pragma unroll
                for (int mt = 0; mt < 5; mt++)
                    hmma(acc[mt][nt][0], acc[mt][nt][1], acc[mt][nt][2], acc[mt][nt][3],
                         ah[mt][0], ah[mt][1], ah[mt][2], ah[mt][3], bh0, bh1);
            }
        }
        __syncthreads();
    }
    float* outp = d_XGp + (size_t)blockIdx.y * NJ;
#pragma unroll
    for (int mt = 0; mt < 5; mt++) {
#pragma unroll
        for (int nt = 0; nt < 3; nt++) {
            int r0 = rowb + 16 * mt + g;
            int col = wid * 24 + nt * 8 + 2 * t4;
            float2 v0 = {acc[mt][nt][0], acc[mt][nt][1]};
            float2 v1 = {acc[mt][nt][2], acc[mt][nt][3]};
            *(float2*)&outp[r0 * Jj + col] = v0;
            *(float2*)&outp[(r0 + 8) * Jj + col] = v1;
        }
    }
}

// ---------------- fp16 mma LSTM: 64 rows/block, 8 warps, 2 CTAs/SM ----------------
#define WTS 72
#define OFF_WIHH 0u
#define OFF_WHHH 36864u
#define OFF_GH 73728u          // 64*72*2 = 9216
#define OFF_HH 82944u          // 9216
#define OFF_BIAS 92160u        // 256 f
#define OFF_WG 93184u          // 128 f
#define OFF_BG 93696u          // 64 f
#define OFF_WO 93952u          // 64 f
#define OFF_SXA 94208u         // 64*24 f = 6144 B
#define LSTM_SMEM 100352u

// 1-term pass: acc += A@B.  A tile = 32 rows (this warp's m-half), warp n-slice wq*64.
__device__ __forceinline__ void mma_pass1(float (*acc)[8][4],
        const __half* Ah, const __half* Bh, int g, int t4, int wq) {
#pragma unroll
    for (int kc = 0; kc < 4; kc++) {
        int kk = kc * 16 + 2 * t4;
        uint32_t ah[2][4];
#pragma unroll
        for (int mt = 0; mt < 2; mt++) {
            const __half* p0 = Ah + (16 * mt + g) * WTS + kk;
            const __half* p1 = Ah + (16 * mt + 8 + g) * WTS + kk;
            ah[mt][0] = *(const uint32_t*)p0;
            ah[mt][1] = *(const uint32_t*)p1;
            ah[mt][2] = *(const uint32_t*)(p0 + 8);
            ah[mt][3] = *(const uint32_t*)(p1 + 8);
        }
#pragma unroll
        for (int np = 0; np < 4; np++) {
            int n0 = wq * 64 + (2 * np) * 8 + g;
            int n1 = n0 + 8;
            const __half* pb0 = Bh + n0 * WTS + kk;
            const __half* pb1 = Bh + n1 * WTS + kk;
            uint32_t b0h0 = *(const uint32_t*)pb0, b0h1 = *(const uint32_t*)(pb0 + 8);
            uint32_t b1h0 = *(const uint32_t*)pb1, b1h1 = *(const uint32_t*)(pb1 + 8);
            float* a00 = acc[0][2 * np];
            float* a10 = acc[1][2 * np];
            float* a01 = acc[0][2 * np + 1];
            float* a11 = acc[1][2 * np + 1];
            hmma(a00[0], a00[1], a00[2], a00[3], ah[0][0], ah[0][1], ah[0][2], ah[0][3], b0h0, b0h1);
            hmma(a10[0], a10[1], a10[2], a10[3], ah[1][0], ah[1][1], ah[1][2], ah[1][3], b0h0, b0h1);
            hmma(a01[0], a01[1], a01[2], a01[3], ah[0][0], ah[0][1], ah[0][2], ah[0][3], b1h0, b1h1);
            hmma(a11[0], a11[1], a11[2], a11[3], ah[1][0], ah[1][1], ah[1][2], ah[1][3], b1h0, b1h1);
        }
    }
}

__global__ __launch_bounds__(256, 2) void lstm_mma(
        const float* __restrict__ Wg,  const float* __restrict__ bg,
        const float* __restrict__ bih, const float* __restrict__ bhh,
        const float* __restrict__ Wout, const float* __restrict__ bout,
        float* __restrict__ out) {
    extern __shared__ __align__(16) char smc[];
    __half* WIHh = (__half*)(smc + OFF_WIHH);
    __half* WHHh = (__half*)(smc + OFF_WHHH);
    __half* Gh = (__half*)(smc + OFF_GH);
    __half* Hh = (__half*)(smc + OFF_HH);
    float* sbias = (float*)(smc + OFF_BIAS);
    float* sWg   = (float*)(smc + OFF_WG);
    float* sbg   = (float*)(smc + OFF_BG);
    float* sWo   = (float*)(smc + OFF_WO);
    float* sxa   = (float*)(smc + OFF_SXA);
    float* outp  = (float*)(smc + OFF_GH);   // reused after final MMA (4*68 floats)

    int tid = threadIdx.x, wid = tid >> 5, lane = tid & 31;
    int g = lane >> 2, t4 = lane & 3;
    int wm = wid >> 2, wq = wid & 3;        // m-half (32 rows), n-slice (64 cols)
    int rowb = blockIdx.x * 64;

    {   // linear copy of pre-permuted weight image: 4608 uint4 over 256 threads
        const uint4* src = (const uint4*)d_Wall;
        uint4* dst = (uint4*)smc;
#pragma unroll
        for (int q = 0; q < 18; q++) dst[tid + 256 * q] = src[tid + 256 * q];
    }
    {
        int n = tid;
        int gate = (n >> 3) & 3, h = (n >> 5) * 8 + (n & 7);
        int o = gate * 64 + h;
        sbias[n] = bih[o] + bhh[o];
    }
    if (tid < 128) sWg[tid] = Wg[tid];
    if (tid < 64) { sbg[tid] = bg[tid]; sWo[tid] = Wout[tid]; }
    // fused split-K reduce: this block's 64 rows x 24 cols
    for (int v = tid; v < 64 * 24; v += 256) {
        int row = v / 24, j = v - row * 24;
        int R = rowb + row;
        int b = R / Nn, n = R - b * Nn;
        size_t idx = (size_t)n * Jj + b * 24 + j;
        float s = 0.f;
#pragma unroll
        for (int sp = 0; sp < SPLITK; sp++) s += d_XGp[(size_t)sp * NJ + idx];
        sxa[v] = s * ADJ_INV;
    }
    __syncthreads();

    int grow = tid >> 2, t4b = tid & 3;      // G-build: row = tid>>2 (0..63)
    float cst[2][8];
#pragma unroll
    for (int mt = 0; mt < 2; mt++)
#pragma unroll
        for (int q = 0; q < 8; q++) cst[mt][q] = 0.f;

    const __half* Ahm = Gh + wm * 32 * WTS;
    const __half* Hhm = Hh + wm * 32 * WTS;

    for (int t = 0; t < Tt; t++) {
        // ---- G tile build (relu GCN, fp16) ----
        {
            float xv0 = sxa[grow * 24 + 2 * t];
            float xv1 = sxa[grow * 24 + 2 * t + 1];
#pragma unroll
            for (int j = 0; j < 8; j++) {
                int k = t4b * 2 + 8 * j;
                float z0 = fmaf(xv0, sWg[2 * k],     fmaf(xv1, sWg[2 * k + 1], sbg[k]));
                float z1 = fmaf(xv0, sWg[2 * k + 2], fmaf(xv1, sWg[2 * k + 3], sbg[k + 1]));
                z0 = fmaxf(z0, 0.f); z1 = fmaxf(z1, 0.f);
                *(uint32_t*)(Gh + grow * WTS + k) =
                    pack2h(__float2half(z0), __float2half(z1));
            }
        }
        __syncthreads();
        float acc[2][8][4];
#pragma unroll
        for (int mt = 0; mt < 2; mt++)
#pragma unroll
            for (int nt = 0; nt < 8; nt++)
#pragma unroll
                for (int q = 0; q < 4; q++) acc[mt][nt][q] = 0.f;
        mma_pass1(acc, Ahm, WIHh, g, t4, wq);
        if (t > 0) mma_pass1(acc, Hhm, WHHh, g, t4, wq);
        // ---- cell update ----
#pragma unroll
        for (int mt = 0; mt < 2; mt++) {
#pragma unroll
            for (int hg = 0; hg < 2; hg++) {
#pragma unroll
                for (int d = 0; d < 4; d++) {
                    int j = d & 1;
                    int nb = wq * 64 + hg * 32 + 2 * t4 + j;
                    float ig = acc[mt][hg * 4 + 0][d] + sbias[nb];
                    float fg = acc[mt][hg * 4 + 1][d] + sbias[nb + 8];
                    float gg = acc[mt][hg * 4 + 2][d] + sbias[nb + 16];
                    float og = acc[mt][hg * 4 + 3][d] + sbias[nb + 24];
                    float cn = siga(fg) * cst[mt][hg * 4 + d] + siga(ig) * tanha(gg);
                    cst[mt][hg * 4 + d] = cn;
                    acc[mt][hg * 4 + 0][d] = siga(og) * tanha(cn);
                }
            }
        }
        __syncthreads();
        if (t < Tt - 1) {
            // store new H (fp16): h = (2wq+hg)*8 + 2*t4 (+1)
#pragma unroll
            for (int mt = 0; mt < 2; mt++) {
#pragma unroll
                for (int s = 0; s < 2; s++) {
                    int row = wm * 32 + 16 * mt + 8 * s + g;
#pragma unroll
                    for (int hg = 0; hg < 2; hg++) {
                        int hidx = (2 * wq + hg) * 8 + 2 * t4;
                        *(uint32_t*)(Hh + row * WTS + hidx) =
                            pack2h(__float2half(acc[mt][hg * 4][2 * s]),
                                   __float2half(acc[mt][hg * 4][2 * s + 1]));
                    }
                }
            }
        } else {
            // output head partials: this warp covers h = wq*16 .. +15
#pragma unroll
            for (int mt = 0; mt < 2; mt++) {
#pragma unroll
                for (int s = 0; s < 2; s++) {
                    int row = wm * 32 + 16 * mt + 8 * s + g;
                    float c = 0.f;
#pragma unroll
                    for (int hg = 0; hg < 2; hg++) {
                        int hidx = (2 * wq + hg) * 8 + 2 * t4;
                        c = fmaf(acc[mt][hg * 4][2 * s],     sWo[hidx],
                            fmaf(acc[mt][hg * 4][2 * s + 1], sWo[hidx + 1], c));
                    }
                    c += __shfl_down_sync(0xffffffffu, c, 2, 4);
                    c += __shfl_down_sync(0xffffffffu, c, 1, 4);
                    if (t4 == 0) outp[wq * 68 + row] = c;
                }
            }
        }
    }
    __syncthreads();
    if (tid < 64) {
        float s = outp[tid] + outp[68 + tid] + outp[136 + tid] + outp[204 + tid];
        out[rowb + tid] = s + bout[0];
    }
}

// ---------------- launch ----------------
extern "C" void kernel_launch(void* const* d_in, const int* in_sizes, int n_in,
                              void* d_out, int out_size) {
    const float* x    = (const float*)d_in[0];
    const float* adj  = (const float*)d_in[1];
    const float* Wg   = (const float*)d_in[2];
    const float* bg   = (const float*)d_in[3];
    const float* Wih  = (const float*)d_in[4];
    const float* Whh  = (const float*)d_in[5];
    const float* bih  = (const float*)d_in[6];
    const float* bhh  = (const float*)d_in[7];
    const float* Wout = (const float*)d_in[8];
    const float* bout = (const float*)d_in[9];
    float* out = (float*)d_out;

    cudaFuncSetAttribute(lstm_mma, cudaFuncAttributeMaxDynamicSharedMemorySize, LSTM_SMEM);

    prep_all<<<(Jj * 2000 + 255) / 256, 256>>>(x, Wih, Whh);
    dim3 ga(50, SPLITK);
    gemm_adj_mma<<<ga, 256>>>(adj);
    lstm_mma<<<BNr / 64, 256, LSTM_SMEM>>>(Wg, bg, bih, bhh, Wout, bout, out);
}